// round 1
// baseline (speedup 1.0000x reference)
#include <cuda_runtime.h>
#include <math.h>

// Problem constants: B=2, N=2048, D=512, H=8, hd=64
#define BATCH 2
#define SEQ   2048
#define DMODEL 512
#define HEADS 8
#define HDIM  64
#define QKVDIM 1536   // 3*DMODEL

// Tiled GEMM config
#define BM 64
#define BN 64
#define BK 16
#define LDS_S 68   // padded smem row stride (floats): 68*4B = 272B, 16B-aligned, reduces STS conflicts

// Scratch (no cudaMalloc allowed -> __device__ globals)
__device__ float g_qkv[BATCH * SEQ * QKVDIM];            // 25 MB
__device__ float g_scores[(size_t)BATCH * HEADS * SEQ * SEQ]; // 256 MB
__device__ float g_attn[BATCH * SEQ * DMODEL];           // 8 MB

// ---------------------------------------------------------------------------
// GEMM NT body: C[m,n] = alpha * sum_k A[m,k]*B[n,k] (+ bias[n])
// A: [M,K] row-major (lda), B: [Nn,K] row-major (ldb), C: [M,Nn] (ldc)
// grid: (Nn/BN, M/BM), block: 256 threads. M,Nn multiples of 64; K multiple of 16.
// ---------------------------------------------------------------------------
__device__ __forceinline__ void gemm_nt_body(
    const float* __restrict__ A, int lda,
    const float* __restrict__ B, int ldb,
    float* __restrict__ C, int ldc,
    int K, float alpha, const float* __restrict__ bias)
{
    __shared__ float As[BK][LDS_S];
    __shared__ float Bs[BK][LDS_S];

    const int t    = threadIdx.x;
    const int tx   = t & 15;        // 0..15 -> n microtile
    const int ty   = t >> 4;        // 0..15 -> m microtile
    const int lrow = t >> 2;        // 0..63 (global tile row for loads)
    const int lcol = (t & 3) << 2;  // 0,4,8,12 (k offset for loads)
    const int m0 = blockIdx.y * BM;
    const int n0 = blockIdx.x * BN;

    const float* Ag = A + (long long)(m0 + lrow) * lda + lcol;
    const float* Bg = B + (long long)(n0 + lrow) * ldb + lcol;

    float acc[4][4] = {};

    for (int k0 = 0; k0 < K; k0 += BK) {
        float4 av = *(const float4*)(Ag + k0);
        float4 bv = *(const float4*)(Bg + k0);
        As[lcol + 0][lrow] = av.x; As[lcol + 1][lrow] = av.y;
        As[lcol + 2][lrow] = av.z; As[lcol + 3][lrow] = av.w;
        Bs[lcol + 0][lrow] = bv.x; Bs[lcol + 1][lrow] = bv.y;
        Bs[lcol + 2][lrow] = bv.z; Bs[lcol + 3][lrow] = bv.w;
        __syncthreads();
#pragma unroll
        for (int kk = 0; kk < BK; kk++) {
            float a[4], b[4];
            *(float4*)a = *(const float4*)&As[kk][ty << 2];
            *(float4*)b = *(const float4*)&Bs[kk][tx << 2];
#pragma unroll
            for (int i = 0; i < 4; i++)
#pragma unroll
                for (int j = 0; j < 4; j++)
                    acc[i][j] += a[i] * b[j];
        }
        __syncthreads();
    }

    float4 bv4 = make_float4(0.f, 0.f, 0.f, 0.f);
    if (bias) bv4 = *(const float4*)&bias[n0 + (tx << 2)];
#pragma unroll
    for (int i = 0; i < 4; i++) {
        float4 r;
        r.x = acc[i][0] * alpha + bv4.x;
        r.y = acc[i][1] * alpha + bv4.y;
        r.z = acc[i][2] * alpha + bv4.z;
        r.w = acc[i][3] * alpha + bv4.w;
        *(float4*)&C[(long long)(m0 + (ty << 2) + i) * ldc + n0 + (tx << 2)] = r;
    }
}

__global__ __launch_bounds__(256) void gemm_nt_kernel(
    const float* __restrict__ A, int lda,
    const float* __restrict__ B, int ldb,
    float* __restrict__ C, int ldc,
    int K, float alpha, const float* __restrict__ bias)
{
    gemm_nt_body(A, lda, B, ldb, C, ldc, K, alpha, bias);
}

// scores[z][n][m] = 0.125 * sum_d q[b,n,h,d] * k[b,m,h,d],  z = b*8+h
__global__ __launch_bounds__(256) void scores_kernel(
    const float* __restrict__ qkv, float* __restrict__ scores)
{
    const int z = blockIdx.z;
    const int b = z >> 3, h = z & 7;
    const float* base = qkv + (long long)b * SEQ * QKVDIM + h * HDIM;
    gemm_nt_body(base, QKVDIM,            // Q
                 base + DMODEL, QKVDIM,   // K (offset 512 in e-dim)
                 scores + (long long)z * SEQ * SEQ, SEQ,
                 HDIM, 0.125f, nullptr);
}

// ---------------------------------------------------------------------------
// Row-wise: s /= (||s||_2 + 1e-6); softmax(s). One block per row of 2048.
// ---------------------------------------------------------------------------
__global__ __launch_bounds__(256) void norm_softmax_kernel(float* __restrict__ S)
{
    const int N = SEQ;
    float* row = S + (long long)blockIdx.x * N;
    const int t = threadIdx.x;
    const int lane = t & 31, wid = t >> 5;
    __shared__ float red[8];
    __shared__ float bc;

    float v[8];
    float ss = 0.f;
#pragma unroll
    for (int i = 0; i < 8; i++) { v[i] = row[t + i * 256]; ss += v[i] * v[i]; }
#pragma unroll
    for (int o = 16; o; o >>= 1) ss += __shfl_xor_sync(0xffffffffu, ss, o);
    if (lane == 0) red[wid] = ss;
    __syncthreads();
    if (t == 0) {
        float s = 0.f;
#pragma unroll
        for (int i = 0; i < 8; i++) s += red[i];
        bc = 1.0f / (sqrtf(s) + 1e-6f);
    }
    __syncthreads();
    const float inv = bc;

    float m = -3.402823466e38f;
#pragma unroll
    for (int i = 0; i < 8; i++) { v[i] *= inv; m = fmaxf(m, v[i]); }
    __syncthreads();  // protect red/bc reuse
#pragma unroll
    for (int o = 16; o; o >>= 1) m = fmaxf(m, __shfl_xor_sync(0xffffffffu, m, o));
    if (lane == 0) red[wid] = m;
    __syncthreads();
    if (t == 0) {
        float mm = red[0];
#pragma unroll
        for (int i = 1; i < 8; i++) mm = fmaxf(mm, red[i]);
        bc = mm;
    }
    __syncthreads();
    const float mx = bc;

    float se = 0.f;
#pragma unroll
    for (int i = 0; i < 8; i++) { v[i] = __expf(v[i] - mx); se += v[i]; }
    __syncthreads();
#pragma unroll
    for (int o = 16; o; o >>= 1) se += __shfl_xor_sync(0xffffffffu, se, o);
    if (lane == 0) red[wid] = se;
    __syncthreads();
    if (t == 0) {
        float s = 0.f;
#pragma unroll
        for (int i = 0; i < 8; i++) s += red[i];
        bc = 1.0f / s;
    }
    __syncthreads();
    const float r = bc;
#pragma unroll
    for (int i = 0; i < 8; i++) row[t + i * 256] = v[i] * r;
}

// ---------------------------------------------------------------------------
// P @ V (NN): out[b,n,h*64+d] = sum_m P[z][n][m] * v[b,m,h,d]
// A: scores [2048,2048] k-contig; B: v [2048(k), 64(n)] with ldb=1536
// grid: (1, 32, 16)
// ---------------------------------------------------------------------------
__global__ __launch_bounds__(256) void pv_kernel(
    const float* __restrict__ S, const float* __restrict__ qkv,
    float* __restrict__ attn)
{
    __shared__ float As[BK][LDS_S];
    __shared__ float Bs[BK][LDS_S];

    const int z = blockIdx.z, b = z >> 3, h = z & 7;
    const float* A = S + (long long)z * SEQ * SEQ;
    const float* B = qkv + (long long)b * SEQ * QKVDIM + 2 * DMODEL + h * HDIM;
    float* C = attn + (long long)b * SEQ * DMODEL + h * HDIM;

    const int t    = threadIdx.x;
    const int tx   = t & 15, ty = t >> 4;
    const int lrow = t >> 2;        // A load row 0..63
    const int lcol = (t & 3) << 2;  // A load k 0,4,8,12
    const int brow = t >> 4;        // B load k-row 0..15
    const int bcol = (t & 15) << 2; // B load n 0..60
    const int m0 = blockIdx.y * BM;

    const float* Ag = A + (long long)(m0 + lrow) * SEQ + lcol;

    float acc[4][4] = {};
    for (int k0 = 0; k0 < SEQ; k0 += BK) {
        float4 av = *(const float4*)(Ag + k0);
        As[lcol + 0][lrow] = av.x; As[lcol + 1][lrow] = av.y;
        As[lcol + 2][lrow] = av.z; As[lcol + 3][lrow] = av.w;
        float4 bv = *(const float4*)(B + (long long)(k0 + brow) * QKVDIM + bcol);
        *(float4*)&Bs[brow][bcol] = bv;
        __syncthreads();
#pragma unroll
        for (int kk = 0; kk < BK; kk++) {
            float a[4], bb[4];
            *(float4*)a  = *(const float4*)&As[kk][ty << 2];
            *(float4*)bb = *(const float4*)&Bs[kk][tx << 2];
#pragma unroll
            for (int i = 0; i < 4; i++)
#pragma unroll
                for (int j = 0; j < 4; j++)
                    acc[i][j] += a[i] * bb[j];
        }
        __syncthreads();
    }
#pragma unroll
    for (int i = 0; i < 4; i++) {
        float4 r = make_float4(acc[i][0], acc[i][1], acc[i][2], acc[i][3]);
        *(float4*)&C[(long long)(m0 + (ty << 2) + i) * DMODEL + (tx << 2)] = r;
    }
}

// ---------------------------------------------------------------------------
extern "C" void kernel_launch(void* const* d_in, const int* in_sizes, int n_in,
                              void* d_out, int out_size)
{
    const float* x      = (const float*)d_in[0];
    const float* qkv_w  = (const float*)d_in[1];
    const float* qkv_b  = (const float*)d_in[2];
    const float* proj_w = (const float*)d_in[3];
    const float* proj_b = (const float*)d_in[4];
    float* out = (float*)d_out;

    float *qkv, *scores, *attn;
    cudaGetSymbolAddress((void**)&qkv, g_qkv);
    cudaGetSymbolAddress((void**)&scores, g_scores);
    cudaGetSymbolAddress((void**)&attn, g_attn);

    // 1) QKV projection: [4096,512] @ [1536,512]^T + bias -> [4096,1536]
    gemm_nt_kernel<<<dim3(QKVDIM / BN, (BATCH * SEQ) / BM), 256>>>(
        x, DMODEL, qkv_w, DMODEL, qkv, QKVDIM, DMODEL, 1.0f, qkv_b);

    // 2) scores = 0.125 * Q K^T per (b,h)
    scores_kernel<<<dim3(SEQ / BN, SEQ / BM, BATCH * HEADS), 256>>>(qkv, scores);

    // 3) L2-normalize rows + softmax
    norm_softmax_kernel<<<BATCH * HEADS * SEQ, 256>>>(scores);

    // 4) out_h = P @ V per (b,h)
    pv_kernel<<<dim3(1, SEQ / BM, BATCH * HEADS), 256>>>(scores, qkv, attn);

    // 5) final projection: [4096,512] @ [512,512]^T + bias
    gemm_nt_kernel<<<dim3(DMODEL / BN, (BATCH * SEQ) / BM), 256>>>(
        attn, DMODEL, proj_w, DMODEL, out, DMODEL, DMODEL, 1.0f, proj_b);
}

// round 2
// speedup vs baseline: 1.2426x; 1.2426x over previous
#include <cuda_runtime.h>
#include <math.h>

// Problem constants: B=2, N=2048, D=512, H=8, hd=64
#define BATCH 2
#define SEQ   2048
#define DMODEL 512
#define HEADS 8
#define HDIM  64
#define QKVDIM 1536   // 3*DMODEL

// Tiled GEMM config: 128x64 CTA tile, 8x4 per-thread microtile, 256 threads
#define BM 128
#define BN 64
#define BK 16

// Scratch (no cudaMalloc allowed -> __device__ globals)
__device__ float g_qkv[BATCH * SEQ * QKVDIM];                 // 25 MB
__device__ float g_scores[(size_t)BATCH * HEADS * SEQ * SEQ]; // 256 MB
__device__ float g_attn[BATCH * SEQ * DMODEL];                // 8 MB

// ---------------------------------------------------------------------------
// GEMM body. C[m,n] = alpha * sum_k A[m,k] * B'[k,n] (+ bias[n])
//   A is always [M,K] row-major (lda = row stride).
//   BNT=1: B is [N,K] row-major (NT gemm).  BNT=0: B is [K,N] row-major (NN).
// Double-buffered smem, one __syncthreads per k-step.
// ---------------------------------------------------------------------------
template<int BNT>
__device__ __forceinline__ void gemm_body(
    const float* __restrict__ A, int lda,
    const float* __restrict__ B, int ldb,
    float* __restrict__ C, int ldc,
    int K, float alpha, const float* __restrict__ bias,
    int m0, int n0)
{
    __shared__ float As[2][BK][BM + 4];   // [k][m], transposed store
    __shared__ float Bs[2][BK][BN + 4];   // [k][n]

    const int t  = threadIdx.x;
    const int tx = t & 15;   // n microtile (16 x 4 = 64)
    const int ty = t >> 4;   // m microtile (16 x 8 = 128)

    // A tile loads: 128 rows x 16 k = 512 float4; 2 per thread
    const int ar = t >> 2;         // 0..63 (+64 for second)
    const int ac = (t & 3) << 2;   // k offset 0,4,8,12
    const float* Ag0 = A + (long long)(m0 + ar) * lda + ac;
    const float* Ag1 = A + (long long)(m0 + ar + 64) * lda + ac;

    // B tile loads
    int br, bc;
    const float* Bg;
    if (BNT) { br = t >> 2;  bc = (t & 3) << 2;  Bg = B + (long long)(n0 + br) * ldb + bc; }
    else     { br = t >> 4;  bc = (t & 15) << 2; Bg = B + (long long)br * ldb + n0 + bc; }

    float acc[8][4] = {};

    // --- prologue: load tile 0 into smem[0]
    {
        float4 a0 = *(const float4*)(Ag0);
        float4 a1 = *(const float4*)(Ag1);
        As[0][ac + 0][ar] = a0.x; As[0][ac + 1][ar] = a0.y;
        As[0][ac + 2][ar] = a0.z; As[0][ac + 3][ar] = a0.w;
        As[0][ac + 0][ar + 64] = a1.x; As[0][ac + 1][ar + 64] = a1.y;
        As[0][ac + 2][ar + 64] = a1.z; As[0][ac + 3][ar + 64] = a1.w;
        float4 bv = *(const float4*)(Bg);
        if (BNT) {
            Bs[0][bc + 0][br] = bv.x; Bs[0][bc + 1][br] = bv.y;
            Bs[0][bc + 2][br] = bv.z; Bs[0][bc + 3][br] = bv.w;
        } else {
            *(float4*)&Bs[0][br][bc] = bv;
        }
    }
    __syncthreads();

    int buf = 0;
    for (int k0 = 0; k0 < K; k0 += BK) {
        const bool has_next = (k0 + BK) < K;
        float4 a0, a1, bv;
        if (has_next) {
            a0 = *(const float4*)(Ag0 + k0 + BK);
            a1 = *(const float4*)(Ag1 + k0 + BK);
            bv = BNT ? *(const float4*)(Bg + k0 + BK)
                     : *(const float4*)(Bg + (long long)(k0 + BK) * ldb);
        }

#pragma unroll
        for (int kk = 0; kk < BK; kk++) {
            float a[8], b[4];
            *(float4*)&a[0] = *(const float4*)&As[buf][kk][ty << 3];
            *(float4*)&a[4] = *(const float4*)&As[buf][kk][(ty << 3) + 4];
            *(float4*)&b[0] = *(const float4*)&Bs[buf][kk][tx << 2];
#pragma unroll
            for (int i = 0; i < 8; i++)
#pragma unroll
                for (int j = 0; j < 4; j++)
                    acc[i][j] += a[i] * b[j];
        }

        if (has_next) {
            const int nb = buf ^ 1;
            As[nb][ac + 0][ar] = a0.x; As[nb][ac + 1][ar] = a0.y;
            As[nb][ac + 2][ar] = a0.z; As[nb][ac + 3][ar] = a0.w;
            As[nb][ac + 0][ar + 64] = a1.x; As[nb][ac + 1][ar + 64] = a1.y;
            As[nb][ac + 2][ar + 64] = a1.z; As[nb][ac + 3][ar + 64] = a1.w;
            if (BNT) {
                Bs[nb][bc + 0][br] = bv.x; Bs[nb][bc + 1][br] = bv.y;
                Bs[nb][bc + 2][br] = bv.z; Bs[nb][bc + 3][br] = bv.w;
            } else {
                *(float4*)&Bs[nb][br][bc] = bv;
            }
        }
        __syncthreads();
        buf ^= 1;
    }

    float4 bv4 = make_float4(0.f, 0.f, 0.f, 0.f);
    if (bias) bv4 = *(const float4*)&bias[n0 + (tx << 2)];
#pragma unroll
    for (int i = 0; i < 8; i++) {
        float4 r;
        r.x = acc[i][0] * alpha + bv4.x;
        r.y = acc[i][1] * alpha + bv4.y;
        r.z = acc[i][2] * alpha + bv4.z;
        r.w = acc[i][3] * alpha + bv4.w;
        *(float4*)&C[(long long)(m0 + (ty << 3) + i) * ldc + n0 + (tx << 2)] = r;
    }
}

__global__ __launch_bounds__(256) void gemm_nt_kernel(
    const float* __restrict__ A, int lda,
    const float* __restrict__ B, int ldb,
    float* __restrict__ C, int ldc,
    int K, float alpha, const float* __restrict__ bias)
{
    gemm_body<1>(A, lda, B, ldb, C, ldc, K, alpha, bias,
                 blockIdx.y * BM, blockIdx.x * BN);
}

// scores[z][n][m] = 0.125 * sum_d q[b,n,h,d] * k[b,m,h,d],  z = b*8+h
__global__ __launch_bounds__(256) void scores_kernel(
    const float* __restrict__ qkv, float* __restrict__ scores)
{
    const int z = blockIdx.z;
    const int b = z >> 3, h = z & 7;
    const float* base = qkv + (long long)b * SEQ * QKVDIM + h * HDIM;
    gemm_body<1>(base, QKVDIM,            // Q rows
                 base + DMODEL, QKVDIM,   // K rows (offset 512 in e-dim)
                 scores + (long long)z * SEQ * SEQ, SEQ,
                 HDIM, 0.125f, nullptr,
                 blockIdx.y * BM, blockIdx.x * BN);
}

// P @ V (NN): out[b,n,h*64+d] = sum_m P[z][n][m] * v[b,m,h,d]
__global__ __launch_bounds__(256) void pv_kernel(
    const float* __restrict__ S, const float* __restrict__ qkv,
    float* __restrict__ attn)
{
    const int z = blockIdx.z, b = z >> 3, h = z & 7;
    gemm_body<0>(S + (long long)z * SEQ * SEQ, SEQ,
                 qkv + (long long)b * SEQ * QKVDIM + 2 * DMODEL + h * HDIM, QKVDIM,
                 attn + (long long)b * SEQ * DMODEL + h * HDIM, DMODEL,
                 SEQ, 1.0f, nullptr,
                 blockIdx.y * BM, 0);
}

// ---------------------------------------------------------------------------
// Row-wise: s /= (||s||_2 + 1e-6); softmax(s). One block per row of 2048.
// ---------------------------------------------------------------------------
__global__ __launch_bounds__(256) void norm_softmax_kernel(float* __restrict__ S)
{
    const int N = SEQ;
    float* row = S + (long long)blockIdx.x * N;
    const int t = threadIdx.x;
    const int lane = t & 31, wid = t >> 5;
    __shared__ float red[8];
    __shared__ float bc;

    float v[8];
    float ss = 0.f;
#pragma unroll
    for (int i = 0; i < 8; i++) { v[i] = row[t + i * 256]; ss += v[i] * v[i]; }
#pragma unroll
    for (int o = 16; o; o >>= 1) ss += __shfl_xor_sync(0xffffffffu, ss, o);
    if (lane == 0) red[wid] = ss;
    __syncthreads();
    if (t == 0) {
        float s = 0.f;
#pragma unroll
        for (int i = 0; i < 8; i++) s += red[i];
        bc = 1.0f / (sqrtf(s) + 1e-6f);
    }
    __syncthreads();
    const float inv = bc;

    float m = -3.402823466e38f;
#pragma unroll
    for (int i = 0; i < 8; i++) { v[i] *= inv; m = fmaxf(m, v[i]); }
    __syncthreads();
#pragma unroll
    for (int o = 16; o; o >>= 1) m = fmaxf(m, __shfl_xor_sync(0xffffffffu, m, o));
    if (lane == 0) red[wid] = m;
    __syncthreads();
    if (t == 0) {
        float mm = red[0];
#pragma unroll
        for (int i = 1; i < 8; i++) mm = fmaxf(mm, red[i]);
        bc = mm;
    }
    __syncthreads();
    const float mx = bc;

    float se = 0.f;
#pragma unroll
    for (int i = 0; i < 8; i++) { v[i] = __expf(v[i] - mx); se += v[i]; }
    __syncthreads();
#pragma unroll
    for (int o = 16; o; o >>= 1) se += __shfl_xor_sync(0xffffffffu, se, o);
    if (lane == 0) red[wid] = se;
    __syncthreads();
    if (t == 0) {
        float s = 0.f;
#pragma unroll
        for (int i = 0; i < 8; i++) s += red[i];
        bc = 1.0f / s;
    }
    __syncthreads();
    const float r = bc;
#pragma unroll
    for (int i = 0; i < 8; i++) row[t + i * 256] = v[i] * r;
}

// ---------------------------------------------------------------------------
extern "C" void kernel_launch(void* const* d_in, const int* in_sizes, int n_in,
                              void* d_out, int out_size)
{
    const float* x      = (const float*)d_in[0];
    const float* qkv_w  = (const float*)d_in[1];
    const float* qkv_b  = (const float*)d_in[2];
    const float* proj_w = (const float*)d_in[3];
    const float* proj_b = (const float*)d_in[4];
    float* out = (float*)d_out;

    float *qkv, *scores, *attn;
    cudaGetSymbolAddress((void**)&qkv, g_qkv);
    cudaGetSymbolAddress((void**)&scores, g_scores);
    cudaGetSymbolAddress((void**)&attn, g_attn);

    // 1) QKV projection: [4096,512] @ [1536,512]^T + bias -> [4096,1536]
    gemm_nt_kernel<<<dim3(QKVDIM / BN, (BATCH * SEQ) / BM), 256>>>(
        x, DMODEL, qkv_w, DMODEL, qkv, QKVDIM, DMODEL, 1.0f, qkv_b);

    // 2) scores = 0.125 * Q K^T per (b,h)
    scores_kernel<<<dim3(SEQ / BN, SEQ / BM, BATCH * HEADS), 256>>>(qkv, scores);

    // 3) L2-normalize rows + softmax
    norm_softmax_kernel<<<BATCH * HEADS * SEQ, 256>>>(scores);

    // 4) out_h = P @ V per (b,h)
    pv_kernel<<<dim3(1, SEQ / BM, BATCH * HEADS), 256>>>(scores, qkv, attn);

    // 5) final projection: [4096,512] @ [512,512]^T + bias
    gemm_nt_kernel<<<dim3(DMODEL / BN, (BATCH * SEQ) / BM), 256>>>(
        attn, DMODEL, proj_w, DMODEL, out, DMODEL, DMODEL, 1.0f, proj_b);
}

// round 7
// speedup vs baseline: 1.7851x; 1.4366x over previous
#include <cuda_runtime.h>
#include <cuda_bf16.h>
#include <math.h>
#include <stdint.h>

// Problem constants: B=2, N=2048, D=512, H=8, hd=64
#define BATCH 2
#define SEQ   2048
#define DMODEL 512
#define HEADS 8
#define HDIM  64
#define QKVDIM 1536

// Scratch (no cudaMalloc -> __device__ globals)
__device__ float g_qkv[(size_t)BATCH * SEQ * QKVDIM];                 // 25 MB
__device__ float g_scores[(size_t)BATCH * HEADS * SEQ * SEQ];         // 256 MB
__device__ float g_attn[(size_t)BATCH * SEQ * DMODEL];                // 8 MB
__device__ float g_sumsq[(size_t)BATCH * HEADS * SEQ];                // 128 KB

// ---------------------------------------------------------------------------
// Shared-memory layout: bf16, row stride 72 elements, 16B units bank-rotated
// per row -> conflict-free ldmatrix, ~2-way worst-case staging stores.
// soff returns element offset; byte offset = soff * 2.
// ---------------------------------------------------------------------------
#define SSTR 72
__device__ __forceinline__ uint32_t soff(int row, int k) {
    int u = ((k >> 3) + (row >> 2)) & 7;
    return (uint32_t)(row * SSTR + (u << 3) + (k & 7));
}

__device__ __forceinline__ uint32_t smem_u32(const void* p) {
    uint32_t a;
    asm("{ .reg .u64 t; cvta.to.shared.u64 t, %1; cvt.u32.u64 %0, t; }" : "=r"(a) : "l"(p));
    return a;
}

__device__ __forceinline__ void ldsm_x4(uint32_t* r, uint32_t addr) {
    asm volatile("ldmatrix.sync.aligned.m8n8.x4.shared.b16 {%0,%1,%2,%3}, [%4];"
        : "=r"(r[0]), "=r"(r[1]), "=r"(r[2]), "=r"(r[3]) : "r"(addr));
}

__device__ __forceinline__ void mma_bf16(float* c, const uint32_t* a, const uint32_t* b) {
    asm volatile(
        "mma.sync.aligned.m16n8k16.row.col.f32.bf16.bf16.f32 "
        "{%0,%1,%2,%3}, {%4,%5,%6,%7}, {%8,%9}, {%0,%1,%2,%3};"
        : "+f"(c[0]), "+f"(c[1]), "+f"(c[2]), "+f"(c[3])
        : "r"(a[0]), "r"(a[1]), "r"(a[2]), "r"(a[3]), "r"(b[0]), "r"(b[1]));
}

// split fp32x4 (4 consecutive k of one row) -> hi/lo bf16 slabs
__device__ __forceinline__ void st_split4(char* hiB, char* loB, int row, int k, float4 v) {
    __nv_bfloat162 h0 = __floats2bfloat162_rn(v.x, v.y);
    __nv_bfloat162 l0 = __floats2bfloat162_rn(v.x - __low2float(h0), v.y - __high2float(h0));
    __nv_bfloat162 h1 = __floats2bfloat162_rn(v.z, v.w);
    __nv_bfloat162 l1 = __floats2bfloat162_rn(v.z - __low2float(h1), v.w - __high2float(h1));
    uint32_t o0 = soff(row, k) * 2;
    uint32_t o1 = soff(row, k + 2) * 2;
    *(__nv_bfloat162*)(hiB + o0) = h0; *(__nv_bfloat162*)(hiB + o1) = h1;
    *(__nv_bfloat162*)(loB + o0) = l0; *(__nv_bfloat162*)(loB + o1) = l1;
}

// smem buffer offsets (bytes)
#define A_HI 0
#define A_LO 18432
#define B_HI 36864
#define B_LO 46080
#define SMEM_DYN 55296

// ---------------------------------------------------------------------------
// One 64-wide K slab of MMAs. Warp grid 4(M) x 2(N); warp tile 32x32.
// 3-chain split bf16: hi*hi + hi*lo + lo*hi.
// ---------------------------------------------------------------------------
__device__ __forceinline__ void mma_slab(uint32_t sbase, float c[2][4][4], int wid, int lane) {
    const int wm = (wid & 3) << 5;
    const int wn = (wid >> 2) << 5;
    const int lrow = lane & 15, lhalf = lane >> 4;
    const int bq = lane >> 3, br = lane & 7;
    const int bnq = ((bq >> 1) << 3) + br;   // n offset within 16-block
    const int bk8 = (bq & 1) << 3;           // k half
#pragma unroll
    for (int kk = 0; kk < 64; kk += 16) {
        uint32_t ah[2][4], al[2][4], bh[2][4], bl[2][4];
#pragma unroll
        for (int mf = 0; mf < 2; mf++) {
            uint32_t o = soff(wm + (mf << 4) + lrow, kk + (lhalf << 3)) * 2;
            ldsm_x4(ah[mf], sbase + A_HI + o);
            ldsm_x4(al[mf], sbase + A_LO + o);
        }
#pragma unroll
        for (int np = 0; np < 2; np++) {
            uint32_t o = soff(wn + (np << 4) + bnq, kk + bk8) * 2;
            ldsm_x4(bh[np], sbase + B_HI + o);
            ldsm_x4(bl[np], sbase + B_LO + o);
        }
#pragma unroll
        for (int mf = 0; mf < 2; mf++)
#pragma unroll
            for (int nf = 0; nf < 4; nf++) {
                const uint32_t* bhp = &bh[nf >> 1][(nf & 1) << 1];
                const uint32_t* blp = &bl[nf >> 1][(nf & 1) << 1];
                mma_bf16(c[mf][nf], ah[mf], bhp);
                mma_bf16(c[mf][nf], ah[mf], blp);
                mma_bf16(c[mf][nf], al[mf], bhp);
            }
    }
}

// ============================================================================
// Generic NT GEMM: C[m,n] = alpha*sum_k A[m,k]*B[n,k] (+bias[n]).
// CTA tile 128(M) x 64(N), K multiple of 64. Optional per-row sumsq atomics.
// ============================================================================
__global__ __launch_bounds__(256) void gemm_nt_tc(
    const float* __restrict__ A, int lda, long long sAb, long long sAh,
    const float* __restrict__ B, int ldb, long long sBb, long long sBh,
    float* __restrict__ C, int ldc, long long sCb, long long sCh,
    int K, float alpha, const float* __restrict__ bias, float* __restrict__ sumsq)
{
    extern __shared__ char sm[];
    const int t = threadIdx.x, lane = t & 31, wid = t >> 5;
    const int z = blockIdx.z, zb = z >> 3, zh = z & 7;
    const int m0 = blockIdx.y * 128;
    const int n0 = blockIdx.x * 64;
    A += (size_t)zb * sAb + (size_t)zh * sAh;
    B += (size_t)zb * sBb + (size_t)zh * sBh;
    C += (size_t)zb * sCb + (size_t)zh * sCh;

    char *aHi = sm + A_HI, *aLo = sm + A_LO, *bHi = sm + B_HI, *bLo = sm + B_LO;
    const uint32_t sbase = smem_u32(sm);

    float c[2][4][4] = {};
    const int ar = t >> 4, ac4 = (t & 15) << 2;

    const int S = K >> 6;
    for (int s = 0; s < S; s++) {
        const int k0 = s << 6;
        float4 av[8], bv[4];
#pragma unroll
        for (int i = 0; i < 8; i++)
            av[i] = *(const float4*)(A + (size_t)(m0 + (i << 4) + ar) * lda + k0 + ac4);
#pragma unroll
        for (int i = 0; i < 4; i++)
            bv[i] = *(const float4*)(B + (size_t)(n0 + (i << 4) + ar) * ldb + k0 + ac4);
        __syncthreads();   // prior slab fully consumed
#pragma unroll
        for (int i = 0; i < 8; i++) st_split4(aHi, aLo, (i << 4) + ar, ac4, av[i]);
#pragma unroll
        for (int i = 0; i < 4; i++) st_split4(bHi, bLo, (i << 4) + ar, ac4, bv[i]);
        __syncthreads();
        mma_slab(sbase, c, wid, lane);
    }

    // epilogue
    const int wm = (wid & 3) << 5, wn = (wid >> 2) << 5;
    const int r4 = lane >> 2, c2 = (lane & 3) << 1;
    float ss[4] = {0.f, 0.f, 0.f, 0.f};
#pragma unroll
    for (int mf = 0; mf < 2; mf++)
#pragma unroll
        for (int half = 0; half < 2; half++) {
            const int row = m0 + wm + (mf << 4) + (half << 3) + r4;
#pragma unroll
            for (int nf = 0; nf < 4; nf++) {
                const int col = n0 + wn + (nf << 3) + c2;
                float2 o;
                o.x = c[mf][nf][half * 2 + 0] * alpha;
                o.y = c[mf][nf][half * 2 + 1] * alpha;
                if (bias) { o.x += bias[col]; o.y += bias[col + 1]; }
                ss[mf * 2 + half] += o.x * o.x + o.y * o.y;
                *(float2*)&C[(size_t)row * ldc + col] = o;
            }
        }
    if (sumsq) {
#pragma unroll
        for (int q = 0; q < 4; q++) {
            float v = ss[q];
            v += __shfl_xor_sync(0xffffffffu, v, 1);
            v += __shfl_xor_sync(0xffffffffu, v, 2);
            if ((lane & 3) == 0) {
                const int row = m0 + wm + ((q >> 1) << 4) + ((q & 1) << 3) + r4;
                atomicAdd(&sumsq[(size_t)z * SEQ + row], v);
            }
        }
    }
}

// ============================================================================
// Fused norm+softmax+PV: p = exp(s * inv_norm)  (|s*inv| <= 1, no max needed),
// per-row sum(p) accumulated in-CTA (CTA spans full K=2048), P@V via HMMA,
// epilogue divides by sumexp. V transposed during staging.
// ============================================================================
__global__ __launch_bounds__(256) void pv_tc(
    const float* __restrict__ Sm, const float* __restrict__ qkv,
    const float* __restrict__ sumsq, float* __restrict__ attn)
{
    extern __shared__ char sm[];
    __shared__ float s_inv[128];
    __shared__ float s_se[128];
    const int t = threadIdx.x, lane = t & 31, wid = t >> 5;
    const int z = blockIdx.z, b = z >> 3, h = z & 7;
    const int m0 = blockIdx.y * 128;
    const float* Sg = Sm + (size_t)z * SEQ * SEQ;
    const float* Vg = qkv + (size_t)b * SEQ * QKVDIM + 2 * DMODEL + h * HDIM;
    float* Cg = attn + (size_t)b * SEQ * DMODEL + h * HDIM;

    char *aHi = sm + A_HI, *aLo = sm + A_LO, *bHi = sm + B_HI, *bLo = sm + B_LO;
    const uint32_t sbase = smem_u32(sm);

    if (t < 128) s_inv[t] = 1.0f / (sqrtf(sumsq[(size_t)z * SEQ + m0 + t]) + 1e-6f);
    __syncthreads();

    float c[2][4][4] = {};
    float se[8] = {0.f, 0.f, 0.f, 0.f, 0.f, 0.f, 0.f, 0.f};
    const int ar = t >> 4, ac4 = (t & 15) << 2;
    const int nq = t & 15;

    for (int s = 0; s < SEQ / 64; s++) {
        const int k0 = s << 6;
        float4 av[8];
#pragma unroll
        for (int i = 0; i < 8; i++)
            av[i] = *(const float4*)(Sg + (size_t)(m0 + (i << 4) + ar) * SEQ + k0 + ac4);
        float4 v0[2], v1[2];
#pragma unroll
        for (int i = 0; i < 2; i++) {
            const int kp = (i << 4) + ar;   // k-pair index 0..31
            v0[i] = *(const float4*)(Vg + (size_t)(k0 + 2 * kp)     * QKVDIM + (nq << 2));
            v1[i] = *(const float4*)(Vg + (size_t)(k0 + 2 * kp + 1) * QKVDIM + (nq << 2));
        }
        __syncthreads();
#pragma unroll
        for (int i = 0; i < 8; i++) {
            const int row = (i << 4) + ar;
            const float inv = s_inv[row];
            float4 p;
            p.x = __expf(av[i].x * inv);
            p.y = __expf(av[i].y * inv);
            p.z = __expf(av[i].z * inv);
            p.w = __expf(av[i].w * inv);
            se[i] += p.x + p.y + p.z + p.w;
            st_split4(aHi, aLo, row, ac4, p);
        }
#pragma unroll
        for (int i = 0; i < 2; i++) {
            const int kp = (i << 4) + ar;
            const float a0[4] = {v0[i].x, v0[i].y, v0[i].z, v0[i].w};
            const float a1[4] = {v1[i].x, v1[i].y, v1[i].z, v1[i].w};
#pragma unroll
            for (int j = 0; j < 4; j++) {
                const int row = (nq << 2) + j;   // n index
                __nv_bfloat162 hh = __floats2bfloat162_rn(a0[j], a1[j]);
                __nv_bfloat162 ll = __floats2bfloat162_rn(a0[j] - __low2float(hh),
                                                          a1[j] - __high2float(hh));
                const uint32_t o = soff(row, 2 * kp) * 2;
                *(__nv_bfloat162*)(bHi + o) = hh;
                *(__nv_bfloat162*)(bLo + o) = ll;
            }
        }
        __syncthreads();
        mma_slab(sbase, c, wid, lane);
    }

    // per-row sumexp: reduce across the 16 threads sharing each row
#pragma unroll
    for (int i = 0; i < 8; i++) {
        float v = se[i];
        v += __shfl_xor_sync(0xffffffffu, v, 1);
        v += __shfl_xor_sync(0xffffffffu, v, 2);
        v += __shfl_xor_sync(0xffffffffu, v, 4);
        v += __shfl_xor_sync(0xffffffffu, v, 8);
        if ((t & 15) == 0) s_se[(i << 4) + ar] = v;
    }
    __syncthreads();

    const int wm = (wid & 3) << 5, wn = (wid >> 2) << 5;
    const int r4 = lane >> 2, c2 = (lane & 3) << 1;
#pragma unroll
    for (int mf = 0; mf < 2; mf++)
#pragma unroll
        for (int half = 0; half < 2; half++) {
            const int rl = wm + (mf << 4) + (half << 3) + r4;
            const float rse = 1.0f / s_se[rl];
#pragma unroll
            for (int nf = 0; nf < 4; nf++) {
                const int col = wn + (nf << 3) + c2;
                float2 o;
                o.x = c[mf][nf][half * 2 + 0] * rse;
                o.y = c[mf][nf][half * 2 + 1] * rse;
                *(float2*)&Cg[(size_t)(m0 + rl) * DMODEL + col] = o;
            }
        }
}

__global__ void zero_stats(float* p) {
    ((float4*)p)[blockIdx.x * blockDim.x + threadIdx.x] = make_float4(0.f, 0.f, 0.f, 0.f);
}

// ---------------------------------------------------------------------------
extern "C" void kernel_launch(void* const* d_in, const int* in_sizes, int n_in,
                              void* d_out, int out_size)
{
    const float* x      = (const float*)d_in[0];
    const float* qkv_w  = (const float*)d_in[1];
    const float* qkv_b  = (const float*)d_in[2];
    const float* proj_w = (const float*)d_in[3];
    const float* proj_b = (const float*)d_in[4];
    float* out = (float*)d_out;

    float *qkv, *scores, *attn, *sumsq;
    cudaGetSymbolAddress((void**)&qkv, g_qkv);
    cudaGetSymbolAddress((void**)&scores, g_scores);
    cudaGetSymbolAddress((void**)&attn, g_attn);
    cudaGetSymbolAddress((void**)&sumsq, g_sumsq);

    cudaFuncSetAttribute(gemm_nt_tc, cudaFuncAttributeMaxDynamicSharedMemorySize, SMEM_DYN);
    cudaFuncSetAttribute(pv_tc, cudaFuncAttributeMaxDynamicSharedMemorySize, SMEM_DYN);

    // 0) zero per-row sumsq stats (32768 floats)
    zero_stats<<<32, 256>>>(sumsq);

    // 1) QKV projection: [4096,512] @ [1536,512]^T + bias
    gemm_nt_tc<<<dim3(QKVDIM / 64, (BATCH * SEQ) / 128, 1), 256, SMEM_DYN>>>(
        x, DMODEL, 0, 0, qkv_w, DMODEL, 0, 0, qkv, QKVDIM, 0, 0,
        DMODEL, 1.0f, qkv_b, nullptr);

    // 2) scores = 0.125 * Q K^T per (b,h); epilogue accumulates row sumsq
    gemm_nt_tc<<<dim3(SEQ / 64, SEQ / 128, BATCH * HEADS), 256, SMEM_DYN>>>(
        qkv, QKVDIM, (long long)SEQ * QKVDIM, HDIM,
        qkv + DMODEL, QKVDIM, (long long)SEQ * QKVDIM, HDIM,
        scores, SEQ, (long long)HEADS * SEQ * SEQ, (long long)SEQ * SEQ,
        HDIM, 0.125f, nullptr, sumsq);

    // 3) fused norm+softmax+PV
    pv_tc<<<dim3(1, SEQ / 128, BATCH * HEADS), 256, SMEM_DYN>>>(scores, qkv, sumsq, attn);

    // 4) final projection: [4096,512] @ [512,512]^T + bias
    gemm_nt_tc<<<dim3(DMODEL / 64, (BATCH * SEQ) / 128, 1), 256, SMEM_DYN>>>(
        attn, DMODEL, 0, 0, proj_w, DMODEL, 0, 0, out, DMODEL, 0, 0,
        DMODEL, 1.0f, proj_b, nullptr);
}

// round 8
// speedup vs baseline: 1.8979x; 1.0632x over previous
#include <cuda_runtime.h>
#include <cuda_bf16.h>
#include <math.h>
#include <stdint.h>

// Problem constants: B=2, N=2048, D=512, H=8, hd=64
#define BATCH 2
#define SEQ   2048
#define DMODEL 512
#define HEADS 8
#define HDIM  64
#define QKVDIM 1536

// Scratch (no cudaMalloc -> __device__ globals)
__device__ float g_qkv[(size_t)BATCH * SEQ * QKVDIM];                 // 25 MB
__device__ float g_scores[(size_t)BATCH * HEADS * SEQ * SEQ];         // 256 MB
__device__ float g_attn[(size_t)BATCH * SEQ * DMODEL];                // 8 MB
__device__ float g_sumsq[(size_t)BATCH * HEADS * SEQ];                // 128 KB

// ---------------------------------------------------------------------------
// Shared-memory layout: bf16, row stride 72 elements, 16B units bank-rotated
// per row -> conflict-free ldmatrix, ~2-way worst-case staging stores.
// ---------------------------------------------------------------------------
#define SSTR 72
__device__ __forceinline__ uint32_t soff(int row, int k) {
    int u = ((k >> 3) + (row >> 2)) & 7;
    return (uint32_t)(row * SSTR + (u << 3) + (k & 7));
}

__device__ __forceinline__ uint32_t smem_u32(const void* p) {
    uint32_t a;
    asm("{ .reg .u64 t; cvta.to.shared.u64 t, %1; cvt.u32.u64 %0, t; }" : "=r"(a) : "l"(p));
    return a;
}

__device__ __forceinline__ void ldsm_x4(uint32_t* r, uint32_t addr) {
    asm volatile("ldmatrix.sync.aligned.m8n8.x4.shared.b16 {%0,%1,%2,%3}, [%4];"
        : "=r"(r[0]), "=r"(r[1]), "=r"(r[2]), "=r"(r[3]) : "r"(addr));
}

__device__ __forceinline__ void mma_bf16(float* c, const uint32_t* a, const uint32_t* b) {
    asm volatile(
        "mma.sync.aligned.m16n8k16.row.col.f32.bf16.bf16.f32 "
        "{%0,%1,%2,%3}, {%4,%5,%6,%7}, {%8,%9}, {%0,%1,%2,%3};"
        : "+f"(c[0]), "+f"(c[1]), "+f"(c[2]), "+f"(c[3])
        : "r"(a[0]), "r"(a[1]), "r"(a[2]), "r"(a[3]), "r"(b[0]), "r"(b[1]));
}

// split fp32x4 (4 consecutive k of one row) -> hi/lo bf16 slabs
__device__ __forceinline__ void st_split4(char* hiB, char* loB, int row, int k, float4 v) {
    __nv_bfloat162 h0 = __floats2bfloat162_rn(v.x, v.y);
    __nv_bfloat162 l0 = __floats2bfloat162_rn(v.x - __low2float(h0), v.y - __high2float(h0));
    __nv_bfloat162 h1 = __floats2bfloat162_rn(v.z, v.w);
    __nv_bfloat162 l1 = __floats2bfloat162_rn(v.z - __low2float(h1), v.w - __high2float(h1));
    uint32_t o0 = soff(row, k) * 2;
    uint32_t o1 = soff(row, k + 2) * 2;
    *(__nv_bfloat162*)(hiB + o0) = h0; *(__nv_bfloat162*)(hiB + o1) = h1;
    *(__nv_bfloat162*)(loB + o0) = l0; *(__nv_bfloat162*)(loB + o1) = l1;
}

// smem buffer offsets (bytes) within one slab buffer
#define A_HI 0
#define A_LO 18432
#define B_HI 36864
#define B_LO 46080
#define BUFSZ 55296
#define SMEM_1BUF 55296
#define SMEM_2BUF 110592

// ---------------------------------------------------------------------------
// One 64-wide K slab of MMAs. Warp grid 4(M) x 2(N); warp tile 32x32.
// 3-chain split bf16: hi*hi + hi*lo + lo*hi.
// ---------------------------------------------------------------------------
__device__ __forceinline__ void mma_slab(uint32_t sbase, float c[2][4][4], int wid, int lane) {
    const int wm = (wid & 3) << 5;
    const int wn = (wid >> 2) << 5;
    const int lrow = lane & 15, lhalf = lane >> 4;
    const int bq = lane >> 3, br = lane & 7;
    const int bnq = ((bq >> 1) << 3) + br;   // n offset within 16-block
    const int bk8 = (bq & 1) << 3;           // k half
#pragma unroll
    for (int kk = 0; kk < 64; kk += 16) {
        uint32_t ah[2][4], al[2][4], bh[2][4], bl[2][4];
#pragma unroll
        for (int mf = 0; mf < 2; mf++) {
            uint32_t o = soff(wm + (mf << 4) + lrow, kk + (lhalf << 3)) * 2;
            ldsm_x4(ah[mf], sbase + A_HI + o);
            ldsm_x4(al[mf], sbase + A_LO + o);
        }
#pragma unroll
        for (int np = 0; np < 2; np++) {
            uint32_t o = soff(wn + (np << 4) + bnq, kk + bk8) * 2;
            ldsm_x4(bh[np], sbase + B_HI + o);
            ldsm_x4(bl[np], sbase + B_LO + o);
        }
#pragma unroll
        for (int mf = 0; mf < 2; mf++)
#pragma unroll
            for (int nf = 0; nf < 4; nf++) {
                const uint32_t* bhp = &bh[nf >> 1][(nf & 1) << 1];
                const uint32_t* blp = &bl[nf >> 1][(nf & 1) << 1];
                mma_bf16(c[mf][nf], ah[mf], bhp);
                mma_bf16(c[mf][nf], ah[mf], blp);
                mma_bf16(c[mf][nf], al[mf], bhp);
            }
    }
}

// ============================================================================
// Generic NT GEMM: C[m,n] = alpha*sum_k A[m,k]*B[n,k] (+bias[n]).
// CTA tile 128(M) x 64(N), K multiple of 64. Software-pipelined, double-
// buffered smem (launch with SMEM_2BUF; S==1 launches may use SMEM_1BUF).
// MINB: min blocks/SM hint (2 caps regs at 128 for the K=64 scores launch).
// ============================================================================
template<int MINB>
__global__ __launch_bounds__(256, MINB) void gemm_nt_tc(
    const float* __restrict__ A, int lda, long long sAb, long long sAh,
    const float* __restrict__ B, int ldb, long long sBb, long long sBh,
    float* __restrict__ C, int ldc, long long sCb, long long sCh,
    int K, float alpha, const float* __restrict__ bias, float* __restrict__ sumsq)
{
    extern __shared__ char sm[];
    const int t = threadIdx.x, lane = t & 31, wid = t >> 5;
    const int z = blockIdx.z, zb = z >> 3, zh = z & 7;
    const int m0 = blockIdx.y * 128;
    const int n0 = blockIdx.x * 64;
    A += (size_t)zb * sAb + (size_t)zh * sAh;
    B += (size_t)zb * sBb + (size_t)zh * sBh;
    C += (size_t)zb * sCb + (size_t)zh * sCh;

    const uint32_t sbase = smem_u32(sm);
    const int ar = t >> 4, ac4 = (t & 15) << 2;

    float4 av[8], bv[4];
    auto load_slab = [&](int k0) {
#pragma unroll
        for (int i = 0; i < 8; i++)
            av[i] = *(const float4*)(A + (size_t)(m0 + (i << 4) + ar) * lda + k0 + ac4);
#pragma unroll
        for (int i = 0; i < 4; i++)
            bv[i] = *(const float4*)(B + (size_t)(n0 + (i << 4) + ar) * ldb + k0 + ac4);
    };
    auto store_slab = [&](int bs) {
        char* bp = sm + bs * BUFSZ;
#pragma unroll
        for (int i = 0; i < 8; i++) st_split4(bp + A_HI, bp + A_LO, (i << 4) + ar, ac4, av[i]);
#pragma unroll
        for (int i = 0; i < 4; i++) st_split4(bp + B_HI, bp + B_LO, (i << 4) + ar, ac4, bv[i]);
    };

    float c[2][4][4] = {};
    load_slab(0);
    store_slab(0);
    __syncthreads();

    const int S = K >> 6;
    for (int s = 0; s < S; s++) {
        if (s + 1 < S) load_slab((s + 1) << 6);
        mma_slab(sbase + (s & 1) * BUFSZ, c, wid, lane);
        if (s + 1 < S) {
            store_slab((s + 1) & 1);
            __syncthreads();
        }
    }

    // epilogue
    const int wm = (wid & 3) << 5, wn = (wid >> 2) << 5;
    const int r4 = lane >> 2, c2 = (lane & 3) << 1;
    float ss[4] = {0.f, 0.f, 0.f, 0.f};
#pragma unroll
    for (int mf = 0; mf < 2; mf++)
#pragma unroll
        for (int half = 0; half < 2; half++) {
            const int row = m0 + wm + (mf << 4) + (half << 3) + r4;
#pragma unroll
            for (int nf = 0; nf < 4; nf++) {
                const int col = n0 + wn + (nf << 3) + c2;
                float2 o;
                o.x = c[mf][nf][half * 2 + 0] * alpha;
                o.y = c[mf][nf][half * 2 + 1] * alpha;
                if (bias) { o.x += bias[col]; o.y += bias[col + 1]; }
                ss[mf * 2 + half] += o.x * o.x + o.y * o.y;
                *(float2*)&C[(size_t)row * ldc + col] = o;
            }
        }
    if (sumsq) {
#pragma unroll
        for (int q = 0; q < 4; q++) {
            float v = ss[q];
            v += __shfl_xor_sync(0xffffffffu, v, 1);
            v += __shfl_xor_sync(0xffffffffu, v, 2);
            if ((lane & 3) == 0) {
                const int row = m0 + wm + ((q >> 1) << 4) + ((q & 1) << 3) + r4;
                atomicAdd(&sumsq[(size_t)z * SEQ + row], v);
            }
        }
    }
}

// ============================================================================
// Fused norm+softmax+PV: p = exp(s * inv_norm) (|s*inv| <= 1, no max needed),
// per-row sum(p) accumulated in-CTA (CTA spans full K=2048), P@V via HMMA,
// epilogue divides by sumexp. V transposed during staging. Pipelined 2-buf.
// ============================================================================
__global__ __launch_bounds__(256, 1) void pv_tc(
    const float* __restrict__ Sm, const float* __restrict__ qkv,
    const float* __restrict__ sumsq, float* __restrict__ attn)
{
    extern __shared__ char sm[];
    __shared__ float s_inv[128];
    __shared__ float s_se[128];
    const int t = threadIdx.x, lane = t & 31, wid = t >> 5;
    const int z = blockIdx.z, b = z >> 3, h = z & 7;
    const int m0 = blockIdx.y * 128;
    const float* Sg = Sm + (size_t)z * SEQ * SEQ;
    const float* Vg = qkv + (size_t)b * SEQ * QKVDIM + 2 * DMODEL + h * HDIM;
    float* Cg = attn + (size_t)b * SEQ * DMODEL + h * HDIM;

    const uint32_t sbase = smem_u32(sm);

    if (t < 128) s_inv[t] = 1.0f / (sqrtf(sumsq[(size_t)z * SEQ + m0 + t]) + 1e-6f);
    __syncthreads();

    float se[8] = {0.f, 0.f, 0.f, 0.f, 0.f, 0.f, 0.f, 0.f};
    const int ar = t >> 4, ac4 = (t & 15) << 2;
    const int nq = t & 15;

    float4 av[8], v0[2], v1[2];
    auto load_slab = [&](int k0) {
#pragma unroll
        for (int i = 0; i < 8; i++)
            av[i] = *(const float4*)(Sg + (size_t)(m0 + (i << 4) + ar) * SEQ + k0 + ac4);
#pragma unroll
        for (int i = 0; i < 2; i++) {
            const int kp = (i << 4) + ar;   // k-pair index 0..31
            v0[i] = *(const float4*)(Vg + (size_t)(k0 + 2 * kp)     * QKVDIM + (nq << 2));
            v1[i] = *(const float4*)(Vg + (size_t)(k0 + 2 * kp + 1) * QKVDIM + (nq << 2));
        }
    };
    auto store_slab = [&](int bs) {
        char* bp = sm + bs * BUFSZ;
#pragma unroll
        for (int i = 0; i < 8; i++) {
            const int row = (i << 4) + ar;
            const float inv = s_inv[row];
            float4 p;
            p.x = __expf(av[i].x * inv);
            p.y = __expf(av[i].y * inv);
            p.z = __expf(av[i].z * inv);
            p.w = __expf(av[i].w * inv);
            se[i] += p.x + p.y + p.z + p.w;
            st_split4(bp + A_HI, bp + A_LO, row, ac4, p);
        }
#pragma unroll
        for (int i = 0; i < 2; i++) {
            const int kp = (i << 4) + ar;
            const float a0[4] = {v0[i].x, v0[i].y, v0[i].z, v0[i].w};
            const float a1[4] = {v1[i].x, v1[i].y, v1[i].z, v1[i].w};
#pragma unroll
            for (int j = 0; j < 4; j++) {
                const int row = (nq << 2) + j;   // n index
                __nv_bfloat162 hh = __floats2bfloat162_rn(a0[j], a1[j]);
                __nv_bfloat162 ll = __floats2bfloat162_rn(a0[j] - __low2float(hh),
                                                          a1[j] - __high2float(hh));
                const uint32_t o = soff(row, 2 * kp) * 2;
                *(__nv_bfloat162*)(bp + B_HI + o) = hh;
                *(__nv_bfloat162*)(bp + B_LO + o) = ll;
            }
        }
    };

    float c[2][4][4] = {};
    load_slab(0);
    store_slab(0);
    __syncthreads();

    const int S = SEQ / 64;
    for (int s = 0; s < S; s++) {
        if (s + 1 < S) load_slab((s + 1) << 6);
        mma_slab(sbase + (s & 1) * BUFSZ, c, wid, lane);
        if (s + 1 < S) {
            store_slab((s + 1) & 1);
            __syncthreads();
        }
    }

    // per-row sumexp: reduce across the 16 threads sharing each row
#pragma unroll
    for (int i = 0; i < 8; i++) {
        float v = se[i];
        v += __shfl_xor_sync(0xffffffffu, v, 1);
        v += __shfl_xor_sync(0xffffffffu, v, 2);
        v += __shfl_xor_sync(0xffffffffu, v, 4);
        v += __shfl_xor_sync(0xffffffffu, v, 8);
        if ((t & 15) == 0) s_se[(i << 4) + ar] = v;
    }
    __syncthreads();

    const int wm = (wid & 3) << 5, wn = (wid >> 2) << 5;
    const int r4 = lane >> 2, c2 = (lane & 3) << 1;
#pragma unroll
    for (int mf = 0; mf < 2; mf++)
#pragma unroll
        for (int half = 0; half < 2; half++) {
            const int rl = wm + (mf << 4) + (half << 3) + r4;
            const float rse = 1.0f / s_se[rl];
#pragma unroll
            for (int nf = 0; nf < 4; nf++) {
                const int col = wn + (nf << 3) + c2;
                float2 o;
                o.x = c[mf][nf][half * 2 + 0] * rse;
                o.y = c[mf][nf][half * 2 + 1] * rse;
                *(float2*)&Cg[(size_t)(m0 + rl) * DMODEL + col] = o;
            }
        }
}

__global__ void zero_stats(float* p) {
    ((float4*)p)[blockIdx.x * blockDim.x + threadIdx.x] = make_float4(0.f, 0.f, 0.f, 0.f);
}

// ---------------------------------------------------------------------------
extern "C" void kernel_launch(void* const* d_in, const int* in_sizes, int n_in,
                              void* d_out, int out_size)
{
    const float* x      = (const float*)d_in[0];
    const float* qkv_w  = (const float*)d_in[1];
    const float* qkv_b  = (const float*)d_in[2];
    const float* proj_w = (const float*)d_in[3];
    const float* proj_b = (const float*)d_in[4];
    float* out = (float*)d_out;

    float *qkv, *scores, *attn, *sumsq;
    cudaGetSymbolAddress((void**)&qkv, g_qkv);
    cudaGetSymbolAddress((void**)&scores, g_scores);
    cudaGetSymbolAddress((void**)&attn, g_attn);
    cudaGetSymbolAddress((void**)&sumsq, g_sumsq);

    cudaFuncSetAttribute(gemm_nt_tc<1>, cudaFuncAttributeMaxDynamicSharedMemorySize, SMEM_2BUF);
    cudaFuncSetAttribute(gemm_nt_tc<2>, cudaFuncAttributeMaxDynamicSharedMemorySize, SMEM_1BUF);
    cudaFuncSetAttribute(pv_tc, cudaFuncAttributeMaxDynamicSharedMemorySize, SMEM_2BUF);

    // 0) zero per-row sumsq stats (32768 floats)
    zero_stats<<<32, 256>>>(sumsq);

    // 1) QKV projection: [4096,512] @ [1536,512]^T + bias  (K=512, pipelined)
    gemm_nt_tc<1><<<dim3(QKVDIM / 64, (BATCH * SEQ) / 128, 1), 256, SMEM_2BUF>>>(
        x, DMODEL, 0, 0, qkv_w, DMODEL, 0, 0, qkv, QKVDIM, 0, 0,
        DMODEL, 1.0f, qkv_b, nullptr);

    // 2) scores = 0.125 * Q K^T per (b,h); K=64 (single slab, 1-buf, 2 CTA/SM)
    gemm_nt_tc<2><<<dim3(SEQ / 64, SEQ / 128, BATCH * HEADS), 256, SMEM_1BUF>>>(
        qkv, QKVDIM, (long long)SEQ * QKVDIM, HDIM,
        qkv + DMODEL, QKVDIM, (long long)SEQ * QKVDIM, HDIM,
        scores, SEQ, (long long)HEADS * SEQ * SEQ, (long long)SEQ * SEQ,
        HDIM, 0.125f, nullptr, sumsq);

    // 3) fused norm+softmax+PV (K=2048, pipelined)
    pv_tc<<<dim3(1, SEQ / 128, BATCH * HEADS), 256, SMEM_2BUF>>>(scores, qkv, sumsq, attn);

    // 4) final projection: [4096,512] @ [512,512]^T + bias (K=512, pipelined)
    gemm_nt_tc<1><<<dim3(DMODEL / 64, (BATCH * SEQ) / 128, 1), 256, SMEM_2BUF>>>(
        attn, DMODEL, 0, 0, proj_w, DMODEL, 0, 0, out, DMODEL, 0, 0,
        DMODEL, 1.0f, proj_b, nullptr);
}

// round 9
// speedup vs baseline: 2.2003x; 1.1594x over previous
#include <cuda_runtime.h>
#include <cuda_bf16.h>
#include <math.h>
#include <stdint.h>

// Problem constants: B=2, N=2048, D=512, H=8, hd=64
#define BATCH 2
#define SEQ   2048
#define DMODEL 512
#define HEADS 8
#define HDIM  64
#define QKVDIM 1536
#define ZTOT  (BATCH * HEADS)        // 16
#define ZSTRIDE ((size_t)SEQ * HDIM) // 131072

// Scratch (no cudaMalloc -> __device__ globals)
__device__ float g_scores[(size_t)ZTOT * SEQ * SEQ];          // 256 MB
__device__ float g_attn[(size_t)BATCH * SEQ * DMODEL];        // 8 MB
__device__ float g_sumsq[(size_t)ZTOT * SEQ];                 // 128 KB
// pre-split bf16 operands, produced by qkv epilogue
__device__ __nv_bfloat16 g_qh[(size_t)ZTOT * SEQ * HDIM];     // 4 MB each
__device__ __nv_bfloat16 g_ql[(size_t)ZTOT * SEQ * HDIM];
__device__ __nv_bfloat16 g_kh[(size_t)ZTOT * SEQ * HDIM];
__device__ __nv_bfloat16 g_kl[(size_t)ZTOT * SEQ * HDIM];
__device__ __nv_bfloat16 g_vh[(size_t)ZTOT * HDIM * SEQ];     // transposed [z][d][n]
__device__ __nv_bfloat16 g_vl[(size_t)ZTOT * HDIM * SEQ];

// ---------------------------------------------------------------------------
// Shared-memory layout: bf16, row stride 72 elements, 16B units bank-rotated
// per row -> conflict-free ldmatrix, ~2-way worst-case staging stores.
// ---------------------------------------------------------------------------
#define SSTR 72
__device__ __forceinline__ uint32_t soff(int row, int k) {
    int u = ((k >> 3) + (row >> 2)) & 7;
    return (uint32_t)(row * SSTR + (u << 3) + (k & 7));
}

__device__ __forceinline__ uint32_t smem_u32(const void* p) {
    uint32_t a;
    asm("{ .reg .u64 t; cvta.to.shared.u64 t, %1; cvt.u32.u64 %0, t; }" : "=r"(a) : "l"(p));
    return a;
}

__device__ __forceinline__ void ldsm_x4(uint32_t* r, uint32_t addr) {
    asm volatile("ldmatrix.sync.aligned.m8n8.x4.shared.b16 {%0,%1,%2,%3}, [%4];"
        : "=r"(r[0]), "=r"(r[1]), "=r"(r[2]), "=r"(r[3]) : "r"(addr));
}

__device__ __forceinline__ void mma_bf16(float* c, const uint32_t* a, const uint32_t* b) {
    asm volatile(
        "mma.sync.aligned.m16n8k16.row.col.f32.bf16.bf16.f32 "
        "{%0,%1,%2,%3}, {%4,%5,%6,%7}, {%8,%9}, {%0,%1,%2,%3};"
        : "+f"(c[0]), "+f"(c[1]), "+f"(c[2]), "+f"(c[3])
        : "r"(a[0]), "r"(a[1]), "r"(a[2]), "r"(a[3]), "r"(b[0]), "r"(b[1]));
}

__device__ __forceinline__ void cp16(uint32_t dst, const void* src) {
    asm volatile("cp.async.cg.shared.global [%0], [%1], 16;" :: "r"(dst), "l"(src));
}
#define CP_COMMIT() asm volatile("cp.async.commit_group;" ::: "memory")
#define CP_WAIT0()  asm volatile("cp.async.wait_group 0;" ::: "memory")

// split fp32x4 (4 consecutive k of one row) -> hi/lo bf16 slabs
__device__ __forceinline__ void st_split4(char* hiB, char* loB, int row, int k, float4 v) {
    __nv_bfloat162 h0 = __floats2bfloat162_rn(v.x, v.y);
    __nv_bfloat162 l0 = __floats2bfloat162_rn(v.x - __low2float(h0), v.y - __high2float(h0));
    __nv_bfloat162 h1 = __floats2bfloat162_rn(v.z, v.w);
    __nv_bfloat162 l1 = __floats2bfloat162_rn(v.z - __low2float(h1), v.w - __high2float(h1));
    uint32_t o0 = soff(row, k) * 2;
    uint32_t o1 = soff(row, k + 2) * 2;
    *(__nv_bfloat162*)(hiB + o0) = h0; *(__nv_bfloat162*)(hiB + o1) = h1;
    *(__nv_bfloat162*)(loB + o0) = l0; *(__nv_bfloat162*)(loB + o1) = l1;
}

// smem buffer offsets (bytes) within one slab buffer
#define A_HI 0
#define A_LO 18432
#define B_HI 36864
#define B_LO 46080
#define BUFSZ 55296
#define SMEM_1BUF 55296
#define SMEM_2BUF 110592

// ---------------------------------------------------------------------------
// One 64-wide K slab of MMAs. Warp grid 4(M) x 2(N); warp tile 32x32.
// 3-chain split bf16: hi*hi + hi*lo + lo*hi.
// ---------------------------------------------------------------------------
__device__ __forceinline__ void mma_slab(uint32_t sbase, float c[2][4][4], int wid, int lane) {
    const int wm = (wid & 3) << 5;
    const int wn = (wid >> 2) << 5;
    const int lrow = lane & 15, lhalf = lane >> 4;
    const int bq = lane >> 3, br = lane & 7;
    const int bnq = ((bq >> 1) << 3) + br;
    const int bk8 = (bq & 1) << 3;
#pragma unroll
    for (int kk = 0; kk < 64; kk += 16) {
        uint32_t ah[2][4], al[2][4], bh[2][4], bl[2][4];
#pragma unroll
        for (int mf = 0; mf < 2; mf++) {
            uint32_t o = soff(wm + (mf << 4) + lrow, kk + (lhalf << 3)) * 2;
            ldsm_x4(ah[mf], sbase + A_HI + o);
            ldsm_x4(al[mf], sbase + A_LO + o);
        }
#pragma unroll
        for (int np = 0; np < 2; np++) {
            uint32_t o = soff(wn + (np << 4) + bnq, kk + bk8) * 2;
            ldsm_x4(bh[np], sbase + B_HI + o);
            ldsm_x4(bl[np], sbase + B_LO + o);
        }
#pragma unroll
        for (int mf = 0; mf < 2; mf++)
#pragma unroll
            for (int nf = 0; nf < 4; nf++) {
                const uint32_t* bhp = &bh[nf >> 1][(nf & 1) << 1];
                const uint32_t* blp = &bl[nf >> 1][(nf & 1) << 1];
                mma_bf16(c[mf][nf], ah[mf], bhp);
                mma_bf16(c[mf][nf], ah[mf], blp);
                mma_bf16(c[mf][nf], al[mf], bhp);
            }
    }
}

// ============================================================================
// QKV projection: [4096,512] @ [1536,512]^T + bias. fp32 inputs, pipelined.
// Epilogue writes pre-split bf16: Q (x0.125) and K as [z][n][d]; V transposed
// to [z][d][n] via smem staging. No fp32 output.
// ============================================================================
__global__ __launch_bounds__(256) void qkv_tc(
    const float* __restrict__ A, const float* __restrict__ B,
    const float* __restrict__ bias)
{
    extern __shared__ char sm[];
    const int t = threadIdx.x, lane = t & 31, wid = t >> 5;
    const int m0 = blockIdx.y * 128;
    const int n0 = blockIdx.x * 64;
    const int lda = DMODEL, ldb = DMODEL;

    const uint32_t sbase = smem_u32(sm);
    const int ar = t >> 4, ac4 = (t & 15) << 2;

    float4 av[8], bv[4];
    auto load_slab = [&](int k0) {
#pragma unroll
        for (int i = 0; i < 8; i++)
            av[i] = *(const float4*)(A + (size_t)(m0 + (i << 4) + ar) * lda + k0 + ac4);
#pragma unroll
        for (int i = 0; i < 4; i++)
            bv[i] = *(const float4*)(B + (size_t)(n0 + (i << 4) + ar) * ldb + k0 + ac4);
    };
    auto store_slab = [&](int bs) {
        char* bp = sm + bs * BUFSZ;
#pragma unroll
        for (int i = 0; i < 8; i++) st_split4(bp + A_HI, bp + A_LO, (i << 4) + ar, ac4, av[i]);
#pragma unroll
        for (int i = 0; i < 4; i++) st_split4(bp + B_HI, bp + B_LO, (i << 4) + ar, ac4, bv[i]);
    };

    float c[2][4][4] = {};
    load_slab(0);
    store_slab(0);
    __syncthreads();
    const int S = DMODEL >> 6;
    for (int s = 0; s < S; s++) {
        if (s + 1 < S) load_slab((s + 1) << 6);
        mma_slab(sbase + (s & 1) * BUFSZ, c, wid, lane);
        if (s + 1 < S) { store_slab((s + 1) & 1); __syncthreads(); }
    }

    // ---- epilogue: classify by output-column block ----
    const int wm = (wid & 3) << 5, wn = (wid >> 2) << 5;
    const int r4 = lane >> 2, c2 = (lane & 3) << 1;
    const int typ = n0 >> 9;              // 0=q 1=k 2=v
    const int h = (n0 >> 6) & 7;
    const int b = m0 >> 11;
    const int z = b * HEADS + h;
    const int nloc = m0 & (SEQ - 1);
    const float scl = (typ == 0) ? 0.125f : 1.0f;

    if (typ < 2) {
        __nv_bfloat16* dh = ((typ == 0) ? g_qh : g_kh) + (size_t)z * ZSTRIDE;
        __nv_bfloat16* dl = ((typ == 0) ? g_ql : g_kl) + (size_t)z * ZSTRIDE;
#pragma unroll
        for (int mf = 0; mf < 2; mf++)
#pragma unroll
            for (int half = 0; half < 2; half++) {
                const int row = wm + (mf << 4) + (half << 3) + r4;
#pragma unroll
                for (int nf = 0; nf < 4; nf++) {
                    const int d = wn + (nf << 3) + c2;
                    float ox = (c[mf][nf][half * 2 + 0] + bias[n0 + d]) * scl;
                    float oy = (c[mf][nf][half * 2 + 1] + bias[n0 + d + 1]) * scl;
                    __nv_bfloat162 hh = __floats2bfloat162_rn(ox, oy);
                    __nv_bfloat162 ll = __floats2bfloat162_rn(ox - __low2float(hh),
                                                              oy - __high2float(hh));
                    size_t o = (size_t)(nloc + row) * HDIM + d;
                    *(__nv_bfloat162*)&dh[o] = hh;
                    *(__nv_bfloat162*)&dl[o] = ll;
                }
            }
    } else {
        // V: stage [d][n] transpose in smem (stride 136), then coalesced copy
        __syncthreads();
        __nv_bfloat16* th = (__nv_bfloat16*)sm;
        __nv_bfloat16* tl = th + 64 * 136;
#pragma unroll
        for (int mf = 0; mf < 2; mf++)
#pragma unroll
            for (int half = 0; half < 2; half++) {
                const int row = wm + (mf << 4) + (half << 3) + r4;
#pragma unroll
                for (int nf = 0; nf < 4; nf++) {
                    const int d = wn + (nf << 3) + c2;
                    float ox = c[mf][nf][half * 2 + 0] + bias[n0 + d];
                    float oy = c[mf][nf][half * 2 + 1] + bias[n0 + d + 1];
                    __nv_bfloat16 hx = __float2bfloat16(ox);
                    __nv_bfloat16 hy = __float2bfloat16(oy);
                    th[d * 136 + row]       = hx;
                    th[(d + 1) * 136 + row] = hy;
                    tl[d * 136 + row]       = __float2bfloat16(ox - __bfloat162float(hx));
                    tl[(d + 1) * 136 + row] = __float2bfloat16(oy - __bfloat162float(hy));
                }
            }
        __syncthreads();
        __nv_bfloat16* vh = g_vh + (size_t)z * ZSTRIDE;
        __nv_bfloat16* vl = g_vl + (size_t)z * ZSTRIDE;
#pragma unroll
        for (int i = 0; i < 8; i++) {
            int idx = i * 256 + t;         // 0..2047
            int d = idx >> 5, nm = (idx & 31) << 2;
            *(uint2*)&vh[(size_t)d * SEQ + nloc + nm] = *(uint2*)&th[d * 136 + nm];
            *(uint2*)&vl[(size_t)d * SEQ + nloc + nm] = *(uint2*)&tl[d * 136 + nm];
        }
    }
}

// ============================================================================
// scores = Q K^T per z (Q pre-scaled). Pure bf16 GEMM, cp.async operands,
// single K=64 slab. Epilogue: write fp32 scores + per-row sumsq atomics.
// ============================================================================
__global__ __launch_bounds__(256) void scores_bf(float* __restrict__ scores,
                                                 float* __restrict__ sumsq)
{
    extern __shared__ char sm[];
    const int t = threadIdx.x, lane = t & 31, wid = t >> 5;
    const int z = blockIdx.z;
    const int m0 = blockIdx.y * 128;
    const int n0 = blockIdx.x * 64;
    const __nv_bfloat16* qh = g_qh + (size_t)z * ZSTRIDE;
    const __nv_bfloat16* ql = g_ql + (size_t)z * ZSTRIDE;
    const __nv_bfloat16* kh = g_kh + (size_t)z * ZSTRIDE;
    const __nv_bfloat16* kl = g_kl + (size_t)z * ZSTRIDE;
    const uint32_t sbase = smem_u32(sm);

#pragma unroll
    for (int i = 0; i < 4; i++) {
        int idx = i * 256 + t;             // 0..1023
        int row = idx >> 3, q8 = (idx & 7) << 3;
        uint32_t dsw = soff(row, q8) * 2;
        cp16(sbase + A_HI + dsw, qh + (size_t)(m0 + row) * HDIM + q8);
        cp16(sbase + A_LO + dsw, ql + (size_t)(m0 + row) * HDIM + q8);
    }
#pragma unroll
    for (int i = 0; i < 2; i++) {
        int idx = i * 256 + t;             // 0..511
        int row = idx >> 3, q8 = (idx & 7) << 3;
        uint32_t dsw = soff(row, q8) * 2;
        cp16(sbase + B_HI + dsw, kh + (size_t)(n0 + row) * HDIM + q8);
        cp16(sbase + B_LO + dsw, kl + (size_t)(n0 + row) * HDIM + q8);
    }
    CP_COMMIT();
    CP_WAIT0();
    __syncthreads();

    float c[2][4][4] = {};
    mma_slab(sbase, c, wid, lane);

    float* C = scores + (size_t)z * SEQ * SEQ;
    const int wm = (wid & 3) << 5, wn = (wid >> 2) << 5;
    const int r4 = lane >> 2, c2 = (lane & 3) << 1;
    float ss[4] = {0.f, 0.f, 0.f, 0.f};
#pragma unroll
    for (int mf = 0; mf < 2; mf++)
#pragma unroll
        for (int half = 0; half < 2; half++) {
            const int row = m0 + wm + (mf << 4) + (half << 3) + r4;
#pragma unroll
            for (int nf = 0; nf < 4; nf++) {
                const int col = n0 + wn + (nf << 3) + c2;
                float2 o = make_float2(c[mf][nf][half * 2 + 0], c[mf][nf][half * 2 + 1]);
                ss[mf * 2 + half] += o.x * o.x + o.y * o.y;
                *(float2*)&C[(size_t)row * SEQ + col] = o;
            }
        }
#pragma unroll
    for (int q = 0; q < 4; q++) {
        float v = ss[q];
        v += __shfl_xor_sync(0xffffffffu, v, 1);
        v += __shfl_xor_sync(0xffffffffu, v, 2);
        if ((lane & 3) == 0) {
            const int row = m0 + wm + ((q >> 1) << 4) + ((q & 1) << 3) + r4;
            atomicAdd(&sumsq[(size_t)z * SEQ + row], v);
        }
    }
}

// ============================================================================
// Fused norm+softmax+PV: p = exp(s*inv) (|s*inv|<=1), in-CTA sum(p),
// P@V via HMMA with V pre-split+transposed arriving by cp.async.
// ============================================================================
__global__ __launch_bounds__(256, 2) void pv_tc(
    const float* __restrict__ Sm, const float* __restrict__ sumsq,
    float* __restrict__ attn)
{
    extern __shared__ char sm[];
    __shared__ float s_inv[128];
    __shared__ float s_se[128];
    const int t = threadIdx.x, lane = t & 31, wid = t >> 5;
    const int z = blockIdx.z, b = z >> 3, h = z & 7;
    const int m0 = blockIdx.y * 128;
    const float* Sg = Sm + (size_t)z * SEQ * SEQ;
    const __nv_bfloat16* vh = g_vh + (size_t)z * ZSTRIDE;
    const __nv_bfloat16* vl = g_vl + (size_t)z * ZSTRIDE;
    float* Cg = attn + (size_t)b * SEQ * DMODEL + h * HDIM;
    const uint32_t sbase = smem_u32(sm);

    if (t < 128) s_inv[t] = 1.0f / (sqrtf(sumsq[(size_t)z * SEQ + m0 + t]) + 1e-6f);
    __syncthreads();

    float se[8] = {0.f, 0.f, 0.f, 0.f, 0.f, 0.f, 0.f, 0.f};
    const int ar = t >> 4, ac4 = (t & 15) << 2;

    float4 av[8];
    auto load_A = [&](int k0) {
#pragma unroll
        for (int i = 0; i < 8; i++)
            av[i] = *(const float4*)(Sg + (size_t)(m0 + (i << 4) + ar) * SEQ + k0 + ac4);
    };
    auto store_A = [&](int bs) {
        char* bp = sm + bs * BUFSZ;
#pragma unroll
        for (int i = 0; i < 8; i++) {
            const int row = (i << 4) + ar;
            const float inv = s_inv[row];
            float4 p;
            p.x = __expf(av[i].x * inv);
            p.y = __expf(av[i].y * inv);
            p.z = __expf(av[i].z * inv);
            p.w = __expf(av[i].w * inv);
            se[i] += p.x + p.y + p.z + p.w;
            st_split4(bp + A_HI, bp + A_LO, row, ac4, p);
        }
    };
    auto cp_B = [&](int bs, int k0) {
        uint32_t db = sbase + bs * BUFSZ;
#pragma unroll
        for (int i = 0; i < 2; i++) {
            int idx = i * 256 + t;         // 0..511
            int d = idx >> 3, q8 = (idx & 7) << 3;
            uint32_t dsw = soff(d, q8) * 2;
            cp16(db + B_HI + dsw, vh + (size_t)d * SEQ + k0 + q8);
            cp16(db + B_LO + dsw, vl + (size_t)d * SEQ + k0 + q8);
        }
    };

    float c[2][4][4] = {};
    cp_B(0, 0); CP_COMMIT();
    load_A(0);
    store_A(0);
    CP_WAIT0();
    __syncthreads();

    const int S = SEQ / 64;
    for (int s = 0; s < S; s++) {
        if (s + 1 < S) {
            cp_B((s + 1) & 1, (s + 1) << 6); CP_COMMIT();
            load_A((s + 1) << 6);
        }
        mma_slab(sbase + (s & 1) * BUFSZ, c, wid, lane);
        if (s + 1 < S) {
            store_A((s + 1) & 1);
            CP_WAIT0();
            __syncthreads();
        }
    }

    // per-row sumexp: reduce across the 16 threads sharing each row
#pragma unroll
    for (int i = 0; i < 8; i++) {
        float v = se[i];
        v += __shfl_xor_sync(0xffffffffu, v, 1);
        v += __shfl_xor_sync(0xffffffffu, v, 2);
        v += __shfl_xor_sync(0xffffffffu, v, 4);
        v += __shfl_xor_sync(0xffffffffu, v, 8);
        if ((t & 15) == 0) s_se[(i << 4) + ar] = v;
    }
    __syncthreads();

    const int wm = (wid & 3) << 5, wn = (wid >> 2) << 5;
    const int r4 = lane >> 2, c2 = (lane & 3) << 1;
#pragma unroll
    for (int mf = 0; mf < 2; mf++)
#pragma unroll
        for (int half = 0; half < 2; half++) {
            const int rl = wm + (mf << 4) + (half << 3) + r4;
            const float rse = 1.0f / s_se[rl];
#pragma unroll
            for (int nf = 0; nf < 4; nf++) {
                const int col = wn + (nf << 3) + c2;
                float2 o;
                o.x = c[mf][nf][half * 2 + 0] * rse;
                o.y = c[mf][nf][half * 2 + 1] * rse;
                *(float2*)&Cg[(size_t)(m0 + rl) * DMODEL + col] = o;
            }
        }
}

// ============================================================================
// Final projection (fp32 inputs): C = A @ W^T + bias  (K=512, pipelined)
// ============================================================================
__global__ __launch_bounds__(256) void proj_tc(
    const float* __restrict__ A, const float* __restrict__ B,
    float* __restrict__ C, const float* __restrict__ bias)
{
    extern __shared__ char sm[];
    const int t = threadIdx.x, lane = t & 31, wid = t >> 5;
    const int m0 = blockIdx.y * 128;
    const int n0 = blockIdx.x * 64;
    const uint32_t sbase = smem_u32(sm);
    const int ar = t >> 4, ac4 = (t & 15) << 2;

    float4 av[8], bv[4];
    auto load_slab = [&](int k0) {
#pragma unroll
        for (int i = 0; i < 8; i++)
            av[i] = *(const float4*)(A + (size_t)(m0 + (i << 4) + ar) * DMODEL + k0 + ac4);
#pragma unroll
        for (int i = 0; i < 4; i++)
            bv[i] = *(const float4*)(B + (size_t)(n0 + (i << 4) + ar) * DMODEL + k0 + ac4);
    };
    auto store_slab = [&](int bs) {
        char* bp = sm + bs * BUFSZ;
#pragma unroll
        for (int i = 0; i < 8; i++) st_split4(bp + A_HI, bp + A_LO, (i << 4) + ar, ac4, av[i]);
#pragma unroll
        for (int i = 0; i < 4; i++) st_split4(bp + B_HI, bp + B_LO, (i << 4) + ar, ac4, bv[i]);
    };

    float c[2][4][4] = {};
    load_slab(0);
    store_slab(0);
    __syncthreads();
    const int S = DMODEL >> 6;
    for (int s = 0; s < S; s++) {
        if (s + 1 < S) load_slab((s + 1) << 6);
        mma_slab(sbase + (s & 1) * BUFSZ, c, wid, lane);
        if (s + 1 < S) { store_slab((s + 1) & 1); __syncthreads(); }
    }

    const int wm = (wid & 3) << 5, wn = (wid >> 2) << 5;
    const int r4 = lane >> 2, c2 = (lane & 3) << 1;
#pragma unroll
    for (int mf = 0; mf < 2; mf++)
#pragma unroll
        for (int half = 0; half < 2; half++) {
            const int row = m0 + wm + (mf << 4) + (half << 3) + r4;
#pragma unroll
            for (int nf = 0; nf < 4; nf++) {
                const int col = n0 + wn + (nf << 3) + c2;
                float2 o;
                o.x = c[mf][nf][half * 2 + 0] + bias[col];
                o.y = c[mf][nf][half * 2 + 1] + bias[col + 1];
                *(float2*)&C[(size_t)row * DMODEL + col] = o;
            }
        }
}

__global__ void zero_stats(float* p) {
    ((float4*)p)[blockIdx.x * blockDim.x + threadIdx.x] = make_float4(0.f, 0.f, 0.f, 0.f);
}

// ---------------------------------------------------------------------------
extern "C" void kernel_launch(void* const* d_in, const int* in_sizes, int n_in,
                              void* d_out, int out_size)
{
    const float* x      = (const float*)d_in[0];
    const float* qkv_w  = (const float*)d_in[1];
    const float* qkv_b  = (const float*)d_in[2];
    const float* proj_w = (const float*)d_in[3];
    const float* proj_b = (const float*)d_in[4];
    float* out = (float*)d_out;

    float *scores, *attn, *sumsq;
    cudaGetSymbolAddress((void**)&scores, g_scores);
    cudaGetSymbolAddress((void**)&attn, g_attn);
    cudaGetSymbolAddress((void**)&sumsq, g_sumsq);

    cudaFuncSetAttribute(qkv_tc, cudaFuncAttributeMaxDynamicSharedMemorySize, SMEM_2BUF);
    cudaFuncSetAttribute(scores_bf, cudaFuncAttributeMaxDynamicSharedMemorySize, SMEM_1BUF);
    cudaFuncSetAttribute(pv_tc, cudaFuncAttributeMaxDynamicSharedMemorySize, SMEM_2BUF);
    cudaFuncSetAttribute(proj_tc, cudaFuncAttributeMaxDynamicSharedMemorySize, SMEM_2BUF);

    // 0) zero per-row sumsq stats
    zero_stats<<<32, 256>>>(sumsq);

    // 1) QKV projection + pre-split/transpose epilogue
    qkv_tc<<<dim3(QKVDIM / 64, (BATCH * SEQ) / 128), 256, SMEM_2BUF>>>(x, qkv_w, qkv_b);

    // 2) scores = Q K^T (Q pre-scaled), bf16 operands via cp.async
    scores_bf<<<dim3(SEQ / 64, SEQ / 128, ZTOT), 256, SMEM_1BUF>>>(scores, sumsq);

    // 3) fused norm+softmax+PV
    pv_tc<<<dim3(1, SEQ / 128, ZTOT), 256, SMEM_2BUF>>>(scores, sumsq, attn);

    // 4) final projection
    proj_tc<<<dim3(DMODEL / 64, (BATCH * SEQ) / 128), 256, SMEM_2BUF>>>(attn, proj_w, out, proj_b);
}

// round 10
// speedup vs baseline: 2.3401x; 1.0635x over previous
#include <cuda_runtime.h>
#include <cuda_bf16.h>
#include <cuda_fp16.h>
#include <math.h>
#include <stdint.h>

// Problem constants: B=2, N=2048, D=512, H=8, hd=64
#define BATCH 2
#define SEQ   2048
#define DMODEL 512
#define HEADS 8
#define HDIM  64
#define QKVDIM 1536
#define ZTOT  (BATCH * HEADS)        // 16
#define ZSTRIDE ((size_t)SEQ * HDIM) // 131072

// Scratch (no cudaMalloc -> __device__ globals)
__device__ __half g_scores[(size_t)ZTOT * SEQ * SEQ];         // 128 MB (fp16)
__device__ float g_attn[(size_t)BATCH * SEQ * DMODEL];        // 8 MB
__device__ float g_sumsq[(size_t)ZTOT * SEQ];                 // 128 KB
// pre-split bf16 operands, produced by qkv epilogue
__device__ __nv_bfloat16 g_qh[(size_t)ZTOT * SEQ * HDIM];     // 4 MB each
__device__ __nv_bfloat16 g_ql[(size_t)ZTOT * SEQ * HDIM];
__device__ __nv_bfloat16 g_kh[(size_t)ZTOT * SEQ * HDIM];
__device__ __nv_bfloat16 g_kl[(size_t)ZTOT * SEQ * HDIM];
__device__ __nv_bfloat16 g_vh[(size_t)ZTOT * HDIM * SEQ];     // transposed [z][d][n]
__device__ __nv_bfloat16 g_vl[(size_t)ZTOT * HDIM * SEQ];

// ---------------------------------------------------------------------------
// Shared-memory layout: bf16, row stride 72 elements, 16B units bank-rotated
// per row -> conflict-free ldmatrix, ~2-way worst-case staging stores.
// ---------------------------------------------------------------------------
#define SSTR 72
__device__ __forceinline__ uint32_t soff(int row, int k) {
    int u = ((k >> 3) + (row >> 2)) & 7;
    return (uint32_t)(row * SSTR + (u << 3) + (k & 7));
}

__device__ __forceinline__ uint32_t smem_u32(const void* p) {
    uint32_t a;
    asm("{ .reg .u64 t; cvta.to.shared.u64 t, %1; cvt.u32.u64 %0, t; }" : "=r"(a) : "l"(p));
    return a;
}

__device__ __forceinline__ void ldsm_x4(uint32_t* r, uint32_t addr) {
    asm volatile("ldmatrix.sync.aligned.m8n8.x4.shared.b16 {%0,%1,%2,%3}, [%4];"
        : "=r"(r[0]), "=r"(r[1]), "=r"(r[2]), "=r"(r[3]) : "r"(addr));
}

__device__ __forceinline__ void mma_bf16(float* c, const uint32_t* a, const uint32_t* b) {
    asm volatile(
        "mma.sync.aligned.m16n8k16.row.col.f32.bf16.bf16.f32 "
        "{%0,%1,%2,%3}, {%4,%5,%6,%7}, {%8,%9}, {%0,%1,%2,%3};"
        : "+f"(c[0]), "+f"(c[1]), "+f"(c[2]), "+f"(c[3])
        : "r"(a[0]), "r"(a[1]), "r"(a[2]), "r"(a[3]), "r"(b[0]), "r"(b[1]));
}

__device__ __forceinline__ void cp16(uint32_t dst, const void* src) {
    asm volatile("cp.async.cg.shared.global [%0], [%1], 16;" :: "r"(dst), "l"(src));
}
#define CP_COMMIT() asm volatile("cp.async.commit_group;" ::: "memory")
#define CP_WAIT0()  asm volatile("cp.async.wait_group 0;" ::: "memory")

// split fp32x4 (4 consecutive k of one row) -> hi/lo bf16 slabs
__device__ __forceinline__ void st_split4(char* hiB, char* loB, int row, int k, float4 v) {
    __nv_bfloat162 h0 = __floats2bfloat162_rn(v.x, v.y);
    __nv_bfloat162 l0 = __floats2bfloat162_rn(v.x - __low2float(h0), v.y - __high2float(h0));
    __nv_bfloat162 h1 = __floats2bfloat162_rn(v.z, v.w);
    __nv_bfloat162 l1 = __floats2bfloat162_rn(v.z - __low2float(h1), v.w - __high2float(h1));
    uint32_t o0 = soff(row, k) * 2;
    uint32_t o1 = soff(row, k + 2) * 2;
    *(__nv_bfloat162*)(hiB + o0) = h0; *(__nv_bfloat162*)(hiB + o1) = h1;
    *(__nv_bfloat162*)(loB + o0) = l0; *(__nv_bfloat162*)(loB + o1) = l1;
}

// smem buffer offsets (bytes) within one slab buffer
#define A_HI 0
#define A_LO 18432
#define B_HI 36864
#define B_LO 46080
#define BUFSZ 55296
#define SMEM_1BUF 55296
#define SMEM_2BUF 110592

// ---------------------------------------------------------------------------
// One 64-wide K slab of MMAs. Warp grid 4(M) x 2(N); warp tile 32x32.
// 3-chain split bf16: hi*hi + hi*lo + lo*hi.
// ---------------------------------------------------------------------------
__device__ __forceinline__ void mma_slab(uint32_t sbase, float c[2][4][4], int wid, int lane) {
    const int wm = (wid & 3) << 5;
    const int wn = (wid >> 2) << 5;
    const int lrow = lane & 15, lhalf = lane >> 4;
    const int bq = lane >> 3, br = lane & 7;
    const int bnq = ((bq >> 1) << 3) + br;
    const int bk8 = (bq & 1) << 3;
#pragma unroll
    for (int kk = 0; kk < 64; kk += 16) {
        uint32_t ah[2][4], al[2][4], bh[2][4], bl[2][4];
#pragma unroll
        for (int mf = 0; mf < 2; mf++) {
            uint32_t o = soff(wm + (mf << 4) + lrow, kk + (lhalf << 3)) * 2;
            ldsm_x4(ah[mf], sbase + A_HI + o);
            ldsm_x4(al[mf], sbase + A_LO + o);
        }
#pragma unroll
        for (int np = 0; np < 2; np++) {
            uint32_t o = soff(wn + (np << 4) + bnq, kk + bk8) * 2;
            ldsm_x4(bh[np], sbase + B_HI + o);
            ldsm_x4(bl[np], sbase + B_LO + o);
        }
#pragma unroll
        for (int mf = 0; mf < 2; mf++)
#pragma unroll
            for (int nf = 0; nf < 4; nf++) {
                const uint32_t* bhp = &bh[nf >> 1][(nf & 1) << 1];
                const uint32_t* blp = &bl[nf >> 1][(nf & 1) << 1];
                mma_bf16(c[mf][nf], ah[mf], bhp);
                mma_bf16(c[mf][nf], ah[mf], blp);
                mma_bf16(c[mf][nf], al[mf], bhp);
            }
    }
}

// ============================================================================
// QKV projection: [4096,512] @ [1536,512]^T + bias. fp32 inputs, pipelined.
// Epilogue writes pre-split bf16: Q (x0.125) and K as [z][n][d]; V transposed
// to [z][d][n] via smem staging. No fp32 output.
// ============================================================================
__global__ __launch_bounds__(256) void qkv_tc(
    const float* __restrict__ A, const float* __restrict__ B,
    const float* __restrict__ bias)
{
    extern __shared__ char sm[];
    const int t = threadIdx.x, lane = t & 31, wid = t >> 5;
    const int m0 = blockIdx.y * 128;
    const int n0 = blockIdx.x * 64;
    const int lda = DMODEL, ldb = DMODEL;

    const uint32_t sbase = smem_u32(sm);
    const int ar = t >> 4, ac4 = (t & 15) << 2;

    float4 av[8], bv[4];
    auto load_slab = [&](int k0) {
#pragma unroll
        for (int i = 0; i < 8; i++)
            av[i] = *(const float4*)(A + (size_t)(m0 + (i << 4) + ar) * lda + k0 + ac4);
#pragma unroll
        for (int i = 0; i < 4; i++)
            bv[i] = *(const float4*)(B + (size_t)(n0 + (i << 4) + ar) * ldb + k0 + ac4);
    };
    auto store_slab = [&](int bs) {
        char* bp = sm + bs * BUFSZ;
#pragma unroll
        for (int i = 0; i < 8; i++) st_split4(bp + A_HI, bp + A_LO, (i << 4) + ar, ac4, av[i]);
#pragma unroll
        for (int i = 0; i < 4; i++) st_split4(bp + B_HI, bp + B_LO, (i << 4) + ar, ac4, bv[i]);
    };

    float c[2][4][4] = {};
    load_slab(0);
    store_slab(0);
    __syncthreads();
    const int S = DMODEL >> 6;
    for (int s = 0; s < S; s++) {
        if (s + 1 < S) load_slab((s + 1) << 6);
        mma_slab(sbase + (s & 1) * BUFSZ, c, wid, lane);
        if (s + 1 < S) { store_slab((s + 1) & 1); __syncthreads(); }
    }

    // ---- epilogue: classify by output-column block ----
    const int wm = (wid & 3) << 5, wn = (wid >> 2) << 5;
    const int r4 = lane >> 2, c2 = (lane & 3) << 1;
    const int typ = n0 >> 9;              // 0=q 1=k 2=v
    const int h = (n0 >> 6) & 7;
    const int b = m0 >> 11;
    const int z = b * HEADS + h;
    const int nloc = m0 & (SEQ - 1);
    const float scl = (typ == 0) ? 0.125f : 1.0f;

    if (typ < 2) {
        __nv_bfloat16* dh = ((typ == 0) ? g_qh : g_kh) + (size_t)z * ZSTRIDE;
        __nv_bfloat16* dl = ((typ == 0) ? g_ql : g_kl) + (size_t)z * ZSTRIDE;
#pragma unroll
        for (int mf = 0; mf < 2; mf++)
#pragma unroll
            for (int half = 0; half < 2; half++) {
                const int row = wm + (mf << 4) + (half << 3) + r4;
#pragma unroll
                for (int nf = 0; nf < 4; nf++) {
                    const int d = wn + (nf << 3) + c2;
                    float ox = (c[mf][nf][half * 2 + 0] + bias[n0 + d]) * scl;
                    float oy = (c[mf][nf][half * 2 + 1] + bias[n0 + d + 1]) * scl;
                    __nv_bfloat162 hh = __floats2bfloat162_rn(ox, oy);
                    __nv_bfloat162 ll = __floats2bfloat162_rn(ox - __low2float(hh),
                                                              oy - __high2float(hh));
                    size_t o = (size_t)(nloc + row) * HDIM + d;
                    *(__nv_bfloat162*)&dh[o] = hh;
                    *(__nv_bfloat162*)&dl[o] = ll;
                }
            }
    } else {
        // V: stage [d][n] transpose in smem (stride 136), then coalesced copy
        __syncthreads();
        __nv_bfloat16* th = (__nv_bfloat16*)sm;
        __nv_bfloat16* tl = th + 64 * 136;
#pragma unroll
        for (int mf = 0; mf < 2; mf++)
#pragma unroll
            for (int half = 0; half < 2; half++) {
                const int row = wm + (mf << 4) + (half << 3) + r4;
#pragma unroll
                for (int nf = 0; nf < 4; nf++) {
                    const int d = wn + (nf << 3) + c2;
                    float ox = c[mf][nf][half * 2 + 0] + bias[n0 + d];
                    float oy = c[mf][nf][half * 2 + 1] + bias[n0 + d + 1];
                    __nv_bfloat16 hx = __float2bfloat16(ox);
                    __nv_bfloat16 hy = __float2bfloat16(oy);
                    th[d * 136 + row]       = hx;
                    th[(d + 1) * 136 + row] = hy;
                    tl[d * 136 + row]       = __float2bfloat16(ox - __bfloat162float(hx));
                    tl[(d + 1) * 136 + row] = __float2bfloat16(oy - __bfloat162float(hy));
                }
            }
        __syncthreads();
        __nv_bfloat16* vh = g_vh + (size_t)z * ZSTRIDE;
        __nv_bfloat16* vl = g_vl + (size_t)z * ZSTRIDE;
#pragma unroll
        for (int i = 0; i < 8; i++) {
            int idx = i * 256 + t;         // 0..2047
            int d = idx >> 5, nm = (idx & 31) << 2;
            *(uint2*)&vh[(size_t)d * SEQ + nloc + nm] = *(uint2*)&th[d * 136 + nm];
            *(uint2*)&vl[(size_t)d * SEQ + nloc + nm] = *(uint2*)&tl[d * 136 + nm];
        }
    }
}

// ============================================================================
// scores = Q K^T per z (Q pre-scaled). Pure bf16 GEMM, cp.async operands,
// single K=64 slab. Epilogue: write fp16 scores + per-row sumsq atomics.
// ============================================================================
__global__ __launch_bounds__(256) void scores_bf(__half* __restrict__ scores,
                                                 float* __restrict__ sumsq)
{
    extern __shared__ char sm[];
    const int t = threadIdx.x, lane = t & 31, wid = t >> 5;
    const int z = blockIdx.z;
    const int m0 = blockIdx.y * 128;
    const int n0 = blockIdx.x * 64;
    const __nv_bfloat16* qh = g_qh + (size_t)z * ZSTRIDE;
    const __nv_bfloat16* ql = g_ql + (size_t)z * ZSTRIDE;
    const __nv_bfloat16* kh = g_kh + (size_t)z * ZSTRIDE;
    const __nv_bfloat16* kl = g_kl + (size_t)z * ZSTRIDE;
    const uint32_t sbase = smem_u32(sm);

#pragma unroll
    for (int i = 0; i < 4; i++) {
        int idx = i * 256 + t;             // 0..1023
        int row = idx >> 3, q8 = (idx & 7) << 3;
        uint32_t dsw = soff(row, q8) * 2;
        cp16(sbase + A_HI + dsw, qh + (size_t)(m0 + row) * HDIM + q8);
        cp16(sbase + A_LO + dsw, ql + (size_t)(m0 + row) * HDIM + q8);
    }
#pragma unroll
    for (int i = 0; i < 2; i++) {
        int idx = i * 256 + t;             // 0..511
        int row = idx >> 3, q8 = (idx & 7) << 3;
        uint32_t dsw = soff(row, q8) * 2;
        cp16(sbase + B_HI + dsw, kh + (size_t)(n0 + row) * HDIM + q8);
        cp16(sbase + B_LO + dsw, kl + (size_t)(n0 + row) * HDIM + q8);
    }
    CP_COMMIT();
    CP_WAIT0();
    __syncthreads();

    float c[2][4][4] = {};
    mma_slab(sbase, c, wid, lane);

    __half* C = scores + (size_t)z * SEQ * SEQ;
    const int wm = (wid & 3) << 5, wn = (wid >> 2) << 5;
    const int r4 = lane >> 2, c2 = (lane & 3) << 1;
    float ss[4] = {0.f, 0.f, 0.f, 0.f};
#pragma unroll
    for (int mf = 0; mf < 2; mf++)
#pragma unroll
        for (int half = 0; half < 2; half++) {
            const int row = m0 + wm + (mf << 4) + (half << 3) + r4;
#pragma unroll
            for (int nf = 0; nf < 4; nf++) {
                const int col = n0 + wn + (nf << 3) + c2;
                float ox = c[mf][nf][half * 2 + 0];
                float oy = c[mf][nf][half * 2 + 1];
                ss[mf * 2 + half] += ox * ox + oy * oy;
                *(__half2*)&C[(size_t)row * SEQ + col] = __floats2half2_rn(ox, oy);
            }
        }
#pragma unroll
    for (int q = 0; q < 4; q++) {
        float v = ss[q];
        v += __shfl_xor_sync(0xffffffffu, v, 1);
        v += __shfl_xor_sync(0xffffffffu, v, 2);
        if ((lane & 3) == 0) {
            const int row = m0 + wm + ((q >> 1) << 4) + ((q & 1) << 3) + r4;
            atomicAdd(&sumsq[(size_t)z * SEQ + row], v);
        }
    }
}

// ============================================================================
// Fused norm+softmax+PV: p = exp(s*inv) (|s*inv|<=1), in-CTA sum(p),
// P@V via HMMA with V pre-split+transposed arriving by cp.async.
// S arrives as fp16 (half traffic, small registers).
// ============================================================================
__global__ __launch_bounds__(256, 2) void pv_tc(
    const __half* __restrict__ Sm, const float* __restrict__ sumsq,
    float* __restrict__ attn)
{
    extern __shared__ char sm[];
    __shared__ float s_inv[128];
    __shared__ float s_se[128];
    const int t = threadIdx.x, lane = t & 31, wid = t >> 5;
    const int z = blockIdx.z, b = z >> 3, h = z & 7;
    const int m0 = blockIdx.y * 128;
    const __half* Sg = Sm + (size_t)z * SEQ * SEQ;
    const __nv_bfloat16* vh = g_vh + (size_t)z * ZSTRIDE;
    const __nv_bfloat16* vl = g_vl + (size_t)z * ZSTRIDE;
    float* Cg = attn + (size_t)b * SEQ * DMODEL + h * HDIM;
    const uint32_t sbase = smem_u32(sm);

    if (t < 128) s_inv[t] = 1.0f / (sqrtf(sumsq[(size_t)z * SEQ + m0 + t]) + 1e-6f);
    __syncthreads();

    float se[8] = {0.f, 0.f, 0.f, 0.f, 0.f, 0.f, 0.f, 0.f};
    const int ar = t >> 4, ac4 = (t & 15) << 2;

    uint2 av[8];   // 4 fp16 each
    auto load_A = [&](int k0) {
#pragma unroll
        for (int i = 0; i < 8; i++)
            av[i] = *(const uint2*)(Sg + (size_t)(m0 + (i << 4) + ar) * SEQ + k0 + ac4);
    };
    auto store_A = [&](int bs) {
        char* bp = sm + bs * BUFSZ;
#pragma unroll
        for (int i = 0; i < 8; i++) {
            const int row = (i << 4) + ar;
            const float inv = s_inv[row];
            float2 f01 = __half22float2(*(__half2*)&av[i].x);
            float2 f23 = __half22float2(*(__half2*)&av[i].y);
            float4 p;
            p.x = __expf(f01.x * inv);
            p.y = __expf(f01.y * inv);
            p.z = __expf(f23.x * inv);
            p.w = __expf(f23.y * inv);
            se[i] += p.x + p.y + p.z + p.w;
            st_split4(bp + A_HI, bp + A_LO, row, ac4, p);
        }
    };
    auto cp_B = [&](int bs, int k0) {
        uint32_t db = sbase + bs * BUFSZ;
#pragma unroll
        for (int i = 0; i < 2; i++) {
            int idx = i * 256 + t;         // 0..511
            int d = idx >> 3, q8 = (idx & 7) << 3;
            uint32_t dsw = soff(d, q8) * 2;
            cp16(db + B_HI + dsw, vh + (size_t)d * SEQ + k0 + q8);
            cp16(db + B_LO + dsw, vl + (size_t)d * SEQ + k0 + q8);
        }
    };

    float c[2][4][4] = {};
    cp_B(0, 0); CP_COMMIT();
    load_A(0);
    store_A(0);
    CP_WAIT0();
    __syncthreads();

    const int S = SEQ / 64;
    for (int s = 0; s < S; s++) {
        if (s + 1 < S) {
            cp_B((s + 1) & 1, (s + 1) << 6); CP_COMMIT();
            load_A((s + 1) << 6);
        }
        mma_slab(sbase + (s & 1) * BUFSZ, c, wid, lane);
        if (s + 1 < S) {
            store_A((s + 1) & 1);
            CP_WAIT0();
            __syncthreads();
        }
    }

    // per-row sumexp: reduce across the 16 threads sharing each row
#pragma unroll
    for (int i = 0; i < 8; i++) {
        float v = se[i];
        v += __shfl_xor_sync(0xffffffffu, v, 1);
        v += __shfl_xor_sync(0xffffffffu, v, 2);
        v += __shfl_xor_sync(0xffffffffu, v, 4);
        v += __shfl_xor_sync(0xffffffffu, v, 8);
        if ((t & 15) == 0) s_se[(i << 4) + ar] = v;
    }
    __syncthreads();

    const int wm = (wid & 3) << 5, wn = (wid >> 2) << 5;
    const int r4 = lane >> 2, c2 = (lane & 3) << 1;
#pragma unroll
    for (int mf = 0; mf < 2; mf++)
#pragma unroll
        for (int half = 0; half < 2; half++) {
            const int rl = wm + (mf << 4) + (half << 3) + r4;
            const float rse = 1.0f / s_se[rl];
#pragma unroll
            for (int nf = 0; nf < 4; nf++) {
                const int col = wn + (nf << 3) + c2;
                float2 o;
                o.x = c[mf][nf][half * 2 + 0] * rse;
                o.y = c[mf][nf][half * 2 + 1] * rse;
                *(float2*)&Cg[(size_t)(m0 + rl) * DMODEL + col] = o;
            }
        }
}

// ============================================================================
// Final projection (fp32 inputs): C = A @ W^T + bias  (K=512, pipelined)
// ============================================================================
__global__ __launch_bounds__(256) void proj_tc(
    const float* __restrict__ A, const float* __restrict__ B,
    float* __restrict__ C, const float* __restrict__ bias)
{
    extern __shared__ char sm[];
    const int t = threadIdx.x, lane = t & 31, wid = t >> 5;
    const int m0 = blockIdx.y * 128;
    const int n0 = blockIdx.x * 64;
    const uint32_t sbase = smem_u32(sm);
    const int ar = t >> 4, ac4 = (t & 15) << 2;

    float4 av[8], bv[4];
    auto load_slab = [&](int k0) {
#pragma unroll
        for (int i = 0; i < 8; i++)
            av[i] = *(const float4*)(A + (size_t)(m0 + (i << 4) + ar) * DMODEL + k0 + ac4);
#pragma unroll
        for (int i = 0; i < 4; i++)
            bv[i] = *(const float4*)(B + (size_t)(n0 + (i << 4) + ar) * DMODEL + k0 + ac4);
    };
    auto store_slab = [&](int bs) {
        char* bp = sm + bs * BUFSZ;
#pragma unroll
        for (int i = 0; i < 8; i++) st_split4(bp + A_HI, bp + A_LO, (i << 4) + ar, ac4, av[i]);
#pragma unroll
        for (int i = 0; i < 4; i++) st_split4(bp + B_HI, bp + B_LO, (i << 4) + ar, ac4, bv[i]);
    };

    float c[2][4][4] = {};
    load_slab(0);
    store_slab(0);
    __syncthreads();
    const int S = DMODEL >> 6;
    for (int s = 0; s < S; s++) {
        if (s + 1 < S) load_slab((s + 1) << 6);
        mma_slab(sbase + (s & 1) * BUFSZ, c, wid, lane);
        if (s + 1 < S) { store_slab((s + 1) & 1); __syncthreads(); }
    }

    const int wm = (wid & 3) << 5, wn = (wid >> 2) << 5;
    const int r4 = lane >> 2, c2 = (lane & 3) << 1;
#pragma unroll
    for (int mf = 0; mf < 2; mf++)
#pragma unroll
        for (int half = 0; half < 2; half++) {
            const int row = m0 + wm + (mf << 4) + (half << 3) + r4;
#pragma unroll
            for (int nf = 0; nf < 4; nf++) {
                const int col = n0 + wn + (nf << 3) + c2;
                float2 o;
                o.x = c[mf][nf][half * 2 + 0] + bias[col];
                o.y = c[mf][nf][half * 2 + 1] + bias[col + 1];
                *(float2*)&C[(size_t)row * DMODEL + col] = o;
            }
        }
}

__global__ void zero_stats(float* p) {
    ((float4*)p)[blockIdx.x * blockDim.x + threadIdx.x] = make_float4(0.f, 0.f, 0.f, 0.f);
}

// ---------------------------------------------------------------------------
extern "C" void kernel_launch(void* const* d_in, const int* in_sizes, int n_in,
                              void* d_out, int out_size)
{
    const float* x      = (const float*)d_in[0];
    const float* qkv_w  = (const float*)d_in[1];
    const float* qkv_b  = (const float*)d_in[2];
    const float* proj_w = (const float*)d_in[3];
    const float* proj_b = (const float*)d_in[4];
    float* out = (float*)d_out;

    __half* scores;
    float *attn, *sumsq;
    cudaGetSymbolAddress((void**)&scores, g_scores);
    cudaGetSymbolAddress((void**)&attn, g_attn);
    cudaGetSymbolAddress((void**)&sumsq, g_sumsq);

    cudaFuncSetAttribute(qkv_tc, cudaFuncAttributeMaxDynamicSharedMemorySize, SMEM_2BUF);
    cudaFuncSetAttribute(scores_bf, cudaFuncAttributeMaxDynamicSharedMemorySize, SMEM_1BUF);
    cudaFuncSetAttribute(pv_tc, cudaFuncAttributeMaxDynamicSharedMemorySize, SMEM_2BUF);
    cudaFuncSetAttribute(proj_tc, cudaFuncAttributeMaxDynamicSharedMemorySize, SMEM_2BUF);

    // 0) zero per-row sumsq stats
    zero_stats<<<32, 256>>>(sumsq);

    // 1) QKV projection + pre-split/transpose epilogue
    qkv_tc<<<dim3(QKVDIM / 64, (BATCH * SEQ) / 128), 256, SMEM_2BUF>>>(x, qkv_w, qkv_b);

    // 2) scores = Q K^T (Q pre-scaled), bf16 operands via cp.async, fp16 out
    scores_bf<<<dim3(SEQ / 64, SEQ / 128, ZTOT), 256, SMEM_1BUF>>>(scores, sumsq);

    // 3) fused norm+softmax+PV
    pv_tc<<<dim3(1, SEQ / 128, ZTOT), 256, SMEM_2BUF>>>(scores, sumsq, attn);

    // 4) final projection
    proj_tc<<<dim3(DMODEL / 64, (BATCH * SEQ) / 128), 256, SMEM_2BUF>>>(attn, proj_w, out, proj_b);
}

// round 11
// speedup vs baseline: 3.0023x; 1.2830x over previous
#include <cuda_runtime.h>
#include <cuda_bf16.h>
#include <cuda_fp16.h>
#include <math.h>
#include <stdint.h>

// Problem constants: B=2, N=2048, D=512, H=8, hd=64
#define BATCH 2
#define SEQ   2048
#define DMODEL 512
#define HEADS 8
#define HDIM  64
#define QKVDIM 1536
#define ZTOT  (BATCH * HEADS)        // 16
#define ZSTRIDE ((size_t)SEQ * HDIM) // 131072

// Scratch (no cudaMalloc -> __device__ globals)
__device__ __half g_scores[(size_t)ZTOT * SEQ * SEQ];         // 128 MB (fp16)
__device__ float g_attn[(size_t)BATCH * SEQ * DMODEL];        // 8 MB
__device__ float g_sumsq[(size_t)ZTOT * SEQ];                 // 128 KB
// pre-split bf16 operands, produced by qkv epilogue
__device__ __nv_bfloat16 g_qh[(size_t)ZTOT * SEQ * HDIM];     // 4 MB each
__device__ __nv_bfloat16 g_ql[(size_t)ZTOT * SEQ * HDIM];
__device__ __nv_bfloat16 g_kh[(size_t)ZTOT * SEQ * HDIM];
__device__ __nv_bfloat16 g_kl[(size_t)ZTOT * SEQ * HDIM];
__device__ __nv_bfloat16 g_vh[(size_t)ZTOT * HDIM * SEQ];     // transposed [z][d][n]
__device__ __nv_bfloat16 g_vl[(size_t)ZTOT * HDIM * SEQ];

// ---------------------------------------------------------------------------
// Shared-memory layout: bf16, row stride 64 elements (128B), XOR swizzle on
// 16B units: unit' = (k>>3) ^ (row&7). Conflict-free ldmatrix, 2-way worst
// staging stores, 8B-contiguous per (row, k..k+3).
// ---------------------------------------------------------------------------
__device__ __forceinline__ uint32_t soff(int row, int k) {
    int u = ((k >> 3) ^ row) & 7;
    return (uint32_t)((row << 6) + (u << 3) + (k & 7));
}

__device__ __forceinline__ uint32_t smem_u32(const void* p) {
    uint32_t a;
    asm("{ .reg .u64 t; cvta.to.shared.u64 t, %1; cvt.u32.u64 %0, t; }" : "=r"(a) : "l"(p));
    return a;
}

__device__ __forceinline__ void ldsm_x4(uint32_t* r, uint32_t addr) {
    asm volatile("ldmatrix.sync.aligned.m8n8.x4.shared.b16 {%0,%1,%2,%3}, [%4];"
        : "=r"(r[0]), "=r"(r[1]), "=r"(r[2]), "=r"(r[3]) : "r"(addr));
}

__device__ __forceinline__ void mma_bf16(float* c, const uint32_t* a, const uint32_t* b) {
    asm volatile(
        "mma.sync.aligned.m16n8k16.row.col.f32.bf16.bf16.f32 "
        "{%0,%1,%2,%3}, {%4,%5,%6,%7}, {%8,%9}, {%0,%1,%2,%3};"
        : "+f"(c[0]), "+f"(c[1]), "+f"(c[2]), "+f"(c[3])
        : "r"(a[0]), "r"(a[1]), "r"(a[2]), "r"(a[3]), "r"(b[0]), "r"(b[1]));
}

__device__ __forceinline__ void cp16(uint32_t dst, const void* src) {
    asm volatile("cp.async.cg.shared.global [%0], [%1], 16;" :: "r"(dst), "l"(src));
}
#define CP_COMMIT() asm volatile("cp.async.commit_group;" ::: "memory")
#define CP_WAIT0()  asm volatile("cp.async.wait_group 0;" ::: "memory")

// split fp32x4 (4 consecutive k of one row, k%4==0) -> hi/lo bf16 slabs.
// k..k+3 are contiguous within a 16B unit -> single 8B store per slab.
__device__ __forceinline__ void st_split4(char* hiB, char* loB, int row, int k, float4 v) {
    __nv_bfloat162 h0 = __floats2bfloat162_rn(v.x, v.y);
    __nv_bfloat162 l0 = __floats2bfloat162_rn(v.x - __low2float(h0), v.y - __high2float(h0));
    __nv_bfloat162 h1 = __floats2bfloat162_rn(v.z, v.w);
    __nv_bfloat162 l1 = __floats2bfloat162_rn(v.z - __low2float(h1), v.w - __high2float(h1));
    uint32_t off = soff(row, k) * 2;
    uint2 hu, lu;
    hu.x = *(uint32_t*)&h0; hu.y = *(uint32_t*)&h1;
    lu.x = *(uint32_t*)&l0; lu.y = *(uint32_t*)&l1;
    *(uint2*)(hiB + off) = hu;
    *(uint2*)(loB + off) = lu;
}

// smem buffer offsets (bytes) within one slab buffer
#define A_HI 0
#define A_LO 16384
#define B_HI 32768
#define B_LO 40960
#define BUFSZ 49152
#define SMEM_1BUF 49152
#define SMEM_2BUF 98304

// ---------------------------------------------------------------------------
// One 64-wide K slab of MMAs. Warp grid 4(M) x 2(N); warp tile 32x32.
// 3-chain split bf16: hi*hi + hi*lo + lo*hi.
// ---------------------------------------------------------------------------
__device__ __forceinline__ void mma_slab(uint32_t sbase, float c[2][4][4], int wid, int lane) {
    const int wm = (wid & 3) << 5;
    const int wn = (wid >> 2) << 5;
    const int lrow = lane & 15, lhalf = lane >> 4;
    const int bq = lane >> 3, br = lane & 7;
    const int bnq = ((bq >> 1) << 3) + br;
    const int bk8 = (bq & 1) << 3;
#pragma unroll
    for (int kk = 0; kk < 64; kk += 16) {
        uint32_t ah[2][4], al[2][4], bh[2][4], bl[2][4];
#pragma unroll
        for (int mf = 0; mf < 2; mf++) {
            uint32_t o = soff(wm + (mf << 4) + lrow, kk + (lhalf << 3)) * 2;
            ldsm_x4(ah[mf], sbase + A_HI + o);
            ldsm_x4(al[mf], sbase + A_LO + o);
        }
#pragma unroll
        for (int np = 0; np < 2; np++) {
            uint32_t o = soff(wn + (np << 4) + bnq, kk + bk8) * 2;
            ldsm_x4(bh[np], sbase + B_HI + o);
            ldsm_x4(bl[np], sbase + B_LO + o);
        }
#pragma unroll
        for (int mf = 0; mf < 2; mf++)
#pragma unroll
            for (int nf = 0; nf < 4; nf++) {
                const uint32_t* bhp = &bh[nf >> 1][(nf & 1) << 1];
                const uint32_t* blp = &bl[nf >> 1][(nf & 1) << 1];
                mma_bf16(c[mf][nf], ah[mf], bhp);
                mma_bf16(c[mf][nf], ah[mf], blp);
                mma_bf16(c[mf][nf], al[mf], bhp);
            }
    }
}

// ============================================================================
// QKV projection: [4096,512] @ [1536,512]^T + bias. fp32 inputs, pipelined.
// Epilogue writes pre-split bf16: Q (x0.125) and K as [z][n][d]; V transposed
// to [z][d][n] via smem staging. No fp32 output.
// ============================================================================
__global__ __launch_bounds__(256) void qkv_tc(
    const float* __restrict__ A, const float* __restrict__ B,
    const float* __restrict__ bias)
{
    extern __shared__ char sm[];
    const int t = threadIdx.x, lane = t & 31, wid = t >> 5;
    const int m0 = blockIdx.y * 128;
    const int n0 = blockIdx.x * 64;
    const int lda = DMODEL, ldb = DMODEL;

    const uint32_t sbase = smem_u32(sm);
    const int ar = t >> 4, ac4 = (t & 15) << 2;

    float4 av[8], bv[4];
    auto load_slab = [&](int k0) {
#pragma unroll
        for (int i = 0; i < 8; i++)
            av[i] = *(const float4*)(A + (size_t)(m0 + (i << 4) + ar) * lda + k0 + ac4);
#pragma unroll
        for (int i = 0; i < 4; i++)
            bv[i] = *(const float4*)(B + (size_t)(n0 + (i << 4) + ar) * ldb + k0 + ac4);
    };
    auto store_slab = [&](int bs) {
        char* bp = sm + bs * BUFSZ;
#pragma unroll
        for (int i = 0; i < 8; i++) st_split4(bp + A_HI, bp + A_LO, (i << 4) + ar, ac4, av[i]);
#pragma unroll
        for (int i = 0; i < 4; i++) st_split4(bp + B_HI, bp + B_LO, (i << 4) + ar, ac4, bv[i]);
    };

    float c[2][4][4] = {};
    load_slab(0);
    store_slab(0);
    __syncthreads();
    const int S = DMODEL >> 6;
    for (int s = 0; s < S; s++) {
        if (s + 1 < S) load_slab((s + 1) << 6);
        mma_slab(sbase + (s & 1) * BUFSZ, c, wid, lane);
        if (s + 1 < S) { store_slab((s + 1) & 1); __syncthreads(); }
    }

    // ---- epilogue: classify by output-column block ----
    const int wm = (wid & 3) << 5, wn = (wid >> 2) << 5;
    const int r4 = lane >> 2, c2 = (lane & 3) << 1;
    const int typ = n0 >> 9;              // 0=q 1=k 2=v
    const int h = (n0 >> 6) & 7;
    const int b = m0 >> 11;
    const int z = b * HEADS + h;
    const int nloc = m0 & (SEQ - 1);
    const float scl = (typ == 0) ? 0.125f : 1.0f;

    if (typ < 2) {
        __nv_bfloat16* dh = ((typ == 0) ? g_qh : g_kh) + (size_t)z * ZSTRIDE;
        __nv_bfloat16* dl = ((typ == 0) ? g_ql : g_kl) + (size_t)z * ZSTRIDE;
#pragma unroll
        for (int mf = 0; mf < 2; mf++)
#pragma unroll
            for (int half = 0; half < 2; half++) {
                const int row = wm + (mf << 4) + (half << 3) + r4;
#pragma unroll
                for (int nf = 0; nf < 4; nf++) {
                    const int d = wn + (nf << 3) + c2;
                    float ox = (c[mf][nf][half * 2 + 0] + bias[n0 + d]) * scl;
                    float oy = (c[mf][nf][half * 2 + 1] + bias[n0 + d + 1]) * scl;
                    __nv_bfloat162 hh = __floats2bfloat162_rn(ox, oy);
                    __nv_bfloat162 ll = __floats2bfloat162_rn(ox - __low2float(hh),
                                                              oy - __high2float(hh));
                    size_t o = (size_t)(nloc + row) * HDIM + d;
                    *(__nv_bfloat162*)&dh[o] = hh;
                    *(__nv_bfloat162*)&dl[o] = ll;
                }
            }
    } else {
        // V: stage [d][n] transpose in smem (stride 136), then coalesced copy
        __syncthreads();
        __nv_bfloat16* th = (__nv_bfloat16*)sm;
        __nv_bfloat16* tl = th + 64 * 136;
#pragma unroll
        for (int mf = 0; mf < 2; mf++)
#pragma unroll
            for (int half = 0; half < 2; half++) {
                const int row = wm + (mf << 4) + (half << 3) + r4;
#pragma unroll
                for (int nf = 0; nf < 4; nf++) {
                    const int d = wn + (nf << 3) + c2;
                    float ox = c[mf][nf][half * 2 + 0] + bias[n0 + d];
                    float oy = c[mf][nf][half * 2 + 1] + bias[n0 + d + 1];
                    __nv_bfloat16 hx = __float2bfloat16(ox);
                    __nv_bfloat16 hy = __float2bfloat16(oy);
                    th[d * 136 + row]       = hx;
                    th[(d + 1) * 136 + row] = hy;
                    tl[d * 136 + row]       = __float2bfloat16(ox - __bfloat162float(hx));
                    tl[(d + 1) * 136 + row] = __float2bfloat16(oy - __bfloat162float(hy));
                }
            }
        __syncthreads();
        __nv_bfloat16* vh = g_vh + (size_t)z * ZSTRIDE;
        __nv_bfloat16* vl = g_vl + (size_t)z * ZSTRIDE;
#pragma unroll
        for (int i = 0; i < 8; i++) {
            int idx = i * 256 + t;         // 0..2047
            int d = idx >> 5, nm = (idx & 31) << 2;
            *(uint2*)&vh[(size_t)d * SEQ + nloc + nm] = *(uint2*)&th[d * 136 + nm];
            *(uint2*)&vl[(size_t)d * SEQ + nloc + nm] = *(uint2*)&tl[d * 136 + nm];
        }
    }
}

// ============================================================================
// scores = Q K^T per z (Q pre-scaled). Pure bf16 GEMM, cp.async operands,
// single K=64 slab. Epilogue: write fp16 scores + per-row sumsq atomics.
// ============================================================================
__global__ __launch_bounds__(256, 2) void scores_bf(__half* __restrict__ scores,
                                                    float* __restrict__ sumsq)
{
    extern __shared__ char sm[];
    const int t = threadIdx.x, lane = t & 31, wid = t >> 5;
    const int z = blockIdx.z;
    const int m0 = blockIdx.y * 128;
    const int n0 = blockIdx.x * 64;
    const __nv_bfloat16* qh = g_qh + (size_t)z * ZSTRIDE;
    const __nv_bfloat16* ql = g_ql + (size_t)z * ZSTRIDE;
    const __nv_bfloat16* kh = g_kh + (size_t)z * ZSTRIDE;
    const __nv_bfloat16* kl = g_kl + (size_t)z * ZSTRIDE;
    const uint32_t sbase = smem_u32(sm);

#pragma unroll
    for (int i = 0; i < 4; i++) {
        int idx = i * 256 + t;             // 0..1023
        int row = idx >> 3, q8 = (idx & 7) << 3;
        uint32_t dsw = soff(row, q8) * 2;
        cp16(sbase + A_HI + dsw, qh + (size_t)(m0 + row) * HDIM + q8);
        cp16(sbase + A_LO + dsw, ql + (size_t)(m0 + row) * HDIM + q8);
    }
#pragma unroll
    for (int i = 0; i < 2; i++) {
        int idx = i * 256 + t;             // 0..511
        int row = idx >> 3, q8 = (idx & 7) << 3;
        uint32_t dsw = soff(row, q8) * 2;
        cp16(sbase + B_HI + dsw, kh + (size_t)(n0 + row) * HDIM + q8);
        cp16(sbase + B_LO + dsw, kl + (size_t)(n0 + row) * HDIM + q8);
    }
    CP_COMMIT();
    CP_WAIT0();
    __syncthreads();

    float c[2][4][4] = {};
    mma_slab(sbase, c, wid, lane);

    __half* C = scores + (size_t)z * SEQ * SEQ;
    const int wm = (wid & 3) << 5, wn = (wid >> 2) << 5;
    const int r4 = lane >> 2, c2 = (lane & 3) << 1;
    float ss[4] = {0.f, 0.f, 0.f, 0.f};
#pragma unroll
    for (int mf = 0; mf < 2; mf++)
#pragma unroll
        for (int half = 0; half < 2; half++) {
            const int row = m0 + wm + (mf << 4) + (half << 3) + r4;
#pragma unroll
            for (int nf = 0; nf < 4; nf++) {
                const int col = n0 + wn + (nf << 3) + c2;
                float ox = c[mf][nf][half * 2 + 0];
                float oy = c[mf][nf][half * 2 + 1];
                ss[mf * 2 + half] += ox * ox + oy * oy;
                *(__half2*)&C[(size_t)row * SEQ + col] = __floats2half2_rn(ox, oy);
            }
        }
#pragma unroll
    for (int q = 0; q < 4; q++) {
        float v = ss[q];
        v += __shfl_xor_sync(0xffffffffu, v, 1);
        v += __shfl_xor_sync(0xffffffffu, v, 2);
        if ((lane & 3) == 0) {
            const int row = m0 + wm + ((q >> 1) << 4) + ((q & 1) << 3) + r4;
            atomicAdd(&sumsq[(size_t)z * SEQ + row], v);
        }
    }
}

// ============================================================================
// Fused norm+softmax+PV: p = exp(s*inv) (|s*inv|<=1), in-CTA sum(p),
// P@V via HMMA with V pre-split+transposed arriving by cp.async.
// S arrives as fp16. Compact smem -> 2 CTAs/SM.
// ============================================================================
__global__ __launch_bounds__(256, 2) void pv_tc(
    const __half* __restrict__ Sm, const float* __restrict__ sumsq,
    float* __restrict__ attn)
{
    extern __shared__ char sm[];
    __shared__ float s_inv[128];
    __shared__ float s_se[128];
    const int t = threadIdx.x, lane = t & 31, wid = t >> 5;
    const int z = blockIdx.z, b = z >> 3, h = z & 7;
    const int m0 = blockIdx.y * 128;
    const __half* Sg = Sm + (size_t)z * SEQ * SEQ;
    const __nv_bfloat16* vh = g_vh + (size_t)z * ZSTRIDE;
    const __nv_bfloat16* vl = g_vl + (size_t)z * ZSTRIDE;
    float* Cg = attn + (size_t)b * SEQ * DMODEL + h * HDIM;
    const uint32_t sbase = smem_u32(sm);

    if (t < 128) s_inv[t] = 1.0f / (sqrtf(sumsq[(size_t)z * SEQ + m0 + t]) + 1e-6f);
    __syncthreads();

    float se[8] = {0.f, 0.f, 0.f, 0.f, 0.f, 0.f, 0.f, 0.f};
    const int ar = t >> 4, ac4 = (t & 15) << 2;

    uint2 av[8];   // 4 fp16 each
    auto load_A = [&](int k0) {
#pragma unroll
        for (int i = 0; i < 8; i++)
            av[i] = *(const uint2*)(Sg + (size_t)(m0 + (i << 4) + ar) * SEQ + k0 + ac4);
    };
    auto store_A = [&](int bs) {
        char* bp = sm + bs * BUFSZ;
#pragma unroll
        for (int i = 0; i < 8; i++) {
            const int row = (i << 4) + ar;
            const float inv = s_inv[row];
            float2 f01 = __half22float2(*(__half2*)&av[i].x);
            float2 f23 = __half22float2(*(__half2*)&av[i].y);
            float4 p;
            p.x = __expf(f01.x * inv);
            p.y = __expf(f01.y * inv);
            p.z = __expf(f23.x * inv);
            p.w = __expf(f23.y * inv);
            se[i] += p.x + p.y + p.z + p.w;
            st_split4(bp + A_HI, bp + A_LO, row, ac4, p);
        }
    };
    auto cp_B = [&](int bs, int k0) {
        uint32_t db = sbase + bs * BUFSZ;
#pragma unroll
        for (int i = 0; i < 2; i++) {
            int idx = i * 256 + t;         // 0..511
            int d = idx >> 3, q8 = (idx & 7) << 3;
            uint32_t dsw = soff(d, q8) * 2;
            cp16(db + B_HI + dsw, vh + (size_t)d * SEQ + k0 + q8);
            cp16(db + B_LO + dsw, vl + (size_t)d * SEQ + k0 + q8);
        }
    };

    float c[2][4][4] = {};
    cp_B(0, 0); CP_COMMIT();
    load_A(0);
    store_A(0);
    CP_WAIT0();
    __syncthreads();

    const int S = SEQ / 64;
    for (int s = 0; s < S; s++) {
        if (s + 1 < S) {
            cp_B((s + 1) & 1, (s + 1) << 6); CP_COMMIT();
            load_A((s + 1) << 6);
        }
        mma_slab(sbase + (s & 1) * BUFSZ, c, wid, lane);
        if (s + 1 < S) {
            store_A((s + 1) & 1);
            CP_WAIT0();
            __syncthreads();
        }
    }

    // per-row sumexp: reduce across the 16 threads sharing each row
#pragma unroll
    for (int i = 0; i < 8; i++) {
        float v = se[i];
        v += __shfl_xor_sync(0xffffffffu, v, 1);
        v += __shfl_xor_sync(0xffffffffu, v, 2);
        v += __shfl_xor_sync(0xffffffffu, v, 4);
        v += __shfl_xor_sync(0xffffffffu, v, 8);
        if ((t & 15) == 0) s_se[(i << 4) + ar] = v;
    }
    __syncthreads();

    const int wm = (wid & 3) << 5, wn = (wid >> 2) << 5;
    const int r4 = lane >> 2, c2 = (lane & 3) << 1;
#pragma unroll
    for (int mf = 0; mf < 2; mf++)
#pragma unroll
        for (int half = 0; half < 2; half++) {
            const int rl = wm + (mf << 4) + (half << 3) + r4;
            const float rse = 1.0f / s_se[rl];
#pragma unroll
            for (int nf = 0; nf < 4; nf++) {
                const int col = wn + (nf << 3) + c2;
                float2 o;
                o.x = c[mf][nf][half * 2 + 0] * rse;
                o.y = c[mf][nf][half * 2 + 1] * rse;
                *(float2*)&Cg[(size_t)(m0 + rl) * DMODEL + col] = o;
            }
        }
}

// ============================================================================
// Final projection (fp32 inputs): C = A @ W^T + bias  (K=512, pipelined)
// ============================================================================
__global__ __launch_bounds__(256) void proj_tc(
    const float* __restrict__ A, const float* __restrict__ B,
    float* __restrict__ C, const float* __restrict__ bias)
{
    extern __shared__ char sm[];
    const int t = threadIdx.x, lane = t & 31, wid = t >> 5;
    const int m0 = blockIdx.y * 128;
    const int n0 = blockIdx.x * 64;
    const uint32_t sbase = smem_u32(sm);
    const int ar = t >> 4, ac4 = (t & 15) << 2;

    float4 av[8], bv[4];
    auto load_slab = [&](int k0) {
#pragma unroll
        for (int i = 0; i < 8; i++)
            av[i] = *(const float4*)(A + (size_t)(m0 + (i << 4) + ar) * DMODEL + k0 + ac4);
#pragma unroll
        for (int i = 0; i < 4; i++)
            bv[i] = *(const float4*)(B + (size_t)(n0 + (i << 4) + ar) * DMODEL + k0 + ac4);
    };
    auto store_slab = [&](int bs) {
        char* bp = sm + bs * BUFSZ;
#pragma unroll
        for (int i = 0; i < 8; i++) st_split4(bp + A_HI, bp + A_LO, (i << 4) + ar, ac4, av[i]);
#pragma unroll
        for (int i = 0; i < 4; i++) st_split4(bp + B_HI, bp + B_LO, (i << 4) + ar, ac4, bv[i]);
    };

    float c[2][4][4] = {};
    load_slab(0);
    store_slab(0);
    __syncthreads();
    const int S = DMODEL >> 6;
    for (int s = 0; s < S; s++) {
        if (s + 1 < S) load_slab((s + 1) << 6);
        mma_slab(sbase + (s & 1) * BUFSZ, c, wid, lane);
        if (s + 1 < S) { store_slab((s + 1) & 1); __syncthreads(); }
    }

    const int wm = (wid & 3) << 5, wn = (wid >> 2) << 5;
    const int r4 = lane >> 2, c2 = (lane & 3) << 1;
#pragma unroll
    for (int mf = 0; mf < 2; mf++)
#pragma unroll
        for (int half = 0; half < 2; half++) {
            const int row = m0 + wm + (mf << 4) + (half << 3) + r4;
#pragma unroll
            for (int nf = 0; nf < 4; nf++) {
                const int col = n0 + wn + (nf << 3) + c2;
                float2 o;
                o.x = c[mf][nf][half * 2 + 0] + bias[col];
                o.y = c[mf][nf][half * 2 + 1] + bias[col + 1];
                *(float2*)&C[(size_t)row * DMODEL + col] = o;
            }
        }
}

__global__ void zero_stats(float* p) {
    ((float4*)p)[blockIdx.x * blockDim.x + threadIdx.x] = make_float4(0.f, 0.f, 0.f, 0.f);
}

// ---------------------------------------------------------------------------
extern "C" void kernel_launch(void* const* d_in, const int* in_sizes, int n_in,
                              void* d_out, int out_size)
{
    const float* x      = (const float*)d_in[0];
    const float* qkv_w  = (const float*)d_in[1];
    const float* qkv_b  = (const float*)d_in[2];
    const float* proj_w = (const float*)d_in[3];
    const float* proj_b = (const float*)d_in[4];
    float* out = (float*)d_out;

    __half* scores;
    float *attn, *sumsq;
    cudaGetSymbolAddress((void**)&scores, g_scores);
    cudaGetSymbolAddress((void**)&attn, g_attn);
    cudaGetSymbolAddress((void**)&sumsq, g_sumsq);

    cudaFuncSetAttribute(qkv_tc, cudaFuncAttributeMaxDynamicSharedMemorySize, SMEM_2BUF);
    cudaFuncSetAttribute(scores_bf, cudaFuncAttributeMaxDynamicSharedMemorySize, SMEM_1BUF);
    cudaFuncSetAttribute(pv_tc, cudaFuncAttributeMaxDynamicSharedMemorySize, SMEM_2BUF);
    cudaFuncSetAttribute(proj_tc, cudaFuncAttributeMaxDynamicSharedMemorySize, SMEM_2BUF);

    // 0) zero per-row sumsq stats
    zero_stats<<<32, 256>>>(sumsq);

    // 1) QKV projection + pre-split/transpose epilogue
    qkv_tc<<<dim3(QKVDIM / 64, (BATCH * SEQ) / 128), 256, SMEM_2BUF>>>(x, qkv_w, qkv_b);

    // 2) scores = Q K^T (Q pre-scaled), bf16 operands via cp.async, fp16 out
    scores_bf<<<dim3(SEQ / 64, SEQ / 128, ZTOT), 256, SMEM_1BUF>>>(scores, sumsq);

    // 3) fused norm+softmax+PV
    pv_tc<<<dim3(1, SEQ / 128, ZTOT), 256, SMEM_2BUF>>>(scores, sumsq, attn);

    // 4) final projection
    proj_tc<<<dim3(DMODEL / 64, (BATCH * SEQ) / 128), 256, SMEM_2BUF>>>(attn, proj_w, out, proj_b);
}

// round 12
// speedup vs baseline: 4.0088x; 1.3352x over previous
#include <cuda_runtime.h>
#include <cuda_bf16.h>
#include <cuda_fp16.h>
#include <math.h>
#include <stdint.h>

// Problem constants: B=2, N=2048, D=512, H=8, hd=64
#define BATCH 2
#define SEQ   2048
#define DMODEL 512
#define HEADS 8
#define HDIM  64
#define QKVDIM 1536
#define ZTOT  (BATCH * HEADS)        // 16
#define ZSTRIDE ((size_t)SEQ * HDIM) // 131072

// ---------------- scratch (no cudaMalloc -> __device__ globals) ----------------
__device__ __half g_scores[(size_t)ZTOT * SEQ * SEQ];         // 128 MB fp16
__device__ float  g_sumsq[(size_t)ZTOT * SEQ];
// pre-split bf16 hi/lo of fp32 inputs (produced once per run)
__device__ __nv_bfloat16 g_xh[(size_t)BATCH * SEQ * DMODEL], g_xl[(size_t)BATCH * SEQ * DMODEL];
__device__ __nv_bfloat16 g_wh[(size_t)QKVDIM * DMODEL],      g_wl[(size_t)QKVDIM * DMODEL];
__device__ __nv_bfloat16 g_pwh[(size_t)DMODEL * DMODEL],     g_pwl[(size_t)DMODEL * DMODEL];
// fp16 attention operands (produced by qkv epilogue)
__device__ __half g_q16[(size_t)ZTOT * SEQ * HDIM];           // Q, pre-scaled x0.125
__device__ __half g_k16[(size_t)ZTOT * SEQ * HDIM];
__device__ __half g_vh16[(size_t)ZTOT * HDIM * SEQ];          // V transposed [z][d][n], hi
__device__ __half g_vl16[(size_t)ZTOT * HDIM * SEQ];          // lo residual
// attn output, pre-split bf16 for proj's cp.async mainloop
__device__ __nv_bfloat16 g_ah[(size_t)BATCH * SEQ * DMODEL], g_al[(size_t)BATCH * SEQ * DMODEL];

// ---------------- smem layout: stride-64 rows, XOR swizzle on 16B units ----------------
__device__ __forceinline__ uint32_t soff(int row, int k) {
    int u = ((k >> 3) ^ row) & 7;
    return (uint32_t)((row << 6) + (u << 3) + (k & 7));
}
__device__ __forceinline__ uint32_t smem_u32(const void* p) {
    uint32_t a;
    asm("{ .reg .u64 t; cvta.to.shared.u64 t, %1; cvt.u32.u64 %0, t; }" : "=r"(a) : "l"(p));
    return a;
}
__device__ __forceinline__ void ldsm_x4(uint32_t* r, uint32_t addr) {
    asm volatile("ldmatrix.sync.aligned.m8n8.x4.shared.b16 {%0,%1,%2,%3}, [%4];"
        : "=r"(r[0]), "=r"(r[1]), "=r"(r[2]), "=r"(r[3]) : "r"(addr));
}
__device__ __forceinline__ void mma_bf16(float* c, const uint32_t* a, const uint32_t* b) {
    asm volatile("mma.sync.aligned.m16n8k16.row.col.f32.bf16.bf16.f32 "
        "{%0,%1,%2,%3}, {%4,%5,%6,%7}, {%8,%9}, {%0,%1,%2,%3};"
        : "+f"(c[0]), "+f"(c[1]), "+f"(c[2]), "+f"(c[3])
        : "r"(a[0]), "r"(a[1]), "r"(a[2]), "r"(a[3]), "r"(b[0]), "r"(b[1]));
}
__device__ __forceinline__ void mma_f16(float* c, const uint32_t* a, const uint32_t* b) {
    asm volatile("mma.sync.aligned.m16n8k16.row.col.f32.f16.f16.f32 "
        "{%0,%1,%2,%3}, {%4,%5,%6,%7}, {%8,%9}, {%0,%1,%2,%3};"
        : "+f"(c[0]), "+f"(c[1]), "+f"(c[2]), "+f"(c[3])
        : "r"(a[0]), "r"(a[1]), "r"(a[2]), "r"(a[3]), "r"(b[0]), "r"(b[1]));
}
__device__ __forceinline__ void cp16(uint32_t dst, const void* src) {
    asm volatile("cp.async.cg.shared.global [%0], [%1], 16;" :: "r"(dst), "l"(src));
}
#define CP_COMMIT() asm volatile("cp.async.commit_group;" ::: "memory")
#define CP_WAIT0()  asm volatile("cp.async.wait_group 0;" ::: "memory")
#define CP_WAIT1()  asm volatile("cp.async.wait_group 1;" ::: "memory")

// buffer offsets
// bf16 3-chain GEMM (qkv, proj)
#define A_HI 0
#define A_LO 16384
#define B_HI 32768
#define B_LO 40960
#define BUF3 49152
// scores (fp16 1-chain): Q@0 (16KB), K@16KB (8KB)
#define S_K  16384
#define SMEM_SC 24576
// pv (fp16 2-chain): P@0 (16KB), VH@16KB, VL@24KB
#define PV_VH 16384
#define PV_VL 24576
#define BUFPV 32768

// ---------------- MMA slab variants (warp grid 4(M) x 2(N), warp tile 32x32) ----------------
__device__ __forceinline__ void mma_slab3(uint32_t sbase, float c[2][4][4], int wid, int lane) {
    const int wm = (wid & 3) << 5, wn = (wid >> 2) << 5;
    const int lrow = lane & 15, lhalf = lane >> 4;
    const int bq = lane >> 3, br = lane & 7;
    const int bnq = ((bq >> 1) << 3) + br, bk8 = (bq & 1) << 3;
#pragma unroll
    for (int kk = 0; kk < 64; kk += 16) {
        uint32_t ah[2][4], al[2][4], bh[2][4], bl[2][4];
#pragma unroll
        for (int mf = 0; mf < 2; mf++) {
            uint32_t o = soff(wm + (mf << 4) + lrow, kk + (lhalf << 3)) * 2;
            ldsm_x4(ah[mf], sbase + A_HI + o);
            ldsm_x4(al[mf], sbase + A_LO + o);
        }
#pragma unroll
        for (int np = 0; np < 2; np++) {
            uint32_t o = soff(wn + (np << 4) + bnq, kk + bk8) * 2;
            ldsm_x4(bh[np], sbase + B_HI + o);
            ldsm_x4(bl[np], sbase + B_LO + o);
        }
#pragma unroll
        for (int mf = 0; mf < 2; mf++)
#pragma unroll
            for (int nf = 0; nf < 4; nf++) {
                const uint32_t* bhp = &bh[nf >> 1][(nf & 1) << 1];
                const uint32_t* blp = &bl[nf >> 1][(nf & 1) << 1];
                mma_bf16(c[mf][nf], ah[mf], bhp);
                mma_bf16(c[mf][nf], ah[mf], blp);
                mma_bf16(c[mf][nf], al[mf], bhp);
            }
    }
}
// scores: single-plane fp16 A and B, 1 chain
__device__ __forceinline__ void mma_slab1(uint32_t sbase, float c[2][4][4], int wid, int lane) {
    const int wm = (wid & 3) << 5, wn = (wid >> 2) << 5;
    const int lrow = lane & 15, lhalf = lane >> 4;
    const int bq = lane >> 3, br = lane & 7;
    const int bnq = ((bq >> 1) << 3) + br, bk8 = (bq & 1) << 3;
#pragma unroll
    for (int kk = 0; kk < 64; kk += 16) {
        uint32_t a[2][4], b2[2][4];
#pragma unroll
        for (int mf = 0; mf < 2; mf++)
            ldsm_x4(a[mf], sbase + soff(wm + (mf << 4) + lrow, kk + (lhalf << 3)) * 2);
#pragma unroll
        for (int np = 0; np < 2; np++)
            ldsm_x4(b2[np], sbase + S_K + soff(wn + (np << 4) + bnq, kk + bk8) * 2);
#pragma unroll
        for (int mf = 0; mf < 2; mf++)
#pragma unroll
            for (int nf = 0; nf < 4; nf++)
                mma_f16(c[mf][nf], a[mf], &b2[nf >> 1][(nf & 1) << 1]);
    }
}
// pv: fp16 P single plane x (VH + VL), 2 chains
__device__ __forceinline__ void mma_slab_pv(uint32_t sbase, float c[2][4][4], int wid, int lane) {
    const int wm = (wid & 3) << 5, wn = (wid >> 2) << 5;
    const int lrow = lane & 15, lhalf = lane >> 4;
    const int bq = lane >> 3, br = lane & 7;
    const int bnq = ((bq >> 1) << 3) + br, bk8 = (bq & 1) << 3;
#pragma unroll
    for (int kk = 0; kk < 64; kk += 16) {
        uint32_t a[2][4], bh[2][4], bl[2][4];
#pragma unroll
        for (int mf = 0; mf < 2; mf++)
            ldsm_x4(a[mf], sbase + soff(wm + (mf << 4) + lrow, kk + (lhalf << 3)) * 2);
#pragma unroll
        for (int np = 0; np < 2; np++) {
            uint32_t o = soff(wn + (np << 4) + bnq, kk + bk8) * 2;
            ldsm_x4(bh[np], sbase + PV_VH + o);
            ldsm_x4(bl[np], sbase + PV_VL + o);
        }
#pragma unroll
        for (int mf = 0; mf < 2; mf++)
#pragma unroll
            for (int nf = 0; nf < 4; nf++) {
                mma_f16(c[mf][nf], a[mf], &bh[nf >> 1][(nf & 1) << 1]);
                mma_f16(c[mf][nf], a[mf], &bl[nf >> 1][(nf & 1) << 1]);
            }
    }
}

// ============================================================================
// presplit: fp32 -> bf16 hi/lo (exact to ~2^-17 rel). One float4 per thread.
// ============================================================================
__global__ void presplit(const float4* __restrict__ src,
                         __nv_bfloat16* __restrict__ hi, __nv_bfloat16* __restrict__ lo)
{
    int i = blockIdx.x * 256 + threadIdx.x;
    float4 v = src[i];
    __nv_bfloat162 h0 = __floats2bfloat162_rn(v.x, v.y);
    __nv_bfloat162 h1 = __floats2bfloat162_rn(v.z, v.w);
    __nv_bfloat162 l0 = __floats2bfloat162_rn(v.x - __low2float(h0), v.y - __high2float(h0));
    __nv_bfloat162 l1 = __floats2bfloat162_rn(v.z - __low2float(h1), v.w - __high2float(h1));
    uint2 hu, lu;
    hu.x = *(uint32_t*)&h0; hu.y = *(uint32_t*)&h1;
    lu.x = *(uint32_t*)&l0; lu.y = *(uint32_t*)&l1;
    *(uint2*)(hi + 4 * (size_t)i) = hu;
    *(uint2*)(lo + 4 * (size_t)i) = lu;
}

__global__ void zero_stats() {
    ((float4*)g_sumsq)[blockIdx.x * 256 + threadIdx.x] = make_float4(0.f, 0.f, 0.f, 0.f);
}

// ============================================================================
// QKV projection: pre-split bf16 operands via cp.async, 3-chain MMA.
// Epilogue: Q (x0.125) & K as single fp16 [z][n][d]; V split fp16, transposed
// to [z][d][n] via smem staging.
// ============================================================================
__global__ __launch_bounds__(256, 2) void qkv_tc(const float* __restrict__ bias)
{
    extern __shared__ char sm[];
    const int t = threadIdx.x, lane = t & 31, wid = t >> 5;
    const int m0 = blockIdx.y * 128, n0 = blockIdx.x * 64;
    const uint32_t sbase = smem_u32(sm);

    auto cp_slab = [&](int bs, int k0) {
        uint32_t db = sbase + bs * BUF3;
#pragma unroll
        for (int i = 0; i < 4; i++) {
            int idx = i * 256 + t, row = idx >> 3, q8 = (idx & 7) << 3;
            uint32_t dsw = soff(row, q8) * 2;
            cp16(db + A_HI + dsw, g_xh + (size_t)(m0 + row) * DMODEL + k0 + q8);
            cp16(db + A_LO + dsw, g_xl + (size_t)(m0 + row) * DMODEL + k0 + q8);
        }
#pragma unroll
        for (int i = 0; i < 2; i++) {
            int idx = i * 256 + t, row = idx >> 3, q8 = (idx & 7) << 3;
            uint32_t dsw = soff(row, q8) * 2;
            cp16(db + B_HI + dsw, g_wh + (size_t)(n0 + row) * DMODEL + k0 + q8);
            cp16(db + B_LO + dsw, g_wl + (size_t)(n0 + row) * DMODEL + k0 + q8);
        }
    };

    float c[2][4][4] = {};
    cp_slab(0, 0); CP_COMMIT();
    const int S = DMODEL >> 6;
    for (int s = 0; s < S; s++) {
        if (s + 1 < S) { cp_slab((s + 1) & 1, (s + 1) << 6); CP_COMMIT(); CP_WAIT1(); }
        else CP_WAIT0();
        __syncthreads();
        mma_slab3(sbase + (s & 1) * BUF3, c, wid, lane);
        __syncthreads();
    }

    const int wm = (wid & 3) << 5, wn = (wid >> 2) << 5;
    const int r4 = lane >> 2, c2 = (lane & 3) << 1;
    const int typ = n0 >> 9, h = (n0 >> 6) & 7, b = m0 >> 11;
    const int z = b * HEADS + h;
    const int nloc = m0 & (SEQ - 1);

    if (typ < 2) {
        const float scl = (typ == 0) ? 0.125f : 1.0f;
        __half* dst = ((typ == 0) ? g_q16 : g_k16) + (size_t)z * ZSTRIDE;
#pragma unroll
        for (int mf = 0; mf < 2; mf++)
#pragma unroll
            for (int half = 0; half < 2; half++) {
                const int row = wm + (mf << 4) + (half << 3) + r4;
#pragma unroll
                for (int nf = 0; nf < 4; nf++) {
                    const int d = wn + (nf << 3) + c2;
                    float ox = (c[mf][nf][half * 2 + 0] + bias[n0 + d]) * scl;
                    float oy = (c[mf][nf][half * 2 + 1] + bias[n0 + d + 1]) * scl;
                    *(__half2*)&dst[(size_t)(nloc + row) * HDIM + d] = __floats2half2_rn(ox, oy);
                }
            }
    } else {
        // V: split fp16, stage [d][n] transpose in smem (stride 136), coalesced copy
        __half* th = (__half*)sm;
        __half* tl = th + 64 * 136;
#pragma unroll
        for (int mf = 0; mf < 2; mf++)
#pragma unroll
            for (int half = 0; half < 2; half++) {
                const int row = wm + (mf << 4) + (half << 3) + r4;
#pragma unroll
                for (int nf = 0; nf < 4; nf++) {
                    const int d = wn + (nf << 3) + c2;
                    float ox = c[mf][nf][half * 2 + 0] + bias[n0 + d];
                    float oy = c[mf][nf][half * 2 + 1] + bias[n0 + d + 1];
                    __half hx = __float2half_rn(ox), hy = __float2half_rn(oy);
                    th[d * 136 + row] = hx;
                    th[(d + 1) * 136 + row] = hy;
                    tl[d * 136 + row] = __float2half_rn(ox - __half2float(hx));
                    tl[(d + 1) * 136 + row] = __float2half_rn(oy - __half2float(hy));
                }
            }
        __syncthreads();
        __half* vh = g_vh16 + (size_t)z * ZSTRIDE;
        __half* vl = g_vl16 + (size_t)z * ZSTRIDE;
#pragma unroll
        for (int i = 0; i < 8; i++) {
            int idx = i * 256 + t, d = idx >> 5, nm = (idx & 31) << 2;
            *(uint2*)&vh[(size_t)d * SEQ + nloc + nm] = *(uint2*)&th[d * 136 + nm];
            *(uint2*)&vl[(size_t)d * SEQ + nloc + nm] = *(uint2*)&tl[d * 136 + nm];
        }
    }
}

// ============================================================================
// scores = (0.125 Q) K^T per z. Single-fp16 operands, ONE MMA chain.
// Epilogue: fp16 score write + per-row sumsq atomics.
// ============================================================================
__global__ __launch_bounds__(256, 3) void scores_bf()
{
    extern __shared__ char sm[];
    const int t = threadIdx.x, lane = t & 31, wid = t >> 5;
    const int z = blockIdx.z;
    const int m0 = blockIdx.y * 128, n0 = blockIdx.x * 64;
    const __half* q = g_q16 + (size_t)z * ZSTRIDE;
    const __half* k = g_k16 + (size_t)z * ZSTRIDE;
    const uint32_t sbase = smem_u32(sm);

#pragma unroll
    for (int i = 0; i < 4; i++) {
        int idx = i * 256 + t, row = idx >> 3, q8 = (idx & 7) << 3;
        cp16(sbase + soff(row, q8) * 2, q + (size_t)(m0 + row) * HDIM + q8);
    }
#pragma unroll
    for (int i = 0; i < 2; i++) {
        int idx = i * 256 + t, row = idx >> 3, q8 = (idx & 7) << 3;
        cp16(sbase + S_K + soff(row, q8) * 2, k + (size_t)(n0 + row) * HDIM + q8);
    }
    CP_COMMIT();
    CP_WAIT0();
    __syncthreads();

    float c[2][4][4] = {};
    mma_slab1(sbase, c, wid, lane);

    __half* C = g_scores + (size_t)z * SEQ * SEQ;
    const int wm = (wid & 3) << 5, wn = (wid >> 2) << 5;
    const int r4 = lane >> 2, c2 = (lane & 3) << 1;
    float ss[4] = {0.f, 0.f, 0.f, 0.f};
#pragma unroll
    for (int mf = 0; mf < 2; mf++)
#pragma unroll
        for (int half = 0; half < 2; half++) {
            const int row = m0 + wm + (mf << 4) + (half << 3) + r4;
#pragma unroll
            for (int nf = 0; nf < 4; nf++) {
                const int col = n0 + wn + (nf << 3) + c2;
                float ox = c[mf][nf][half * 2 + 0];
                float oy = c[mf][nf][half * 2 + 1];
                ss[mf * 2 + half] += ox * ox + oy * oy;
                *(__half2*)&C[(size_t)row * SEQ + col] = __floats2half2_rn(ox, oy);
            }
        }
#pragma unroll
    for (int qd = 0; qd < 4; qd++) {
        float v = ss[qd];
        v += __shfl_xor_sync(0xffffffffu, v, 1);
        v += __shfl_xor_sync(0xffffffffu, v, 2);
        if ((lane & 3) == 0) {
            const int row = m0 + wm + ((qd >> 1) << 4) + ((qd & 1) << 3) + r4;
            atomicAdd(&g_sumsq[(size_t)z * SEQ + row], v);
        }
    }
}

// ============================================================================
// Fused norm+softmax+PV: p = exp(s*inv) (|s*inv|<=1), in-CTA sum(p),
// P fp16 (single) x V fp16 (hi/lo via cp.async) = 2 chains.
// Epilogue divides by sumexp, writes attn as split bf16 for proj.
// ============================================================================
__global__ __launch_bounds__(256, 2) void pv_tc()
{
    extern __shared__ char sm[];
    __shared__ float s_inv[128];
    __shared__ float s_se[128];
    const int t = threadIdx.x, lane = t & 31, wid = t >> 5;
    const int z = blockIdx.z, b = z >> 3, h = z & 7;
    const int m0 = blockIdx.y * 128;
    const __half* Sg = g_scores + (size_t)z * SEQ * SEQ;
    const __half* vh = g_vh16 + (size_t)z * ZSTRIDE;
    const __half* vl = g_vl16 + (size_t)z * ZSTRIDE;
    const uint32_t sbase = smem_u32(sm);

    if (t < 128) s_inv[t] = 1.0f / (sqrtf(g_sumsq[(size_t)z * SEQ + m0 + t]) + 1e-6f);
    __syncthreads();

    float se[8] = {0.f, 0.f, 0.f, 0.f, 0.f, 0.f, 0.f, 0.f};
    const int ar = t >> 4, ac4 = (t & 15) << 2;

    uint2 av[8];   // 4 fp16 each
    auto load_A = [&](int k0) {
#pragma unroll
        for (int i = 0; i < 8; i++)
            av[i] = *(const uint2*)(Sg + (size_t)(m0 + (i << 4) + ar) * SEQ + k0 + ac4);
    };
    auto store_A = [&](int bs) {
        char* bp = sm + bs * BUFPV;
#pragma unroll
        for (int i = 0; i < 8; i++) {
            const int row = (i << 4) + ar;
            const float inv = s_inv[row];
            float2 f01 = __half22float2(*(__half2*)&av[i].x);
            float2 f23 = __half22float2(*(__half2*)&av[i].y);
            float px = __expf(f01.x * inv), py = __expf(f01.y * inv);
            float pz = __expf(f23.x * inv), pw = __expf(f23.y * inv);
            se[i] += px + py + pz + pw;
            __half2 p01 = __floats2half2_rn(px, py);
            __half2 p23 = __floats2half2_rn(pz, pw);
            uint2 u;
            u.x = *(uint32_t*)&p01; u.y = *(uint32_t*)&p23;
            *(uint2*)(bp + soff(row, ac4) * 2) = u;
        }
    };
    auto cp_B = [&](int bs, int k0) {
        uint32_t db = sbase + bs * BUFPV;
#pragma unroll
        for (int i = 0; i < 2; i++) {
            int idx = i * 256 + t, d = idx >> 3, q8 = (idx & 7) << 3;
            uint32_t dsw = soff(d, q8) * 2;
            cp16(db + PV_VH + dsw, vh + (size_t)d * SEQ + k0 + q8);
            cp16(db + PV_VL + dsw, vl + (size_t)d * SEQ + k0 + q8);
        }
    };

    float c[2][4][4] = {};
    cp_B(0, 0); CP_COMMIT();
    load_A(0);
    store_A(0);
    CP_WAIT0();
    __syncthreads();

    const int S = SEQ / 64;
    for (int s = 0; s < S; s++) {
        if (s + 1 < S) {
            cp_B((s + 1) & 1, (s + 1) << 6); CP_COMMIT();
            load_A((s + 1) << 6);
        }
        mma_slab_pv(sbase + (s & 1) * BUFPV, c, wid, lane);
        if (s + 1 < S) {
            store_A((s + 1) & 1);
            CP_WAIT0();
            __syncthreads();
        }
    }

#pragma unroll
    for (int i = 0; i < 8; i++) {
        float v = se[i];
        v += __shfl_xor_sync(0xffffffffu, v, 1);
        v += __shfl_xor_sync(0xffffffffu, v, 2);
        v += __shfl_xor_sync(0xffffffffu, v, 4);
        v += __shfl_xor_sync(0xffffffffu, v, 8);
        if ((t & 15) == 0) s_se[(i << 4) + ar] = v;
    }
    __syncthreads();

    const int wm = (wid & 3) << 5, wn = (wid >> 2) << 5;
    const int r4 = lane >> 2, c2 = (lane & 3) << 1;
#pragma unroll
    for (int mf = 0; mf < 2; mf++)
#pragma unroll
        for (int half = 0; half < 2; half++) {
            const int rl = wm + (mf << 4) + (half << 3) + r4;
            const float rse = 1.0f / s_se[rl];
            const size_t gr = (size_t)(b * SEQ + m0 + rl) * DMODEL;
#pragma unroll
            for (int nf = 0; nf < 4; nf++) {
                const int gc = h * HDIM + wn + (nf << 3) + c2;
                float ox = c[mf][nf][half * 2 + 0] * rse;
                float oy = c[mf][nf][half * 2 + 1] * rse;
                __nv_bfloat162 hh = __floats2bfloat162_rn(ox, oy);
                __nv_bfloat162 ll = __floats2bfloat162_rn(ox - __low2float(hh),
                                                          oy - __high2float(hh));
                *(uint32_t*)&g_ah[gr + gc] = *(uint32_t*)&hh;
                *(uint32_t*)&g_al[gr + gc] = *(uint32_t*)&ll;
            }
        }
}

// ============================================================================
// Final projection: attn (split bf16) @ proj_w^T (split bf16) + bias -> fp32.
// cp.async operands, 3-chain MMA.
// ============================================================================
__global__ __launch_bounds__(256, 2) void proj_tc(float* __restrict__ out,
                                                  const float* __restrict__ bias)
{
    extern __shared__ char sm[];
    const int t = threadIdx.x, lane = t & 31, wid = t >> 5;
    const int m0 = blockIdx.y * 128, n0 = blockIdx.x * 64;
    const uint32_t sbase = smem_u32(sm);

    auto cp_slab = [&](int bs, int k0) {
        uint32_t db = sbase + bs * BUF3;
#pragma unroll
        for (int i = 0; i < 4; i++) {
            int idx = i * 256 + t, row = idx >> 3, q8 = (idx & 7) << 3;
            uint32_t dsw = soff(row, q8) * 2;
            cp16(db + A_HI + dsw, g_ah + (size_t)(m0 + row) * DMODEL + k0 + q8);
            cp16(db + A_LO + dsw, g_al + (size_t)(m0 + row) * DMODEL + k0 + q8);
        }
#pragma unroll
        for (int i = 0; i < 2; i++) {
            int idx = i * 256 + t, row = idx >> 3, q8 = (idx & 7) << 3;
            uint32_t dsw = soff(row, q8) * 2;
            cp16(db + B_HI + dsw, g_pwh + (size_t)(n0 + row) * DMODEL + k0 + q8);
            cp16(db + B_LO + dsw, g_pwl + (size_t)(n0 + row) * DMODEL + k0 + q8);
        }
    };

    float c[2][4][4] = {};
    cp_slab(0, 0); CP_COMMIT();
    const int S = DMODEL >> 6;
    for (int s = 0; s < S; s++) {
        if (s + 1 < S) { cp_slab((s + 1) & 1, (s + 1) << 6); CP_COMMIT(); CP_WAIT1(); }
        else CP_WAIT0();
        __syncthreads();
        mma_slab3(sbase + (s & 1) * BUF3, c, wid, lane);
        __syncthreads();
    }

    const int wm = (wid & 3) << 5, wn = (wid >> 2) << 5;
    const int r4 = lane >> 2, c2 = (lane & 3) << 1;
#pragma unroll
    for (int mf = 0; mf < 2; mf++)
#pragma unroll
        for (int half = 0; half < 2; half++) {
            const int row = m0 + wm + (mf << 4) + (half << 3) + r4;
#pragma unroll
            for (int nf = 0; nf < 4; nf++) {
                const int col = n0 + wn + (nf << 3) + c2;
                float2 o;
                o.x = c[mf][nf][half * 2 + 0] + bias[col];
                o.y = c[mf][nf][half * 2 + 1] + bias[col + 1];
                *(float2*)&out[(size_t)row * DMODEL + col] = o;
            }
        }
}

// ---------------------------------------------------------------------------
extern "C" void kernel_launch(void* const* d_in, const int* in_sizes, int n_in,
                              void* d_out, int out_size)
{
    const float* x      = (const float*)d_in[0];
    const float* qkv_w  = (const float*)d_in[1];
    const float* qkv_b  = (const float*)d_in[2];
    const float* proj_w = (const float*)d_in[3];
    const float* proj_b = (const float*)d_in[4];
    float* out = (float*)d_out;

    __nv_bfloat16 *xh, *xl, *wh, *wl, *pwh, *pwl;
    cudaGetSymbolAddress((void**)&xh, g_xh);   cudaGetSymbolAddress((void**)&xl, g_xl);
    cudaGetSymbolAddress((void**)&wh, g_wh);   cudaGetSymbolAddress((void**)&wl, g_wl);
    cudaGetSymbolAddress((void**)&pwh, g_pwh); cudaGetSymbolAddress((void**)&pwl, g_pwl);

    cudaFuncSetAttribute(qkv_tc, cudaFuncAttributeMaxDynamicSharedMemorySize, 2 * BUF3);
    cudaFuncSetAttribute(scores_bf, cudaFuncAttributeMaxDynamicSharedMemorySize, SMEM_SC);
    cudaFuncSetAttribute(pv_tc, cudaFuncAttributeMaxDynamicSharedMemorySize, 2 * BUFPV);
    cudaFuncSetAttribute(proj_tc, cudaFuncAttributeMaxDynamicSharedMemorySize, 2 * BUF3);

    // 0) zero sumsq + pre-split fp32 inputs into bf16 hi/lo
    zero_stats<<<32, 256>>>();
    presplit<<<(BATCH * SEQ * DMODEL) / 1024, 256>>>((const float4*)x, xh, xl);
    presplit<<<(QKVDIM * DMODEL) / 1024, 256>>>((const float4*)qkv_w, wh, wl);
    presplit<<<(DMODEL * DMODEL) / 1024, 256>>>((const float4*)proj_w, pwh, pwl);

    // 1) QKV projection (3-chain bf16, cp.async) -> fp16 Q/K, split-fp16 V^T
    qkv_tc<<<dim3(QKVDIM / 64, (BATCH * SEQ) / 128), 256, 2 * BUF3>>>(qkv_b);

    // 2) scores = Q K^T (fp16 single-chain), fp16 out + sumsq
    scores_bf<<<dim3(SEQ / 64, SEQ / 128, ZTOT), 256, SMEM_SC>>>();

    // 3) fused norm+softmax+PV (fp16 P x split-fp16 V, 2 chains) -> split-bf16 attn
    pv_tc<<<dim3(1, SEQ / 128, ZTOT), 256, 2 * BUFPV>>>();

    // 4) final projection (3-chain bf16, cp.async) -> fp32 out
    proj_tc<<<dim3(DMODEL / 64, (BATCH * SEQ) / 128), 256, 2 * BUF3>>>(out, proj_b);
}

// round 13
// speedup vs baseline: 4.8233x; 1.2032x over previous
#include <cuda_runtime.h>
#include <cuda_bf16.h>
#include <cuda_fp16.h>
#include <math.h>
#include <stdint.h>

// Problem constants: B=2, N=2048, D=512, H=8, hd=64
#define BATCH 2
#define SEQ   2048
#define DMODEL 512
#define HEADS 8
#define HDIM  64
#define QKVDIM 1536
#define ZTOT  (BATCH * HEADS)        // 16
#define ZSTRIDE ((size_t)SEQ * HDIM) // 131072

// ---------------- scratch (no cudaMalloc -> __device__ globals) ----------------
// pre-split bf16 hi/lo of fp32 inputs
__device__ __nv_bfloat16 g_xh[(size_t)BATCH * SEQ * DMODEL], g_xl[(size_t)BATCH * SEQ * DMODEL];
__device__ __nv_bfloat16 g_wh[(size_t)QKVDIM * DMODEL],      g_wl[(size_t)QKVDIM * DMODEL];
__device__ __nv_bfloat16 g_pwh[(size_t)DMODEL * DMODEL],     g_pwl[(size_t)DMODEL * DMODEL];
// fp16 attention operands (produced by qkv epilogue)
__device__ __half g_q16[(size_t)ZTOT * SEQ * HDIM];           // Q, pre-scaled x0.125
__device__ __half g_k16[(size_t)ZTOT * SEQ * HDIM];           // K row-major [z][n][d]
__device__ __half g_kt16[(size_t)ZTOT * HDIM * SEQ];          // K transposed [z][d][n]
__device__ __half g_vh16[(size_t)ZTOT * HDIM * SEQ];          // V transposed, hi
__device__ __half g_vl16[(size_t)ZTOT * HDIM * SEQ];          // lo residual
// Gram matrix G = K^T K per z, split fp16
__device__ __half g_Gh[(size_t)ZTOT * HDIM * HDIM], g_Gl[(size_t)ZTOT * HDIM * HDIM];
// attn output, pre-split bf16 for proj
__device__ __nv_bfloat16 g_ah[(size_t)BATCH * SEQ * DMODEL], g_al[(size_t)BATCH * SEQ * DMODEL];

// ---------------- smem layout: stride-64 rows, XOR swizzle on 16B units ----------------
__device__ __forceinline__ uint32_t soff(int row, int k) {
    int u = ((k >> 3) ^ row) & 7;
    return (uint32_t)((row << 6) + (u << 3) + (k & 7));
}
__device__ __forceinline__ uint32_t smem_u32(const void* p) {
    uint32_t a;
    asm("{ .reg .u64 t; cvta.to.shared.u64 t, %1; cvt.u32.u64 %0, t; }" : "=r"(a) : "l"(p));
    return a;
}
__device__ __forceinline__ void ldsm_x4(uint32_t* r, uint32_t addr) {
    asm volatile("ldmatrix.sync.aligned.m8n8.x4.shared.b16 {%0,%1,%2,%3}, [%4];"
        : "=r"(r[0]), "=r"(r[1]), "=r"(r[2]), "=r"(r[3]) : "r"(addr));
}
__device__ __forceinline__ void mma_bf16(float* c, const uint32_t* a, const uint32_t* b) {
    asm volatile("mma.sync.aligned.m16n8k16.row.col.f32.bf16.bf16.f32 "
        "{%0,%1,%2,%3}, {%4,%5,%6,%7}, {%8,%9}, {%0,%1,%2,%3};"
        : "+f"(c[0]), "+f"(c[1]), "+f"(c[2]), "+f"(c[3])
        : "r"(a[0]), "r"(a[1]), "r"(a[2]), "r"(a[3]), "r"(b[0]), "r"(b[1]));
}
__device__ __forceinline__ void mma_f16(float* c, const uint32_t* a, const uint32_t* b) {
    asm volatile("mma.sync.aligned.m16n8k16.row.col.f32.f16.f16.f32 "
        "{%0,%1,%2,%3}, {%4,%5,%6,%7}, {%8,%9}, {%0,%1,%2,%3};"
        : "+f"(c[0]), "+f"(c[1]), "+f"(c[2]), "+f"(c[3])
        : "r"(a[0]), "r"(a[1]), "r"(a[2]), "r"(a[3]), "r"(b[0]), "r"(b[1]));
}
__device__ __forceinline__ void cp16(uint32_t dst, const void* src) {
    asm volatile("cp.async.cg.shared.global [%0], [%1], 16;" :: "r"(dst), "l"(src));
}
#define CP_COMMIT() asm volatile("cp.async.commit_group;" ::: "memory")
#define CP_WAIT0()  asm volatile("cp.async.wait_group 0;" ::: "memory")
#define CP_WAIT1()  asm volatile("cp.async.wait_group 1;" ::: "memory")

// bf16 3-chain GEMM buffers (qkv, proj)
#define A_HI 0
#define A_LO 16384
#define B_HI 32768
#define B_LO 40960
#define BUF3 49152
// pv_fused layout
#define PQ_OFF 0         // Q fp16 128x64 (16 KB), persistent
#define PG_OFF 16384     // G hi (8 KB) then P (16 KB)
#define PG_LO  24576     // G lo (8 KB)
#define PBUF0  32768     // 2 slab buffers
#define PVH_OFF 8192
#define PVL_OFF 16384
#define PBUFSZ 24576
#define PV_SMEM (PBUF0 + 2 * PBUFSZ)   // 81920

// ---------------- 3-chain bf16 slab MMA (warp grid 4x2, warp tile 32x32) ----------------
__device__ __forceinline__ void mma_slab3(uint32_t sbase, float c[2][4][4], int wid, int lane) {
    const int wm = (wid & 3) << 5, wn = (wid >> 2) << 5;
    const int lrow = lane & 15, lhalf = lane >> 4;
    const int bq = lane >> 3, br = lane & 7;
    const int bnq = ((bq >> 1) << 3) + br, bk8 = (bq & 1) << 3;
#pragma unroll
    for (int kk = 0; kk < 64; kk += 16) {
        uint32_t ah[2][4], al[2][4], bh[2][4], bl[2][4];
#pragma unroll
        for (int mf = 0; mf < 2; mf++) {
            uint32_t o = soff(wm + (mf << 4) + lrow, kk + (lhalf << 3)) * 2;
            ldsm_x4(ah[mf], sbase + A_HI + o);
            ldsm_x4(al[mf], sbase + A_LO + o);
        }
#pragma unroll
        for (int np = 0; np < 2; np++) {
            uint32_t o = soff(wn + (np << 4) + bnq, kk + bk8) * 2;
            ldsm_x4(bh[np], sbase + B_HI + o);
            ldsm_x4(bl[np], sbase + B_LO + o);
        }
#pragma unroll
        for (int mf = 0; mf < 2; mf++)
#pragma unroll
            for (int nf = 0; nf < 4; nf++) {
                const uint32_t* bhp = &bh[nf >> 1][(nf & 1) << 1];
                const uint32_t* blp = &bl[nf >> 1][(nf & 1) << 1];
                mma_bf16(c[mf][nf], ah[mf], bhp);
                mma_bf16(c[mf][nf], ah[mf], blp);
                mma_bf16(c[mf][nf], al[mf], bhp);
            }
    }
}

// ============================================================================
// presplit: fp32 -> bf16 hi/lo
// ============================================================================
__global__ void presplit(const float4* __restrict__ src,
                         __nv_bfloat16* __restrict__ hi, __nv_bfloat16* __restrict__ lo)
{
    int i = blockIdx.x * 256 + threadIdx.x;
    float4 v = src[i];
    __nv_bfloat162 h0 = __floats2bfloat162_rn(v.x, v.y);
    __nv_bfloat162 h1 = __floats2bfloat162_rn(v.z, v.w);
    __nv_bfloat162 l0 = __floats2bfloat162_rn(v.x - __low2float(h0), v.y - __high2float(h0));
    __nv_bfloat162 l1 = __floats2bfloat162_rn(v.z - __low2float(h1), v.w - __high2float(h1));
    uint2 hu, lu;
    hu.x = *(uint32_t*)&h0; hu.y = *(uint32_t*)&h1;
    lu.x = *(uint32_t*)&l0; lu.y = *(uint32_t*)&l1;
    *(uint2*)(hi + 4 * (size_t)i) = hu;
    *(uint2*)(lo + 4 * (size_t)i) = lu;
}

// ============================================================================
// QKV projection (3-chain bf16, cp.async). Epilogue: Q fp16 (x0.125);
// K fp16 row-major + transposed; V split fp16 transposed.
// ============================================================================
__global__ __launch_bounds__(256, 2) void qkv_tc(const float* __restrict__ bias)
{
    extern __shared__ char sm[];
    const int t = threadIdx.x, lane = t & 31, wid = t >> 5;
    const int m0 = blockIdx.y * 128, n0 = blockIdx.x * 64;
    const uint32_t sbase = smem_u32(sm);

    auto cp_slab = [&](int bs, int k0) {
        uint32_t db = sbase + bs * BUF3;
#pragma unroll
        for (int i = 0; i < 4; i++) {
            int idx = i * 256 + t, row = idx >> 3, q8 = (idx & 7) << 3;
            uint32_t dsw = soff(row, q8) * 2;
            cp16(db + A_HI + dsw, g_xh + (size_t)(m0 + row) * DMODEL + k0 + q8);
            cp16(db + A_LO + dsw, g_xl + (size_t)(m0 + row) * DMODEL + k0 + q8);
        }
#pragma unroll
        for (int i = 0; i < 2; i++) {
            int idx = i * 256 + t, row = idx >> 3, q8 = (idx & 7) << 3;
            uint32_t dsw = soff(row, q8) * 2;
            cp16(db + B_HI + dsw, g_wh + (size_t)(n0 + row) * DMODEL + k0 + q8);
            cp16(db + B_LO + dsw, g_wl + (size_t)(n0 + row) * DMODEL + k0 + q8);
        }
    };

    float c[2][4][4] = {};
    cp_slab(0, 0); CP_COMMIT();
    const int S = DMODEL >> 6;
    for (int s = 0; s < S; s++) {
        if (s + 1 < S) { cp_slab((s + 1) & 1, (s + 1) << 6); CP_COMMIT(); CP_WAIT1(); }
        else CP_WAIT0();
        __syncthreads();
        mma_slab3(sbase + (s & 1) * BUF3, c, wid, lane);
        __syncthreads();
    }

    const int wm = (wid & 3) << 5, wn = (wid >> 2) << 5;
    const int r4 = lane >> 2, c2 = (lane & 3) << 1;
    const int typ = n0 >> 9, h = (n0 >> 6) & 7, b = m0 >> 11;
    const int z = b * HEADS + h;
    const int nloc = m0 & (SEQ - 1);

    if (typ == 0) {
        __half* dst = g_q16 + (size_t)z * ZSTRIDE;
#pragma unroll
        for (int mf = 0; mf < 2; mf++)
#pragma unroll
            for (int half = 0; half < 2; half++) {
                const int row = wm + (mf << 4) + (half << 3) + r4;
#pragma unroll
                for (int nf = 0; nf < 4; nf++) {
                    const int d = wn + (nf << 3) + c2;
                    float ox = (c[mf][nf][half * 2 + 0] + bias[n0 + d]) * 0.125f;
                    float oy = (c[mf][nf][half * 2 + 1] + bias[n0 + d + 1]) * 0.125f;
                    *(__half2*)&dst[(size_t)(nloc + row) * HDIM + d] = __floats2half2_rn(ox, oy);
                }
            }
    } else if (typ == 1) {
        // K: row-major fp16 + transposed fp16 via smem staging
        __half* dst = g_k16 + (size_t)z * ZSTRIDE;
        __half* th = (__half*)sm;
#pragma unroll
        for (int mf = 0; mf < 2; mf++)
#pragma unroll
            for (int half = 0; half < 2; half++) {
                const int row = wm + (mf << 4) + (half << 3) + r4;
#pragma unroll
                for (int nf = 0; nf < 4; nf++) {
                    const int d = wn + (nf << 3) + c2;
                    float ox = c[mf][nf][half * 2 + 0] + bias[n0 + d];
                    float oy = c[mf][nf][half * 2 + 1] + bias[n0 + d + 1];
                    __half hx = __float2half_rn(ox), hy = __float2half_rn(oy);
                    *(__half2*)&dst[(size_t)(nloc + row) * HDIM + d] = __halves2half2(hx, hy);
                    th[d * 136 + row]       = hx;
                    th[(d + 1) * 136 + row] = hy;
                }
            }
        __syncthreads();
        __half* kt = g_kt16 + (size_t)z * ZSTRIDE;
#pragma unroll
        for (int i = 0; i < 8; i++) {
            int idx = i * 256 + t, d = idx >> 5, nm = (idx & 31) << 2;
            *(uint2*)&kt[(size_t)d * SEQ + nloc + nm] = *(uint2*)&th[d * 136 + nm];
        }
    } else {
        // V: split fp16, transposed via smem staging
        __half* th = (__half*)sm;
        __half* tl = th + 64 * 136;
#pragma unroll
        for (int mf = 0; mf < 2; mf++)
#pragma unroll
            for (int half = 0; half < 2; half++) {
                const int row = wm + (mf << 4) + (half << 3) + r4;
#pragma unroll
                for (int nf = 0; nf < 4; nf++) {
                    const int d = wn + (nf << 3) + c2;
                    float ox = c[mf][nf][half * 2 + 0] + bias[n0 + d];
                    float oy = c[mf][nf][half * 2 + 1] + bias[n0 + d + 1];
                    __half hx = __float2half_rn(ox), hy = __float2half_rn(oy);
                    th[d * 136 + row] = hx;
                    th[(d + 1) * 136 + row] = hy;
                    tl[d * 136 + row] = __float2half_rn(ox - __half2float(hx));
                    tl[(d + 1) * 136 + row] = __float2half_rn(oy - __half2float(hy));
                }
            }
        __syncthreads();
        __half* vh = g_vh16 + (size_t)z * ZSTRIDE;
        __half* vl = g_vl16 + (size_t)z * ZSTRIDE;
#pragma unroll
        for (int i = 0; i < 8; i++) {
            int idx = i * 256 + t, d = idx >> 5, nm = (idx & 31) << 2;
            *(uint2*)&vh[(size_t)d * SEQ + nloc + nm] = *(uint2*)&th[d * 136 + nm];
            *(uint2*)&vl[(size_t)d * SEQ + nloc + nm] = *(uint2*)&tl[d * 136 + nm];
        }
    }
}

// ============================================================================
// gmat: G = K^T K per z from g_kt16 (fp16, fp32 accum), output split fp16.
// One CTA per z, K-loop over m=2048 in 64-slabs. Warp tile 16x32 over 64x64.
// ============================================================================
__global__ __launch_bounds__(256) void gmat_tc()
{
    extern __shared__ char sm[];
    const int t = threadIdx.x, lane = t & 31, wid = t >> 5;
    const int z = blockIdx.x;
    const __half* kt = g_kt16 + (size_t)z * ZSTRIDE;
    const uint32_t sbase = smem_u32(sm);

    auto cp_slab = [&](int bs, int k0) {
        uint32_t db = sbase + bs * 8192;
#pragma unroll
        for (int i = 0; i < 2; i++) {
            int idx = i * 256 + t, row = idx >> 3, q8 = (idx & 7) << 3;
            cp16(db + soff(row, q8) * 2, kt + (size_t)row * SEQ + k0 + q8);
        }
    };

    const int wm = (wid & 3) << 4, wn = (wid >> 2) << 5;
    const int lrow = lane & 15, lhalf = lane >> 4;
    const int bq = lane >> 3, br = lane & 7;
    const int bnq = ((bq >> 1) << 3) + br, bk8 = (bq & 1) << 3;

    float c[4][4] = {};
    cp_slab(0, 0); CP_COMMIT();
    const int S = SEQ >> 6;
    for (int s = 0; s < S; s++) {
        if (s + 1 < S) { cp_slab((s + 1) & 1, (s + 1) << 6); CP_COMMIT(); CP_WAIT1(); }
        else CP_WAIT0();
        __syncthreads();
        uint32_t db = sbase + (s & 1) * 8192;
#pragma unroll
        for (int kk = 0; kk < 64; kk += 16) {
            uint32_t a[4], b2[2][4];
            ldsm_x4(a, db + soff(wm + lrow, kk + (lhalf << 3)) * 2);
#pragma unroll
            for (int np = 0; np < 2; np++)
                ldsm_x4(b2[np], db + soff(wn + (np << 4) + bnq, kk + bk8) * 2);
#pragma unroll
            for (int nf = 0; nf < 4; nf++)
                mma_f16(c[nf], a, &b2[nf >> 1][(nf & 1) << 1]);
        }
        __syncthreads();
    }

    const int r4 = lane >> 2, c2 = (lane & 3) << 1;
    __half* Gh = g_Gh + (size_t)z * HDIM * HDIM;
    __half* Gl = g_Gl + (size_t)z * HDIM * HDIM;
#pragma unroll
    for (int half = 0; half < 2; half++) {
        const int row = wm + (half << 3) + r4;
#pragma unroll
        for (int nf = 0; nf < 4; nf++) {
            const int col = wn + (nf << 3) + c2;
            float vx = c[nf][half * 2 + 0], vy = c[nf][half * 2 + 1];
            __half hx = __float2half_rn(vx), hy = __float2half_rn(vy);
            *(__half2*)&Gh[row * HDIM + col] = __halves2half2(hx, hy);
            __half lx = __float2half_rn(vx - __half2float(hx));
            __half ly = __float2half_rn(vy - __half2float(hy));
            *(__half2*)&Gl[row * HDIM + col] = __halves2half2(lx, ly);
        }
    }
}

// ============================================================================
// pv_fused: per (z, 128-row tile):
//  prologue: sumsq_r = q_r^T G q_r (T = Q*G via 2-chain MMA, then T.q reduce)
//  main:     recompute S slab (Q x K, 1 chain) -> p = exp(s*inv) -> P smem
//            -> P x V (split fp16, 2 chains). No score scratch at all.
//  epilogue: divide by sumexp, write attn split bf16.
// ============================================================================
__global__ __launch_bounds__(256, 2) void pv_tc()
{
    extern __shared__ char sm[];
    __shared__ float s_inv[128], s_red[128], s_se[128];
    const int t = threadIdx.x, lane = t & 31, wid = t >> 5;
    const int z = blockIdx.z, b = z >> 3, h = z & 7;
    const int m0 = blockIdx.y * 128;
    const __half* q   = g_q16 + (size_t)z * ZSTRIDE;
    const __half* kk16 = g_k16 + (size_t)z * ZSTRIDE;
    const __half* vh  = g_vh16 + (size_t)z * ZSTRIDE;
    const __half* vl  = g_vl16 + (size_t)z * ZSTRIDE;
    const uint32_t sbase = smem_u32(sm);

    const int wm = (wid & 3) << 5, wn = (wid >> 2) << 5;
    const int lrow = lane & 15, lhalf = lane >> 4;
    const int bq = lane >> 3, br = lane & 7;
    const int bnq = ((bq >> 1) << 3) + br, bk8 = (bq & 1) << 3;
    const int r4 = lane >> 2, c2 = (lane & 3) << 1;

    auto cp_slab = [&](int bs, int k0) {
        uint32_t db = sbase + PBUF0 + bs * PBUFSZ;
#pragma unroll
        for (int i = 0; i < 2; i++) {
            int idx = i * 256 + t, row = idx >> 3, q8 = (idx & 7) << 3;
            uint32_t dsw = soff(row, q8) * 2;
            cp16(db + dsw,           kk16 + (size_t)(k0 + row) * HDIM + q8);
            cp16(db + PVH_OFF + dsw, vh + (size_t)row * SEQ + k0 + q8);
            cp16(db + PVL_OFF + dsw, vl + (size_t)row * SEQ + k0 + q8);
        }
    };

    if (t < 128) { s_red[t] = 0.f; s_se[t] = 0.f; }
#pragma unroll
    for (int i = 0; i < 4; i++) {
        int idx = i * 256 + t, row = idx >> 3, q8 = (idx & 7) << 3;
        cp16(sbase + PQ_OFF + soff(row, q8) * 2, q + (size_t)(m0 + row) * HDIM + q8);
    }
#pragma unroll
    for (int i = 0; i < 2; i++) {
        int idx = i * 256 + t, row = idx >> 3, q8 = (idx & 7) << 3;
        uint32_t dsw = soff(row, q8) * 2;
        cp16(sbase + PG_OFF + dsw, g_Gh + (size_t)z * HDIM * HDIM + (size_t)row * HDIM + q8);
        cp16(sbase + PG_LO + dsw,  g_Gl + (size_t)z * HDIM * HDIM + (size_t)row * HDIM + q8);
    }
    cp_slab(0, 0);
    CP_COMMIT(); CP_WAIT0();
    __syncthreads();

    // ---- sumsq via T = Q G; sumsq_r = sum_col T[r,:] * q[r,:] ----
    {
        float ct[2][4][4] = {};
#pragma unroll
        for (int kq = 0; kq < 64; kq += 16) {
            uint32_t a[2][4], bh2[2][4], bl2[2][4];
#pragma unroll
            for (int mf = 0; mf < 2; mf++)
                ldsm_x4(a[mf], sbase + PQ_OFF + soff(wm + (mf << 4) + lrow, kq + (lhalf << 3)) * 2);
#pragma unroll
            for (int np = 0; np < 2; np++) {
                uint32_t o = soff(wn + (np << 4) + bnq, kq + bk8) * 2;
                ldsm_x4(bh2[np], sbase + PG_OFF + o);
                ldsm_x4(bl2[np], sbase + PG_LO + o);
            }
#pragma unroll
            for (int mf = 0; mf < 2; mf++)
#pragma unroll
                for (int nf = 0; nf < 4; nf++) {
                    mma_f16(ct[mf][nf], a[mf], &bh2[nf >> 1][(nf & 1) << 1]);
                    mma_f16(ct[mf][nf], a[mf], &bl2[nf >> 1][(nf & 1) << 1]);
                }
        }
        float ssq[4] = {0.f, 0.f, 0.f, 0.f};
#pragma unroll
        for (int mf = 0; mf < 2; mf++)
#pragma unroll
            for (int half = 0; half < 2; half++) {
                const int row = wm + (mf << 4) + (half << 3) + r4;
#pragma unroll
                for (int nf = 0; nf < 4; nf++) {
                    const int col = wn + (nf << 3) + c2;
                    float2 qf = __half22float2(*(__half2*)(sm + PQ_OFF + soff(row, col) * 2));
                    ssq[mf * 2 + half] += ct[mf][nf][half * 2 + 0] * qf.x
                                        + ct[mf][nf][half * 2 + 1] * qf.y;
                }
            }
#pragma unroll
        for (int j = 0; j < 4; j++) {
            float v = ssq[j];
            v += __shfl_xor_sync(0xffffffffu, v, 1);
            v += __shfl_xor_sync(0xffffffffu, v, 2);
            if ((lane & 3) == 0)
                atomicAdd(&s_red[wm + ((j >> 1) << 4) + ((j & 1) << 3) + r4], v);
        }
    }
    __syncthreads();
    if (t < 128) s_inv[t] = 1.0f / (sqrtf(s_red[t]) + 1e-6f);
    __syncthreads();

    // ---- main loop: S recompute -> exp -> P x V ----
    float c_pv[2][4][4] = {};
    float se[4] = {0.f, 0.f, 0.f, 0.f};
    const int S = SEQ >> 6;
    for (int s = 0; s < S; s++) {
        if (s + 1 < S) { cp_slab((s + 1) & 1, (s + 1) << 6); CP_COMMIT(); }
        uint32_t db = sbase + PBUF0 + (s & 1) * PBUFSZ;

        float cs[2][4][4] = {};
#pragma unroll
        for (int kq = 0; kq < 64; kq += 16) {
            uint32_t a[2][4], b2[2][4];
#pragma unroll
            for (int mf = 0; mf < 2; mf++)
                ldsm_x4(a[mf], sbase + PQ_OFF + soff(wm + (mf << 4) + lrow, kq + (lhalf << 3)) * 2);
#pragma unroll
            for (int np = 0; np < 2; np++)
                ldsm_x4(b2[np], db + soff(wn + (np << 4) + bnq, kq + bk8) * 2);
#pragma unroll
            for (int mf = 0; mf < 2; mf++)
#pragma unroll
                for (int nf = 0; nf < 4; nf++)
                    mma_f16(cs[mf][nf], a[mf], &b2[nf >> 1][(nf & 1) << 1]);
        }
#pragma unroll
        for (int mf = 0; mf < 2; mf++)
#pragma unroll
            for (int half = 0; half < 2; half++) {
                const int row = wm + (mf << 4) + (half << 3) + r4;
                const float inv = s_inv[row];
#pragma unroll
                for (int nf = 0; nf < 4; nf++) {
                    float ex = __expf(cs[mf][nf][half * 2 + 0] * inv);
                    float ey = __expf(cs[mf][nf][half * 2 + 1] * inv);
                    se[mf * 2 + half] += ex + ey;
                    *(__half2*)(sm + PG_OFF + soff(row, wn + (nf << 3) + c2) * 2)
                        = __floats2half2_rn(ex, ey);
                }
            }
        __syncthreads();
#pragma unroll
        for (int kq = 0; kq < 64; kq += 16) {
            uint32_t a[2][4], bh2[2][4], bl2[2][4];
#pragma unroll
            for (int mf = 0; mf < 2; mf++)
                ldsm_x4(a[mf], sbase + PG_OFF + soff(wm + (mf << 4) + lrow, kq + (lhalf << 3)) * 2);
#pragma unroll
            for (int np = 0; np < 2; np++) {
                uint32_t o = soff(wn + (np << 4) + bnq, kq + bk8) * 2;
                ldsm_x4(bh2[np], db + PVH_OFF + o);
                ldsm_x4(bl2[np], db + PVL_OFF + o);
            }
#pragma unroll
            for (int mf = 0; mf < 2; mf++)
#pragma unroll
                for (int nf = 0; nf < 4; nf++) {
                    mma_f16(c_pv[mf][nf], a[mf], &bh2[nf >> 1][(nf & 1) << 1]);
                    mma_f16(c_pv[mf][nf], a[mf], &bl2[nf >> 1][(nf & 1) << 1]);
                }
        }
        if (s + 1 < S) CP_WAIT0();
        __syncthreads();
    }

    // ---- sumexp reduce + epilogue ----
#pragma unroll
    for (int j = 0; j < 4; j++) {
        float v = se[j];
        v += __shfl_xor_sync(0xffffffffu, v, 1);
        v += __shfl_xor_sync(0xffffffffu, v, 2);
        if ((lane & 3) == 0)
            atomicAdd(&s_se[wm + ((j >> 1) << 4) + ((j & 1) << 3) + r4], v);
    }
    __syncthreads();

#pragma unroll
    for (int mf = 0; mf < 2; mf++)
#pragma unroll
        for (int half = 0; half < 2; half++) {
            const int rl = wm + (mf << 4) + (half << 3) + r4;
            const float rse = 1.0f / s_se[rl];
            const size_t gr = (size_t)(b * SEQ + m0 + rl) * DMODEL;
#pragma unroll
            for (int nf = 0; nf < 4; nf++) {
                const int gc = h * HDIM + wn + (nf << 3) + c2;
                float ox = c_pv[mf][nf][half * 2 + 0] * rse;
                float oy = c_pv[mf][nf][half * 2 + 1] * rse;
                __nv_bfloat162 hh = __floats2bfloat162_rn(ox, oy);
                __nv_bfloat162 ll = __floats2bfloat162_rn(ox - __low2float(hh),
                                                          oy - __high2float(hh));
                *(uint32_t*)&g_ah[gr + gc] = *(uint32_t*)&hh;
                *(uint32_t*)&g_al[gr + gc] = *(uint32_t*)&ll;
            }
        }
}

// ============================================================================
// Final projection: attn (split bf16) @ proj_w^T (split bf16) + bias -> fp32.
// ============================================================================
__global__ __launch_bounds__(256, 2) void proj_tc(float* __restrict__ out,
                                                  const float* __restrict__ bias)
{
    extern __shared__ char sm[];
    const int t = threadIdx.x, lane = t & 31, wid = t >> 5;
    const int m0 = blockIdx.y * 128, n0 = blockIdx.x * 64;
    const uint32_t sbase = smem_u32(sm);

    auto cp_slab = [&](int bs, int k0) {
        uint32_t db = sbase + bs * BUF3;
#pragma unroll
        for (int i = 0; i < 4; i++) {
            int idx = i * 256 + t, row = idx >> 3, q8 = (idx & 7) << 3;
            uint32_t dsw = soff(row, q8) * 2;
            cp16(db + A_HI + dsw, g_ah + (size_t)(m0 + row) * DMODEL + k0 + q8);
            cp16(db + A_LO + dsw, g_al + (size_t)(m0 + row) * DMODEL + k0 + q8);
        }
#pragma unroll
        for (int i = 0; i < 2; i++) {
            int idx = i * 256 + t, row = idx >> 3, q8 = (idx & 7) << 3;
            uint32_t dsw = soff(row, q8) * 2;
            cp16(db + B_HI + dsw, g_pwh + (size_t)(n0 + row) * DMODEL + k0 + q8);
            cp16(db + B_LO + dsw, g_pwl + (size_t)(n0 + row) * DMODEL + k0 + q8);
        }
    };

    float c[2][4][4] = {};
    cp_slab(0, 0); CP_COMMIT();
    const int S = DMODEL >> 6;
    for (int s = 0; s < S; s++) {
        if (s + 1 < S) { cp_slab((s + 1) & 1, (s + 1) << 6); CP_COMMIT(); CP_WAIT1(); }
        else CP_WAIT0();
        __syncthreads();
        mma_slab3(sbase + (s & 1) * BUF3, c, wid, lane);
        __syncthreads();
    }

    const int wm = (wid & 3) << 5, wn = (wid >> 2) << 5;
    const int r4 = lane >> 2, c2 = (lane & 3) << 1;
#pragma unroll
    for (int mf = 0; mf < 2; mf++)
#pragma unroll
        for (int half = 0; half < 2; half++) {
            const int row = m0 + wm + (mf << 4) + (half << 3) + r4;
#pragma unroll
            for (int nf = 0; nf < 4; nf++) {
                const int col = n0 + wn + (nf << 3) + c2;
                float2 o;
                o.x = c[mf][nf][half * 2 + 0] + bias[col];
                o.y = c[mf][nf][half * 2 + 1] + bias[col + 1];
                *(float2*)&out[(size_t)row * DMODEL + col] = o;
            }
        }
}

// ---------------------------------------------------------------------------
extern "C" void kernel_launch(void* const* d_in, const int* in_sizes, int n_in,
                              void* d_out, int out_size)
{
    const float* x      = (const float*)d_in[0];
    const float* qkv_w  = (const float*)d_in[1];
    const float* qkv_b  = (const float*)d_in[2];
    const float* proj_w = (const float*)d_in[3];
    const float* proj_b = (const float*)d_in[4];
    float* out = (float*)d_out;

    __nv_bfloat16 *xh, *xl, *wh, *wl, *pwh, *pwl;
    cudaGetSymbolAddress((void**)&xh, g_xh);   cudaGetSymbolAddress((void**)&xl, g_xl);
    cudaGetSymbolAddress((void**)&wh, g_wh);   cudaGetSymbolAddress((void**)&wl, g_wl);
    cudaGetSymbolAddress((void**)&pwh, g_pwh); cudaGetSymbolAddress((void**)&pwl, g_pwl);

    cudaFuncSetAttribute(qkv_tc, cudaFuncAttributeMaxDynamicSharedMemorySize, 2 * BUF3);
    cudaFuncSetAttribute(gmat_tc, cudaFuncAttributeMaxDynamicSharedMemorySize, 16384);
    cudaFuncSetAttribute(pv_tc, cudaFuncAttributeMaxDynamicSharedMemorySize, PV_SMEM);
    cudaFuncSetAttribute(proj_tc, cudaFuncAttributeMaxDynamicSharedMemorySize, 2 * BUF3);

    // 0) pre-split fp32 inputs into bf16 hi/lo
    presplit<<<(BATCH * SEQ * DMODEL) / 1024, 256>>>((const float4*)x, xh, xl);
    presplit<<<(QKVDIM * DMODEL) / 1024, 256>>>((const float4*)qkv_w, wh, wl);
    presplit<<<(DMODEL * DMODEL) / 1024, 256>>>((const float4*)proj_w, pwh, pwl);

    // 1) QKV projection -> fp16 Q / K / K^T, split-fp16 V^T
    qkv_tc<<<dim3(QKVDIM / 64, (BATCH * SEQ) / 128), 256, 2 * BUF3>>>(qkv_b);

    // 2) Gram matrices G = K^T K (16 CTAs)
    gmat_tc<<<16, 256, 16384>>>();

    // 3) fused norm+softmax+attention (no score scratch)
    pv_tc<<<dim3(1, SEQ / 128, ZTOT), 256, PV_SMEM>>>();

    // 4) final projection
    proj_tc<<<dim3(DMODEL / 64, (BATCH * SEQ) / 128), 256, 2 * BUF3>>>(out, proj_b);
}

// round 14
// speedup vs baseline: 5.8231x; 1.2073x over previous
#include <cuda_runtime.h>
#include <cuda_bf16.h>
#include <cuda_fp16.h>
#include <math.h>
#include <stdint.h>

// Problem constants: B=2, N=2048, D=512, H=8, hd=64
#define BATCH 2
#define SEQ   2048
#define DMODEL 512
#define HEADS 8
#define HDIM  64
#define QKVDIM 1536
#define ZTOT  (BATCH * HEADS)        // 16
#define ZSTRIDE ((size_t)SEQ * HDIM) // 131072

// ---------------- scratch (no cudaMalloc -> __device__ globals) ----------------
__device__ __nv_bfloat16 g_xh[(size_t)BATCH * SEQ * DMODEL], g_xl[(size_t)BATCH * SEQ * DMODEL];
__device__ __nv_bfloat16 g_wh[(size_t)QKVDIM * DMODEL],      g_wl[(size_t)QKVDIM * DMODEL];
__device__ __nv_bfloat16 g_pwh[(size_t)DMODEL * DMODEL],     g_pwl[(size_t)DMODEL * DMODEL];
__device__ __half g_q16[(size_t)ZTOT * SEQ * HDIM];           // Q, pre-scaled x0.125
__device__ __half g_k16[(size_t)ZTOT * SEQ * HDIM];           // K row-major
__device__ __half g_kt16[(size_t)ZTOT * HDIM * SEQ];          // K transposed [z][d][n]
__device__ __half g_vh16[(size_t)ZTOT * HDIM * SEQ];          // V transposed, single fp16
__device__ __half g_Gh[(size_t)ZTOT * HDIM * HDIM], g_Gl[(size_t)ZTOT * HDIM * HDIM];
__device__ __nv_bfloat16 g_ah[(size_t)BATCH * SEQ * DMODEL], g_al[(size_t)BATCH * SEQ * DMODEL];

// ---------------- smem: stride-64 rows, XOR swizzle on 16B units ----------------
__device__ __forceinline__ uint32_t soff(int row, int k) {
    int u = ((k >> 3) ^ row) & 7;
    return (uint32_t)((row << 6) + (u << 3) + (k & 7));
}
__device__ __forceinline__ uint32_t smem_u32(const void* p) {
    uint32_t a;
    asm("{ .reg .u64 t; cvta.to.shared.u64 t, %1; cvt.u32.u64 %0, t; }" : "=r"(a) : "l"(p));
    return a;
}
__device__ __forceinline__ void ldsm_x4(uint32_t* r, uint32_t addr) {
    asm volatile("ldmatrix.sync.aligned.m8n8.x4.shared.b16 {%0,%1,%2,%3}, [%4];"
        : "=r"(r[0]), "=r"(r[1]), "=r"(r[2]), "=r"(r[3]) : "r"(addr));
}
__device__ __forceinline__ void mma_bf16(float* c, const uint32_t* a, const uint32_t* b) {
    asm volatile("mma.sync.aligned.m16n8k16.row.col.f32.bf16.bf16.f32 "
        "{%0,%1,%2,%3}, {%4,%5,%6,%7}, {%8,%9}, {%0,%1,%2,%3};"
        : "+f"(c[0]), "+f"(c[1]), "+f"(c[2]), "+f"(c[3])
        : "r"(a[0]), "r"(a[1]), "r"(a[2]), "r"(a[3]), "r"(b[0]), "r"(b[1]));
}
__device__ __forceinline__ void mma_f16(float* c, const uint32_t* a, const uint32_t* b) {
    asm volatile("mma.sync.aligned.m16n8k16.row.col.f32.f16.f16.f32 "
        "{%0,%1,%2,%3}, {%4,%5,%6,%7}, {%8,%9}, {%0,%1,%2,%3};"
        : "+f"(c[0]), "+f"(c[1]), "+f"(c[2]), "+f"(c[3])
        : "r"(a[0]), "r"(a[1]), "r"(a[2]), "r"(a[3]), "r"(b[0]), "r"(b[1]));
}
__device__ __forceinline__ void cp16(uint32_t dst, const void* src) {
    asm volatile("cp.async.cg.shared.global [%0], [%1], 16;" :: "r"(dst), "l"(src));
}
#define CP_COMMIT() asm volatile("cp.async.commit_group;" ::: "memory")
#define CP_WAIT0()  asm volatile("cp.async.wait_group 0;" ::: "memory")
#define CP_WAIT1()  asm volatile("cp.async.wait_group 1;" ::: "memory")

// bf16 GEMM buffers (qkv, proj)
#define A_HI 0
#define A_LO 16384
#define B_HI 32768
#define B_LO 40960
#define BUF3 49152
// pv layout: Q (16KB) | G-hi(8K)+P(16K, reuses G space) | G-lo | 2 slab bufs (K 8K + VH 8K)
#define PQ_OFF 0
#define PG_OFF 16384
#define PG_LO  24576
#define PBUF0  32768
#define PVH_OFF 8192
#define PBUFSZ 16384
#define PV_SMEM (PBUF0 + 2 * PBUFSZ)   // 65536

// ---------------- slab MMA variants (warp grid 4x2, warp tile 32x32) ----------------
// 3-chain split bf16 (A hi/lo x B hi/lo, drop lo*lo)
__device__ __forceinline__ void mma_slab3(uint32_t sbase, float c[2][4][4], int wid, int lane) {
    const int wm = (wid & 3) << 5, wn = (wid >> 2) << 5;
    const int lrow = lane & 15, lhalf = lane >> 4;
    const int bq = lane >> 3, br = lane & 7;
    const int bnq = ((bq >> 1) << 3) + br, bk8 = (bq & 1) << 3;
#pragma unroll
    for (int kk = 0; kk < 64; kk += 16) {
        uint32_t ah[2][4], al[2][4], bh[2][4], bl[2][4];
#pragma unroll
        for (int mf = 0; mf < 2; mf++) {
            uint32_t o = soff(wm + (mf << 4) + lrow, kk + (lhalf << 3)) * 2;
            ldsm_x4(ah[mf], sbase + A_HI + o);
            ldsm_x4(al[mf], sbase + A_LO + o);
        }
#pragma unroll
        for (int np = 0; np < 2; np++) {
            uint32_t o = soff(wn + (np << 4) + bnq, kk + bk8) * 2;
            ldsm_x4(bh[np], sbase + B_HI + o);
            ldsm_x4(bl[np], sbase + B_LO + o);
        }
#pragma unroll
        for (int mf = 0; mf < 2; mf++)
#pragma unroll
            for (int nf = 0; nf < 4; nf++) {
                const uint32_t* bhp = &bh[nf >> 1][(nf & 1) << 1];
                const uint32_t* blp = &bl[nf >> 1][(nf & 1) << 1];
                mma_bf16(c[mf][nf], ah[mf], bhp);
                mma_bf16(c[mf][nf], ah[mf], blp);
                mma_bf16(c[mf][nf], al[mf], bhp);
            }
    }
}
// 2-chain: A hi only x B hi/lo (for Q/K blocks of qkv — error suppressed by softmax)
__device__ __forceinline__ void mma_slab2(uint32_t sbase, float c[2][4][4], int wid, int lane) {
    const int wm = (wid & 3) << 5, wn = (wid >> 2) << 5;
    const int lrow = lane & 15, lhalf = lane >> 4;
    const int bq = lane >> 3, br = lane & 7;
    const int bnq = ((bq >> 1) << 3) + br, bk8 = (bq & 1) << 3;
#pragma unroll
    for (int kk = 0; kk < 64; kk += 16) {
        uint32_t ah[2][4], bh[2][4], bl[2][4];
#pragma unroll
        for (int mf = 0; mf < 2; mf++)
            ldsm_x4(ah[mf], sbase + A_HI + soff(wm + (mf << 4) + lrow, kk + (lhalf << 3)) * 2);
#pragma unroll
        for (int np = 0; np < 2; np++) {
            uint32_t o = soff(wn + (np << 4) + bnq, kk + bk8) * 2;
            ldsm_x4(bh[np], sbase + B_HI + o);
            ldsm_x4(bl[np], sbase + B_LO + o);
        }
#pragma unroll
        for (int mf = 0; mf < 2; mf++)
#pragma unroll
            for (int nf = 0; nf < 4; nf++) {
                mma_bf16(c[mf][nf], ah[mf], &bh[nf >> 1][(nf & 1) << 1]);
                mma_bf16(c[mf][nf], ah[mf], &bl[nf >> 1][(nf & 1) << 1]);
            }
    }
}

// ============================================================================
// presplit_all: fp32 -> bf16 hi/lo for x, qkv_w, proj_w in one launch.
// ============================================================================
#define NX_F4 ((BATCH * SEQ * DMODEL) / 4)      // 524288
#define NW_F4 ((QKVDIM * DMODEL) / 4)           // 196608
#define NP_F4 ((DMODEL * DMODEL) / 4)           // 65536
__global__ void presplit_all(const float4* __restrict__ x, const float4* __restrict__ w,
                             const float4* __restrict__ pw)
{
    int i = blockIdx.x * 256 + threadIdx.x;
    const float4* src;
    __nv_bfloat16 *hi, *lo;
    int j = i;
    if (i < NX_F4)                  { src = x;  hi = g_xh;  lo = g_xl; }
    else if (i < NX_F4 + NW_F4)     { src = w;  hi = g_wh;  lo = g_wl;  j = i - NX_F4; }
    else                            { src = pw; hi = g_pwh; lo = g_pwl; j = i - NX_F4 - NW_F4; }
    float4 v = src[j];
    __nv_bfloat162 h0 = __floats2bfloat162_rn(v.x, v.y);
    __nv_bfloat162 h1 = __floats2bfloat162_rn(v.z, v.w);
    __nv_bfloat162 l0 = __floats2bfloat162_rn(v.x - __low2float(h0), v.y - __high2float(h0));
    __nv_bfloat162 l1 = __floats2bfloat162_rn(v.z - __low2float(h1), v.w - __high2float(h1));
    uint2 hu, lu;
    hu.x = *(uint32_t*)&h0; hu.y = *(uint32_t*)&h1;
    lu.x = *(uint32_t*)&l0; lu.y = *(uint32_t*)&l1;
    *(uint2*)(hi + 4 * (size_t)j) = hu;
    *(uint2*)(lo + 4 * (size_t)j) = lu;
}

// ============================================================================
// QKV projection. Q/K column-blocks: 2-chain (no x-lo loads). V blocks: 3-chain.
// Epilogue: Q fp16 (x0.125); K fp16 + K^T; V single fp16 transposed.
// ============================================================================
__global__ __launch_bounds__(256, 2) void qkv_tc(const float* __restrict__ bias)
{
    extern __shared__ char sm[];
    const int t = threadIdx.x, lane = t & 31, wid = t >> 5;
    const int m0 = blockIdx.y * 128, n0 = blockIdx.x * 64;
    const uint32_t sbase = smem_u32(sm);
    const int typ = n0 >> 9;          // 0=q 1=k 2=v
    const bool isV = (typ == 2);

    auto cp_slab = [&](int bs, int k0) {
        uint32_t db = sbase + bs * BUF3;
#pragma unroll
        for (int i = 0; i < 4; i++) {
            int idx = i * 256 + t, row = idx >> 3, q8 = (idx & 7) << 3;
            uint32_t dsw = soff(row, q8) * 2;
            cp16(db + A_HI + dsw, g_xh + (size_t)(m0 + row) * DMODEL + k0 + q8);
            if (isV)
                cp16(db + A_LO + dsw, g_xl + (size_t)(m0 + row) * DMODEL + k0 + q8);
        }
#pragma unroll
        for (int i = 0; i < 2; i++) {
            int idx = i * 256 + t, row = idx >> 3, q8 = (idx & 7) << 3;
            uint32_t dsw = soff(row, q8) * 2;
            cp16(db + B_HI + dsw, g_wh + (size_t)(n0 + row) * DMODEL + k0 + q8);
            cp16(db + B_LO + dsw, g_wl + (size_t)(n0 + row) * DMODEL + k0 + q8);
        }
    };

    float c[2][4][4] = {};
    cp_slab(0, 0); CP_COMMIT();
    const int S = DMODEL >> 6;
    for (int s = 0; s < S; s++) {
        if (s + 1 < S) { cp_slab((s + 1) & 1, (s + 1) << 6); CP_COMMIT(); CP_WAIT1(); }
        else CP_WAIT0();
        __syncthreads();
        if (isV) mma_slab3(sbase + (s & 1) * BUF3, c, wid, lane);
        else     mma_slab2(sbase + (s & 1) * BUF3, c, wid, lane);
        __syncthreads();
    }

    const int wm = (wid & 3) << 5, wn = (wid >> 2) << 5;
    const int r4 = lane >> 2, c2 = (lane & 3) << 1;
    const int h = (n0 >> 6) & 7, b = m0 >> 11;
    const int z = b * HEADS + h;
    const int nloc = m0 & (SEQ - 1);

    if (typ == 0) {
        __half* dst = g_q16 + (size_t)z * ZSTRIDE;
#pragma unroll
        for (int mf = 0; mf < 2; mf++)
#pragma unroll
            for (int half = 0; half < 2; half++) {
                const int row = wm + (mf << 4) + (half << 3) + r4;
#pragma unroll
                for (int nf = 0; nf < 4; nf++) {
                    const int d = wn + (nf << 3) + c2;
                    float ox = (c[mf][nf][half * 2 + 0] + bias[n0 + d]) * 0.125f;
                    float oy = (c[mf][nf][half * 2 + 1] + bias[n0 + d + 1]) * 0.125f;
                    *(__half2*)&dst[(size_t)(nloc + row) * HDIM + d] = __floats2half2_rn(ox, oy);
                }
            }
    } else if (typ == 1) {
        __half* dst = g_k16 + (size_t)z * ZSTRIDE;
        __half* th = (__half*)sm;
#pragma unroll
        for (int mf = 0; mf < 2; mf++)
#pragma unroll
            for (int half = 0; half < 2; half++) {
                const int row = wm + (mf << 4) + (half << 3) + r4;
#pragma unroll
                for (int nf = 0; nf < 4; nf++) {
                    const int d = wn + (nf << 3) + c2;
                    float ox = c[mf][nf][half * 2 + 0] + bias[n0 + d];
                    float oy = c[mf][nf][half * 2 + 1] + bias[n0 + d + 1];
                    __half hx = __float2half_rn(ox), hy = __float2half_rn(oy);
                    *(__half2*)&dst[(size_t)(nloc + row) * HDIM + d] = __halves2half2(hx, hy);
                    th[d * 136 + row]       = hx;
                    th[(d + 1) * 136 + row] = hy;
                }
            }
        __syncthreads();
        __half* kt = g_kt16 + (size_t)z * ZSTRIDE;
#pragma unroll
        for (int i = 0; i < 8; i++) {
            int idx = i * 256 + t, d = idx >> 5, nm = (idx & 31) << 2;
            *(uint2*)&kt[(size_t)d * SEQ + nloc + nm] = *(uint2*)&th[d * 136 + nm];
        }
    } else {
        // V: single fp16, transposed via smem staging
        __half* th = (__half*)sm;
#pragma unroll
        for (int mf = 0; mf < 2; mf++)
#pragma unroll
            for (int half = 0; half < 2; half++) {
                const int row = wm + (mf << 4) + (half << 3) + r4;
#pragma unroll
                for (int nf = 0; nf < 4; nf++) {
                    const int d = wn + (nf << 3) + c2;
                    float ox = c[mf][nf][half * 2 + 0] + bias[n0 + d];
                    float oy = c[mf][nf][half * 2 + 1] + bias[n0 + d + 1];
                    th[d * 136 + row]       = __float2half_rn(ox);
                    th[(d + 1) * 136 + row] = __float2half_rn(oy);
                }
            }
        __syncthreads();
        __half* vh = g_vh16 + (size_t)z * ZSTRIDE;
#pragma unroll
        for (int i = 0; i < 8; i++) {
            int idx = i * 256 + t, d = idx >> 5, nm = (idx & 31) << 2;
            *(uint2*)&vh[(size_t)d * SEQ + nloc + nm] = *(uint2*)&th[d * 136 + nm];
        }
    }
}

// ============================================================================
// gmat: G = K^T K per z (fp16 in, fp32 accum), output split fp16.
// ============================================================================
__global__ __launch_bounds__(256) void gmat_tc()
{
    extern __shared__ char sm[];
    const int t = threadIdx.x, lane = t & 31, wid = t >> 5;
    const int z = blockIdx.x;
    const __half* kt = g_kt16 + (size_t)z * ZSTRIDE;
    const uint32_t sbase = smem_u32(sm);

    auto cp_slab = [&](int bs, int k0) {
        uint32_t db = sbase + bs * 8192;
#pragma unroll
        for (int i = 0; i < 2; i++) {
            int idx = i * 256 + t, row = idx >> 3, q8 = (idx & 7) << 3;
            cp16(db + soff(row, q8) * 2, kt + (size_t)row * SEQ + k0 + q8);
        }
    };

    const int wm = (wid & 3) << 4, wn = (wid >> 2) << 5;
    const int lrow = lane & 15, lhalf = lane >> 4;
    const int bq = lane >> 3, br = lane & 7;
    const int bnq = ((bq >> 1) << 3) + br, bk8 = (bq & 1) << 3;

    float c[4][4] = {};
    cp_slab(0, 0); CP_COMMIT();
    const int S = SEQ >> 6;
    for (int s = 0; s < S; s++) {
        if (s + 1 < S) { cp_slab((s + 1) & 1, (s + 1) << 6); CP_COMMIT(); CP_WAIT1(); }
        else CP_WAIT0();
        __syncthreads();
        uint32_t db = sbase + (s & 1) * 8192;
#pragma unroll
        for (int kk = 0; kk < 64; kk += 16) {
            uint32_t a[4], b2[2][4];
            ldsm_x4(a, db + soff(wm + lrow, kk + (lhalf << 3)) * 2);
#pragma unroll
            for (int np = 0; np < 2; np++)
                ldsm_x4(b2[np], db + soff(wn + (np << 4) + bnq, kk + bk8) * 2);
#pragma unroll
            for (int nf = 0; nf < 4; nf++)
                mma_f16(c[nf], a, &b2[nf >> 1][(nf & 1) << 1]);
        }
        __syncthreads();
    }

    const int r4 = lane >> 2, c2 = (lane & 3) << 1;
    __half* Gh = g_Gh + (size_t)z * HDIM * HDIM;
    __half* Gl = g_Gl + (size_t)z * HDIM * HDIM;
#pragma unroll
    for (int half = 0; half < 2; half++) {
        const int row = wm + (half << 3) + r4;
#pragma unroll
        for (int nf = 0; nf < 4; nf++) {
            const int col = wn + (nf << 3) + c2;
            float vx = c[nf][half * 2 + 0], vy = c[nf][half * 2 + 1];
            __half hx = __float2half_rn(vx), hy = __float2half_rn(vy);
            *(__half2*)&Gh[row * HDIM + col] = __halves2half2(hx, hy);
            __half lx = __float2half_rn(vx - __half2float(hx));
            __half ly = __float2half_rn(vy - __half2float(hy));
            *(__half2*)&Gl[row * HDIM + col] = __halves2half2(lx, ly);
        }
    }
}

// ============================================================================
// pv_fused: sumsq via q^T G q; main loop recomputes S (1 chain), exp -> P,
// P x V single fp16 (1 chain). Epilogue: /sumexp, write split-bf16 attn.
// ============================================================================
__global__ __launch_bounds__(256, 2) void pv_tc()
{
    extern __shared__ char sm[];
    __shared__ float s_inv[128], s_red[128], s_se[128];
    const int t = threadIdx.x, lane = t & 31, wid = t >> 5;
    const int z = blockIdx.z, b = z >> 3, h = z & 7;
    const int m0 = blockIdx.y * 128;
    const __half* q    = g_q16 + (size_t)z * ZSTRIDE;
    const __half* kk16 = g_k16 + (size_t)z * ZSTRIDE;
    const __half* vh   = g_vh16 + (size_t)z * ZSTRIDE;
    const uint32_t sbase = smem_u32(sm);

    const int wm = (wid & 3) << 5, wn = (wid >> 2) << 5;
    const int lrow = lane & 15, lhalf = lane >> 4;
    const int bq = lane >> 3, br = lane & 7;
    const int bnq = ((bq >> 1) << 3) + br, bk8 = (bq & 1) << 3;
    const int r4 = lane >> 2, c2 = (lane & 3) << 1;

    auto cp_slab = [&](int bs, int k0) {
        uint32_t db = sbase + PBUF0 + bs * PBUFSZ;
#pragma unroll
        for (int i = 0; i < 2; i++) {
            int idx = i * 256 + t, row = idx >> 3, q8 = (idx & 7) << 3;
            uint32_t dsw = soff(row, q8) * 2;
            cp16(db + dsw,           kk16 + (size_t)(k0 + row) * HDIM + q8);
            cp16(db + PVH_OFF + dsw, vh + (size_t)row * SEQ + k0 + q8);
        }
    };

    if (t < 128) { s_red[t] = 0.f; s_se[t] = 0.f; }
#pragma unroll
    for (int i = 0; i < 4; i++) {
        int idx = i * 256 + t, row = idx >> 3, q8 = (idx & 7) << 3;
        cp16(sbase + PQ_OFF + soff(row, q8) * 2, q + (size_t)(m0 + row) * HDIM + q8);
    }
#pragma unroll
    for (int i = 0; i < 2; i++) {
        int idx = i * 256 + t, row = idx >> 3, q8 = (idx & 7) << 3;
        uint32_t dsw = soff(row, q8) * 2;
        cp16(sbase + PG_OFF + dsw, g_Gh + (size_t)z * HDIM * HDIM + (size_t)row * HDIM + q8);
        cp16(sbase + PG_LO + dsw,  g_Gl + (size_t)z * HDIM * HDIM + (size_t)row * HDIM + q8);
    }
    cp_slab(0, 0);
    CP_COMMIT(); CP_WAIT0();
    __syncthreads();

    // ---- sumsq via T = Q G (2 chains); sumsq_r = sum T[r,:]*q[r,:] ----
    {
        float ct[2][4][4] = {};
#pragma unroll
        for (int kq = 0; kq < 64; kq += 16) {
            uint32_t a[2][4], bh2[2][4], bl2[2][4];
#pragma unroll
            for (int mf = 0; mf < 2; mf++)
                ldsm_x4(a[mf], sbase + PQ_OFF + soff(wm + (mf << 4) + lrow, kq + (lhalf << 3)) * 2);
#pragma unroll
            for (int np = 0; np < 2; np++) {
                uint32_t o = soff(wn + (np << 4) + bnq, kq + bk8) * 2;
                ldsm_x4(bh2[np], sbase + PG_OFF + o);
                ldsm_x4(bl2[np], sbase + PG_LO + o);
            }
#pragma unroll
            for (int mf = 0; mf < 2; mf++)
#pragma unroll
                for (int nf = 0; nf < 4; nf++) {
                    mma_f16(ct[mf][nf], a[mf], &bh2[nf >> 1][(nf & 1) << 1]);
                    mma_f16(ct[mf][nf], a[mf], &bl2[nf >> 1][(nf & 1) << 1]);
                }
        }
        float ssq[4] = {0.f, 0.f, 0.f, 0.f};
#pragma unroll
        for (int mf = 0; mf < 2; mf++)
#pragma unroll
            for (int half = 0; half < 2; half++) {
                const int row = wm + (mf << 4) + (half << 3) + r4;
#pragma unroll
                for (int nf = 0; nf < 4; nf++) {
                    const int col = wn + (nf << 3) + c2;
                    float2 qf = __half22float2(*(__half2*)(sm + PQ_OFF + soff(row, col) * 2));
                    ssq[mf * 2 + half] += ct[mf][nf][half * 2 + 0] * qf.x
                                        + ct[mf][nf][half * 2 + 1] * qf.y;
                }
            }
#pragma unroll
        for (int j = 0; j < 4; j++) {
            float v = ssq[j];
            v += __shfl_xor_sync(0xffffffffu, v, 1);
            v += __shfl_xor_sync(0xffffffffu, v, 2);
            if ((lane & 3) == 0)
                atomicAdd(&s_red[wm + ((j >> 1) << 4) + ((j & 1) << 3) + r4], v);
        }
    }
    __syncthreads();
    if (t < 128) s_inv[t] = 1.0f / (sqrtf(s_red[t]) + 1e-6f);
    __syncthreads();

    // ---- main loop ----
    float c_pv[2][4][4] = {};
    float se[4] = {0.f, 0.f, 0.f, 0.f};
    const int S = SEQ >> 6;
    for (int s = 0; s < S; s++) {
        if (s + 1 < S) { cp_slab((s + 1) & 1, (s + 1) << 6); CP_COMMIT(); }
        uint32_t db = sbase + PBUF0 + (s & 1) * PBUFSZ;

        float cs[2][4][4] = {};
#pragma unroll
        for (int kq = 0; kq < 64; kq += 16) {
            uint32_t a[2][4], b2[2][4];
#pragma unroll
            for (int mf = 0; mf < 2; mf++)
                ldsm_x4(a[mf], sbase + PQ_OFF + soff(wm + (mf << 4) + lrow, kq + (lhalf << 3)) * 2);
#pragma unroll
            for (int np = 0; np < 2; np++)
                ldsm_x4(b2[np], db + soff(wn + (np << 4) + bnq, kq + bk8) * 2);
#pragma unroll
            for (int mf = 0; mf < 2; mf++)
#pragma unroll
                for (int nf = 0; nf < 4; nf++)
                    mma_f16(cs[mf][nf], a[mf], &b2[nf >> 1][(nf & 1) << 1]);
        }
#pragma unroll
        for (int mf = 0; mf < 2; mf++)
#pragma unroll
            for (int half = 0; half < 2; half++) {
                const int row = wm + (mf << 4) + (half << 3) + r4;
                const float inv = s_inv[row];
#pragma unroll
                for (int nf = 0; nf < 4; nf++) {
                    float ex = __expf(cs[mf][nf][half * 2 + 0] * inv);
                    float ey = __expf(cs[mf][nf][half * 2 + 1] * inv);
                    se[mf * 2 + half] += ex + ey;
                    *(__half2*)(sm + PG_OFF + soff(row, wn + (nf << 3) + c2) * 2)
                        = __floats2half2_rn(ex, ey);
                }
            }
        __syncthreads();
#pragma unroll
        for (int kq = 0; kq < 64; kq += 16) {
            uint32_t a[2][4], bh2[2][4];
#pragma unroll
            for (int mf = 0; mf < 2; mf++)
                ldsm_x4(a[mf], sbase + PG_OFF + soff(wm + (mf << 4) + lrow, kq + (lhalf << 3)) * 2);
#pragma unroll
            for (int np = 0; np < 2; np++)
                ldsm_x4(bh2[np], db + PVH_OFF + soff(wn + (np << 4) + bnq, kq + bk8) * 2);
#pragma unroll
            for (int mf = 0; mf < 2; mf++)
#pragma unroll
                for (int nf = 0; nf < 4; nf++)
                    mma_f16(c_pv[mf][nf], a[mf], &bh2[nf >> 1][(nf & 1) << 1]);
        }
        if (s + 1 < S) CP_WAIT0();
        __syncthreads();
    }

    // ---- sumexp reduce + epilogue ----
#pragma unroll
    for (int j = 0; j < 4; j++) {
        float v = se[j];
        v += __shfl_xor_sync(0xffffffffu, v, 1);
        v += __shfl_xor_sync(0xffffffffu, v, 2);
        if ((lane & 3) == 0)
            atomicAdd(&s_se[wm + ((j >> 1) << 4) + ((j & 1) << 3) + r4], v);
    }
    __syncthreads();

#pragma unroll
    for (int mf = 0; mf < 2; mf++)
#pragma unroll
        for (int half = 0; half < 2; half++) {
            const int rl = wm + (mf << 4) + (half << 3) + r4;
            const float rse = 1.0f / s_se[rl];
            const size_t gr = (size_t)(b * SEQ + m0 + rl) * DMODEL;
#pragma unroll
            for (int nf = 0; nf < 4; nf++) {
                const int gc = h * HDIM + wn + (nf << 3) + c2;
                float ox = c_pv[mf][nf][half * 2 + 0] * rse;
                float oy = c_pv[mf][nf][half * 2 + 1] * rse;
                __nv_bfloat162 hh = __floats2bfloat162_rn(ox, oy);
                __nv_bfloat162 ll = __floats2bfloat162_rn(ox - __low2float(hh),
                                                          oy - __high2float(hh));
                *(uint32_t*)&g_ah[gr + gc] = *(uint32_t*)&hh;
                *(uint32_t*)&g_al[gr + gc] = *(uint32_t*)&ll;
            }
        }
}

// ============================================================================
// Final projection: attn (split bf16) @ proj_w^T (split bf16) + bias -> fp32.
// ============================================================================
__global__ __launch_bounds__(256, 2) void proj_tc(float* __restrict__ out,
                                                  const float* __restrict__ bias)
{
    extern __shared__ char sm[];
    const int t = threadIdx.x, lane = t & 31, wid = t >> 5;
    const int m0 = blockIdx.y * 128, n0 = blockIdx.x * 64;
    const uint32_t sbase = smem_u32(sm);

    auto cp_slab = [&](int bs, int k0) {
        uint32_t db = sbase + bs * BUF3;
#pragma unroll
        for (int i = 0; i < 4; i++) {
            int idx = i * 256 + t, row = idx >> 3, q8 = (idx & 7) << 3;
            uint32_t dsw = soff(row, q8) * 2;
            cp16(db + A_HI + dsw, g_ah + (size_t)(m0 + row) * DMODEL + k0 + q8);
            cp16(db + A_LO + dsw, g_al + (size_t)(m0 + row) * DMODEL + k0 + q8);
        }
#pragma unroll
        for (int i = 0; i < 2; i++) {
            int idx = i * 256 + t, row = idx >> 3, q8 = (idx & 7) << 3;
            uint32_t dsw = soff(row, q8) * 2;
            cp16(db + B_HI + dsw, g_pwh + (size_t)(n0 + row) * DMODEL + k0 + q8);
            cp16(db + B_LO + dsw, g_pwl + (size_t)(n0 + row) * DMODEL + k0 + q8);
        }
    };

    float c[2][4][4] = {};
    cp_slab(0, 0); CP_COMMIT();
    const int S = DMODEL >> 6;
    for (int s = 0; s < S; s++) {
        if (s + 1 < S) { cp_slab((s + 1) & 1, (s + 1) << 6); CP_COMMIT(); CP_WAIT1(); }
        else CP_WAIT0();
        __syncthreads();
        mma_slab3(sbase + (s & 1) * BUF3, c, wid, lane);
        __syncthreads();
    }

    const int wm = (wid & 3) << 5, wn = (wid >> 2) << 5;
    const int r4 = lane >> 2, c2 = (lane & 3) << 1;
#pragma unroll
    for (int mf = 0; mf < 2; mf++)
#pragma unroll
        for (int half = 0; half < 2; half++) {
            const int row = m0 + wm + (mf << 4) + (half << 3) + r4;
#pragma unroll
            for (int nf = 0; nf < 4; nf++) {
                const int col = n0 + wn + (nf << 3) + c2;
                float2 o;
                o.x = c[mf][nf][half * 2 + 0] + bias[col];
                o.y = c[mf][nf][half * 2 + 1] + bias[col + 1];
                *(float2*)&out[(size_t)row * DMODEL + col] = o;
            }
        }
}

// ---------------------------------------------------------------------------
extern "C" void kernel_launch(void* const* d_in, const int* in_sizes, int n_in,
                              void* d_out, int out_size)
{
    const float* x      = (const float*)d_in[0];
    const float* qkv_w  = (const float*)d_in[1];
    const float* qkv_b  = (const float*)d_in[2];
    const float* proj_w = (const float*)d_in[3];
    const float* proj_b = (const float*)d_in[4];
    float* out = (float*)d_out;

    cudaFuncSetAttribute(qkv_tc, cudaFuncAttributeMaxDynamicSharedMemorySize, 2 * BUF3);
    cudaFuncSetAttribute(gmat_tc, cudaFuncAttributeMaxDynamicSharedMemorySize, 16384);
    cudaFuncSetAttribute(pv_tc, cudaFuncAttributeMaxDynamicSharedMemorySize, PV_SMEM);
    cudaFuncSetAttribute(proj_tc, cudaFuncAttributeMaxDynamicSharedMemorySize, 2 * BUF3);

    // 0) pre-split fp32 inputs into bf16 hi/lo (single fused launch)
    presplit_all<<<(NX_F4 + NW_F4 + NP_F4) / 256, 256>>>(
        (const float4*)x, (const float4*)qkv_w, (const float4*)proj_w);

    // 1) QKV projection -> fp16 Q / K / K^T, fp16 V^T
    qkv_tc<<<dim3(QKVDIM / 64, (BATCH * SEQ) / 128), 256, 2 * BUF3>>>(qkv_b);

    // 2) Gram matrices G = K^T K
    gmat_tc<<<16, 256, 16384>>>();

    // 3) fused norm+softmax+attention
    pv_tc<<<dim3(1, SEQ / 128, ZTOT), 256, PV_SMEM>>>();

    // 4) final projection
    proj_tc<<<dim3(DMODEL / 64, (BATCH * SEQ) / 128), 256, 2 * BUF3>>>(out, proj_b);
}

// round 15
// speedup vs baseline: 5.9048x; 1.0140x over previous
#include <cuda_runtime.h>
#include <cuda_bf16.h>
#include <cuda_fp16.h>
#include <math.h>
#include <stdint.h>

// Problem constants: B=2, N=2048, D=512, H=8, hd=64
#define BATCH 2
#define SEQ   2048
#define DMODEL 512
#define HEADS 8
#define HDIM  64
#define QKVDIM 1536
#define ZTOT  (BATCH * HEADS)        // 16
#define ZSTRIDE ((size_t)SEQ * HDIM) // 131072

// ---------------- scratch (no cudaMalloc -> __device__ globals) ----------------
__device__ __nv_bfloat16 g_xh[(size_t)BATCH * SEQ * DMODEL], g_xl[(size_t)BATCH * SEQ * DMODEL];
__device__ __nv_bfloat16 g_wh[(size_t)QKVDIM * DMODEL],      g_wl[(size_t)QKVDIM * DMODEL];
__device__ __nv_bfloat16 g_pwh[(size_t)DMODEL * DMODEL],     g_pwl[(size_t)DMODEL * DMODEL];
__device__ __half g_q16[(size_t)ZTOT * SEQ * HDIM];           // Q, pre-scaled x0.125
__device__ __half g_k16[(size_t)ZTOT * SEQ * HDIM];           // K row-major
__device__ __half g_kt16[(size_t)ZTOT * HDIM * SEQ];          // K transposed [z][d][n]
__device__ __half g_vh16[(size_t)ZTOT * HDIM * SEQ];          // V transposed, single fp16
__device__ __half g_Gh[(size_t)ZTOT * HDIM * HDIM], g_Gl[(size_t)ZTOT * HDIM * HDIM];
__device__ __nv_bfloat16 g_ah[(size_t)BATCH * SEQ * DMODEL], g_al[(size_t)BATCH * SEQ * DMODEL];

// ---------------- smem: stride-64 rows, XOR swizzle on 16B units ----------------
__device__ __forceinline__ uint32_t soff(int row, int k) {
    int u = ((k >> 3) ^ row) & 7;
    return (uint32_t)((row << 6) + (u << 3) + (k & 7));
}
__device__ __forceinline__ uint32_t smem_u32(const void* p) {
    uint32_t a;
    asm("{ .reg .u64 t; cvta.to.shared.u64 t, %1; cvt.u32.u64 %0, t; }" : "=r"(a) : "l"(p));
    return a;
}
__device__ __forceinline__ void ldsm_x4(uint32_t* r, uint32_t addr) {
    asm volatile("ldmatrix.sync.aligned.m8n8.x4.shared.b16 {%0,%1,%2,%3}, [%4];"
        : "=r"(r[0]), "=r"(r[1]), "=r"(r[2]), "=r"(r[3]) : "r"(addr));
}
__device__ __forceinline__ void mma_bf16(float* c, const uint32_t* a, const uint32_t* b) {
    asm volatile("mma.sync.aligned.m16n8k16.row.col.f32.bf16.bf16.f32 "
        "{%0,%1,%2,%3}, {%4,%5,%6,%7}, {%8,%9}, {%0,%1,%2,%3};"
        : "+f"(c[0]), "+f"(c[1]), "+f"(c[2]), "+f"(c[3])
        : "r"(a[0]), "r"(a[1]), "r"(a[2]), "r"(a[3]), "r"(b[0]), "r"(b[1]));
}
__device__ __forceinline__ void mma_f16(float* c, const uint32_t* a, const uint32_t* b) {
    asm volatile("mma.sync.aligned.m16n8k16.row.col.f32.f16.f16.f32 "
        "{%0,%1,%2,%3}, {%4,%5,%6,%7}, {%8,%9}, {%0,%1,%2,%3};"
        : "+f"(c[0]), "+f"(c[1]), "+f"(c[2]), "+f"(c[3])
        : "r"(a[0]), "r"(a[1]), "r"(a[2]), "r"(a[3]), "r"(b[0]), "r"(b[1]));
}
__device__ __forceinline__ void cp16(uint32_t dst, const void* src) {
    asm volatile("cp.async.cg.shared.global [%0], [%1], 16;" :: "r"(dst), "l"(src));
}
#define CP_COMMIT() asm volatile("cp.async.commit_group;" ::: "memory")
#define CP_WAIT0()  asm volatile("cp.async.wait_group 0;" ::: "memory")
#define CP_WAIT1()  asm volatile("cp.async.wait_group 1;" ::: "memory")

// bf16 GEMM buffers (qkv, proj)
#define A_HI 0
#define A_LO 16384
#define B_HI 32768
#define B_LO 40960
#define BUF3 49152
// pv layout: Q (16KB) | G-hi(8K)+P(16K, reuses G space) | G-lo | 2 slab bufs (K 8K + VH 8K)
#define PQ_OFF 0
#define PG_OFF 16384
#define PG_LO  24576
#define PBUF0  32768
#define PVH_OFF 8192
#define PBUFSZ 16384
#define PV_SMEM (PBUF0 + 2 * PBUFSZ)   // 65536

// ---------------- slab MMA variants (warp grid 4x2, warp tile 32x32) ----------------
// 3-chain split bf16 (A hi/lo x B hi/lo, drop lo*lo)
__device__ __forceinline__ void mma_slab3(uint32_t sbase, float c[2][4][4], int wid, int lane) {
    const int wm = (wid & 3) << 5, wn = (wid >> 2) << 5;
    const int lrow = lane & 15, lhalf = lane >> 4;
    const int bq = lane >> 3, br = lane & 7;
    const int bnq = ((bq >> 1) << 3) + br, bk8 = (bq & 1) << 3;
#pragma unroll
    for (int kk = 0; kk < 64; kk += 16) {
        uint32_t ah[2][4], al[2][4], bh[2][4], bl[2][4];
#pragma unroll
        for (int mf = 0; mf < 2; mf++) {
            uint32_t o = soff(wm + (mf << 4) + lrow, kk + (lhalf << 3)) * 2;
            ldsm_x4(ah[mf], sbase + A_HI + o);
            ldsm_x4(al[mf], sbase + A_LO + o);
        }
#pragma unroll
        for (int np = 0; np < 2; np++) {
            uint32_t o = soff(wn + (np << 4) + bnq, kk + bk8) * 2;
            ldsm_x4(bh[np], sbase + B_HI + o);
            ldsm_x4(bl[np], sbase + B_LO + o);
        }
#pragma unroll
        for (int mf = 0; mf < 2; mf++)
#pragma unroll
            for (int nf = 0; nf < 4; nf++) {
                const uint32_t* bhp = &bh[nf >> 1][(nf & 1) << 1];
                const uint32_t* blp = &bl[nf >> 1][(nf & 1) << 1];
                mma_bf16(c[mf][nf], ah[mf], bhp);
                mma_bf16(c[mf][nf], ah[mf], blp);
                mma_bf16(c[mf][nf], al[mf], bhp);
            }
    }
}
// 1-chain: A hi x B hi (Q/K blocks of qkv — error suppressed by self-normalized softmax)
__device__ __forceinline__ void mma_slab1b(uint32_t sbase, float c[2][4][4], int wid, int lane) {
    const int wm = (wid & 3) << 5, wn = (wid >> 2) << 5;
    const int lrow = lane & 15, lhalf = lane >> 4;
    const int bq = lane >> 3, br = lane & 7;
    const int bnq = ((bq >> 1) << 3) + br, bk8 = (bq & 1) << 3;
#pragma unroll
    for (int kk = 0; kk < 64; kk += 16) {
        uint32_t ah[2][4], bh[2][4];
#pragma unroll
        for (int mf = 0; mf < 2; mf++)
            ldsm_x4(ah[mf], sbase + A_HI + soff(wm + (mf << 4) + lrow, kk + (lhalf << 3)) * 2);
#pragma unroll
        for (int np = 0; np < 2; np++)
            ldsm_x4(bh[np], sbase + B_HI + soff(wn + (np << 4) + bnq, kk + bk8) * 2);
#pragma unroll
        for (int mf = 0; mf < 2; mf++)
#pragma unroll
            for (int nf = 0; nf < 4; nf++)
                mma_bf16(c[mf][nf], ah[mf], &bh[nf >> 1][(nf & 1) << 1]);
    }
}

// ============================================================================
// presplit_all: fp32 -> bf16 hi/lo for x, qkv_w, proj_w in one launch.
// ============================================================================
#define NX_F4 ((BATCH * SEQ * DMODEL) / 4)      // 524288
#define NW_F4 ((QKVDIM * DMODEL) / 4)           // 196608
#define NP_F4 ((DMODEL * DMODEL) / 4)           // 65536
__global__ void presplit_all(const float4* __restrict__ x, const float4* __restrict__ w,
                             const float4* __restrict__ pw)
{
    int i = blockIdx.x * 256 + threadIdx.x;
    const float4* src;
    __nv_bfloat16 *hi, *lo;
    int j = i;
    if (i < NX_F4)                  { src = x;  hi = g_xh;  lo = g_xl; }
    else if (i < NX_F4 + NW_F4)     { src = w;  hi = g_wh;  lo = g_wl;  j = i - NX_F4; }
    else                            { src = pw; hi = g_pwh; lo = g_pwl; j = i - NX_F4 - NW_F4; }
    float4 v = src[j];
    __nv_bfloat162 h0 = __floats2bfloat162_rn(v.x, v.y);
    __nv_bfloat162 h1 = __floats2bfloat162_rn(v.z, v.w);
    __nv_bfloat162 l0 = __floats2bfloat162_rn(v.x - __low2float(h0), v.y - __high2float(h0));
    __nv_bfloat162 l1 = __floats2bfloat162_rn(v.z - __low2float(h1), v.w - __high2float(h1));
    uint2 hu, lu;
    hu.x = *(uint32_t*)&h0; hu.y = *(uint32_t*)&h1;
    lu.x = *(uint32_t*)&l0; lu.y = *(uint32_t*)&l1;
    *(uint2*)(hi + 4 * (size_t)j) = hu;
    *(uint2*)(lo + 4 * (size_t)j) = lu;
}

// ============================================================================
// QKV projection. Q/K column-blocks: 1-chain (hi x hi). V blocks: 3-chain.
// Epilogue: Q fp16 (x0.125); K fp16 + K^T; V single fp16 transposed.
// ============================================================================
__global__ __launch_bounds__(256, 2) void qkv_tc(const float* __restrict__ bias)
{
    extern __shared__ char sm[];
    const int t = threadIdx.x, lane = t & 31, wid = t >> 5;
    const int m0 = blockIdx.y * 128, n0 = blockIdx.x * 64;
    const uint32_t sbase = smem_u32(sm);
    const int typ = n0 >> 9;          // 0=q 1=k 2=v
    const bool isV = (typ == 2);

    auto cp_slab = [&](int bs, int k0) {
        uint32_t db = sbase + bs * BUF3;
#pragma unroll
        for (int i = 0; i < 4; i++) {
            int idx = i * 256 + t, row = idx >> 3, q8 = (idx & 7) << 3;
            uint32_t dsw = soff(row, q8) * 2;
            cp16(db + A_HI + dsw, g_xh + (size_t)(m0 + row) * DMODEL + k0 + q8);
            if (isV)
                cp16(db + A_LO + dsw, g_xl + (size_t)(m0 + row) * DMODEL + k0 + q8);
        }
#pragma unroll
        for (int i = 0; i < 2; i++) {
            int idx = i * 256 + t, row = idx >> 3, q8 = (idx & 7) << 3;
            uint32_t dsw = soff(row, q8) * 2;
            cp16(db + B_HI + dsw, g_wh + (size_t)(n0 + row) * DMODEL + k0 + q8);
            if (isV)
                cp16(db + B_LO + dsw, g_wl + (size_t)(n0 + row) * DMODEL + k0 + q8);
        }
    };

    float c[2][4][4] = {};
    cp_slab(0, 0); CP_COMMIT();
    const int S = DMODEL >> 6;
    for (int s = 0; s < S; s++) {
        if (s + 1 < S) { cp_slab((s + 1) & 1, (s + 1) << 6); CP_COMMIT(); CP_WAIT1(); }
        else CP_WAIT0();
        __syncthreads();
        if (isV) mma_slab3(sbase + (s & 1) * BUF3, c, wid, lane);
        else     mma_slab1b(sbase + (s & 1) * BUF3, c, wid, lane);
        __syncthreads();
    }

    const int wm = (wid & 3) << 5, wn = (wid >> 2) << 5;
    const int r4 = lane >> 2, c2 = (lane & 3) << 1;
    const int h = (n0 >> 6) & 7, b = m0 >> 11;
    const int z = b * HEADS + h;
    const int nloc = m0 & (SEQ - 1);

    if (typ == 0) {
        __half* dst = g_q16 + (size_t)z * ZSTRIDE;
#pragma unroll
        for (int mf = 0; mf < 2; mf++)
#pragma unroll
            for (int half = 0; half < 2; half++) {
                const int row = wm + (mf << 4) + (half << 3) + r4;
#pragma unroll
                for (int nf = 0; nf < 4; nf++) {
                    const int d = wn + (nf << 3) + c2;
                    float ox = (c[mf][nf][half * 2 + 0] + bias[n0 + d]) * 0.125f;
                    float oy = (c[mf][nf][half * 2 + 1] + bias[n0 + d + 1]) * 0.125f;
                    *(__half2*)&dst[(size_t)(nloc + row) * HDIM + d] = __floats2half2_rn(ox, oy);
                }
            }
    } else if (typ == 1) {
        __half* dst = g_k16 + (size_t)z * ZSTRIDE;
        __half* th = (__half*)sm;
#pragma unroll
        for (int mf = 0; mf < 2; mf++)
#pragma unroll
            for (int half = 0; half < 2; half++) {
                const int row = wm + (mf << 4) + (half << 3) + r4;
#pragma unroll
                for (int nf = 0; nf < 4; nf++) {
                    const int d = wn + (nf << 3) + c2;
                    float ox = c[mf][nf][half * 2 + 0] + bias[n0 + d];
                    float oy = c[mf][nf][half * 2 + 1] + bias[n0 + d + 1];
                    __half hx = __float2half_rn(ox), hy = __float2half_rn(oy);
                    *(__half2*)&dst[(size_t)(nloc + row) * HDIM + d] = __halves2half2(hx, hy);
                    th[d * 136 + row]       = hx;
                    th[(d + 1) * 136 + row] = hy;
                }
            }
        __syncthreads();
        __half* kt = g_kt16 + (size_t)z * ZSTRIDE;
#pragma unroll
        for (int i = 0; i < 8; i++) {
            int idx = i * 256 + t, d = idx >> 5, nm = (idx & 31) << 2;
            *(uint2*)&kt[(size_t)d * SEQ + nloc + nm] = *(uint2*)&th[d * 136 + nm];
        }
    } else {
        // V: single fp16, transposed via smem staging
        __half* th = (__half*)sm;
#pragma unroll
        for (int mf = 0; mf < 2; mf++)
#pragma unroll
            for (int half = 0; half < 2; half++) {
                const int row = wm + (mf << 4) + (half << 3) + r4;
#pragma unroll
                for (int nf = 0; nf < 4; nf++) {
                    const int d = wn + (nf << 3) + c2;
                    float ox = c[mf][nf][half * 2 + 0] + bias[n0 + d];
                    float oy = c[mf][nf][half * 2 + 1] + bias[n0 + d + 1];
                    th[d * 136 + row]       = __float2half_rn(ox);
                    th[(d + 1) * 136 + row] = __float2half_rn(oy);
                }
            }
        __syncthreads();
        __half* vh = g_vh16 + (size_t)z * ZSTRIDE;
#pragma unroll
        for (int i = 0; i < 8; i++) {
            int idx = i * 256 + t, d = idx >> 5, nm = (idx & 31) << 2;
            *(uint2*)&vh[(size_t)d * SEQ + nloc + nm] = *(uint2*)&th[d * 136 + nm];
        }
    }
}

// ============================================================================
// gmat: G = K^T K per z (fp16 in, fp32 accum), output split fp16.
// ============================================================================
__global__ __launch_bounds__(256) void gmat_tc()
{
    extern __shared__ char sm[];
    const int t = threadIdx.x, lane = t & 31, wid = t >> 5;
    const int z = blockIdx.x;
    const __half* kt = g_kt16 + (size_t)z * ZSTRIDE;
    const uint32_t sbase = smem_u32(sm);

    auto cp_slab = [&](int bs, int k0) {
        uint32_t db = sbase + bs * 8192;
#pragma unroll
        for (int i = 0; i < 2; i++) {
            int idx = i * 256 + t, row = idx >> 3, q8 = (idx & 7) << 3;
            cp16(db + soff(row, q8) * 2, kt + (size_t)row * SEQ + k0 + q8);
        }
    };

    const int wm = (wid & 3) << 4, wn = (wid >> 2) << 5;
    const int lrow = lane & 15, lhalf = lane >> 4;
    const int bq = lane >> 3, br = lane & 7;
    const int bnq = ((bq >> 1) << 3) + br, bk8 = (bq & 1) << 3;

    float c[4][4] = {};
    cp_slab(0, 0); CP_COMMIT();
    const int S = SEQ >> 6;
    for (int s = 0; s < S; s++) {
        if (s + 1 < S) { cp_slab((s + 1) & 1, (s + 1) << 6); CP_COMMIT(); CP_WAIT1(); }
        else CP_WAIT0();
        __syncthreads();
        uint32_t db = sbase + (s & 1) * 8192;
#pragma unroll
        for (int kk = 0; kk < 64; kk += 16) {
            uint32_t a[4], b2[2][4];
            ldsm_x4(a, db + soff(wm + lrow, kk + (lhalf << 3)) * 2);
#pragma unroll
            for (int np = 0; np < 2; np++)
                ldsm_x4(b2[np], db + soff(wn + (np << 4) + bnq, kk + bk8) * 2);
#pragma unroll
            for (int nf = 0; nf < 4; nf++)
                mma_f16(c[nf], a, &b2[nf >> 1][(nf & 1) << 1]);
        }
        __syncthreads();
    }

    const int r4 = lane >> 2, c2 = (lane & 3) << 1;
    __half* Gh = g_Gh + (size_t)z * HDIM * HDIM;
    __half* Gl = g_Gl + (size_t)z * HDIM * HDIM;
#pragma unroll
    for (int half = 0; half < 2; half++) {
        const int row = wm + (half << 3) + r4;
#pragma unroll
        for (int nf = 0; nf < 4; nf++) {
            const int col = wn + (nf << 3) + c2;
            float vx = c[nf][half * 2 + 0], vy = c[nf][half * 2 + 1];
            __half hx = __float2half_rn(vx), hy = __float2half_rn(vy);
            *(__half2*)&Gh[row * HDIM + col] = __halves2half2(hx, hy);
            __half lx = __float2half_rn(vx - __half2float(hx));
            __half ly = __float2half_rn(vy - __half2float(hy));
            *(__half2*)&Gl[row * HDIM + col] = __halves2half2(lx, ly);
        }
    }
}

// ============================================================================
// pv_fused: sumsq via q^T G q; main loop recomputes S (Q frags in REGISTERS),
// exp -> P smem, P x V (1 chain) + P x ones MMA for sumexp (no reductions).
// Epilogue: /sumexp, write split-bf16 attn.
// ============================================================================
__global__ __launch_bounds__(256, 2) void pv_tc()
{
    extern __shared__ char sm[];
    __shared__ float s_inv[128], s_red[128];
    const int t = threadIdx.x, lane = t & 31, wid = t >> 5;
    const int z = blockIdx.z, b = z >> 3, h = z & 7;
    const int m0 = blockIdx.y * 128;
    const __half* q    = g_q16 + (size_t)z * ZSTRIDE;
    const __half* kk16 = g_k16 + (size_t)z * ZSTRIDE;
    const __half* vh   = g_vh16 + (size_t)z * ZSTRIDE;
    const uint32_t sbase = smem_u32(sm);

    const int wm = (wid & 3) << 5, wn = (wid >> 2) << 5;
    const int lrow = lane & 15, lhalf = lane >> 4;
    const int bq = lane >> 3, br = lane & 7;
    const int bnq = ((bq >> 1) << 3) + br, bk8 = (bq & 1) << 3;
    const int r4 = lane >> 2, c2 = (lane & 3) << 1;

    auto cp_slab = [&](int bs, int k0) {
        uint32_t db = sbase + PBUF0 + bs * PBUFSZ;
#pragma unroll
        for (int i = 0; i < 2; i++) {
            int idx = i * 256 + t, row = idx >> 3, q8 = (idx & 7) << 3;
            uint32_t dsw = soff(row, q8) * 2;
            cp16(db + dsw,           kk16 + (size_t)(k0 + row) * HDIM + q8);
            cp16(db + PVH_OFF + dsw, vh + (size_t)row * SEQ + k0 + q8);
        }
    };

    if (t < 128) s_red[t] = 0.f;
#pragma unroll
    for (int i = 0; i < 4; i++) {
        int idx = i * 256 + t, row = idx >> 3, q8 = (idx & 7) << 3;
        cp16(sbase + PQ_OFF + soff(row, q8) * 2, q + (size_t)(m0 + row) * HDIM + q8);
    }
#pragma unroll
    for (int i = 0; i < 2; i++) {
        int idx = i * 256 + t, row = idx >> 3, q8 = (idx & 7) << 3;
        uint32_t dsw = soff(row, q8) * 2;
        cp16(sbase + PG_OFF + dsw, g_Gh + (size_t)z * HDIM * HDIM + (size_t)row * HDIM + q8);
        cp16(sbase + PG_LO + dsw,  g_Gl + (size_t)z * HDIM * HDIM + (size_t)row * HDIM + q8);
    }
    cp_slab(0, 0);
    CP_COMMIT(); CP_WAIT0();
    __syncthreads();

    // ---- Q fragments -> registers (persistent across all slabs) ----
    uint32_t qf[4][2][4];
#pragma unroll
    for (int kq4 = 0; kq4 < 4; kq4++)
#pragma unroll
        for (int mf = 0; mf < 2; mf++)
            ldsm_x4(qf[kq4][mf],
                    sbase + PQ_OFF + soff(wm + (mf << 4) + lrow, (kq4 << 4) + (lhalf << 3)) * 2);

    // ---- sumsq via T = Q G (2 chains); sumsq_r = sum T[r,:]*q[r,:] ----
    {
        float ct[2][4][4] = {};
#pragma unroll
        for (int kq4 = 0; kq4 < 4; kq4++) {
            uint32_t bh2[2][4], bl2[2][4];
#pragma unroll
            for (int np = 0; np < 2; np++) {
                uint32_t o = soff(wn + (np << 4) + bnq, (kq4 << 4) + bk8) * 2;
                ldsm_x4(bh2[np], sbase + PG_OFF + o);
                ldsm_x4(bl2[np], sbase + PG_LO + o);
            }
#pragma unroll
            for (int mf = 0; mf < 2; mf++)
#pragma unroll
                for (int nf = 0; nf < 4; nf++) {
                    mma_f16(ct[mf][nf], qf[kq4][mf], &bh2[nf >> 1][(nf & 1) << 1]);
                    mma_f16(ct[mf][nf], qf[kq4][mf], &bl2[nf >> 1][(nf & 1) << 1]);
                }
        }
        float ssq[4] = {0.f, 0.f, 0.f, 0.f};
#pragma unroll
        for (int mf = 0; mf < 2; mf++)
#pragma unroll
            for (int half = 0; half < 2; half++) {
                const int row = wm + (mf << 4) + (half << 3) + r4;
#pragma unroll
                for (int nf = 0; nf < 4; nf++) {
                    const int col = wn + (nf << 3) + c2;
                    float2 qv = __half22float2(*(__half2*)(sm + PQ_OFF + soff(row, col) * 2));
                    ssq[mf * 2 + half] += ct[mf][nf][half * 2 + 0] * qv.x
                                        + ct[mf][nf][half * 2 + 1] * qv.y;
                }
            }
#pragma unroll
        for (int j = 0; j < 4; j++) {
            float v = ssq[j];
            v += __shfl_xor_sync(0xffffffffu, v, 1);
            v += __shfl_xor_sync(0xffffffffu, v, 2);
            if ((lane & 3) == 0)
                atomicAdd(&s_red[wm + ((j >> 1) << 4) + ((j & 1) << 3) + r4], v);
        }
    }
    __syncthreads();
    if (t < 128) s_inv[t] = 1.0f / (sqrtf(s_red[t]) + 1e-6f);
    __syncthreads();

    // ---- main loop ----
    float c_pv[2][4][4] = {};
    float c_se[2][4] = {};                       // sumexp accumulators (P x ones)
    const uint32_t ONES2 = 0x3C003C00u;          // fp16 (1.0, 1.0)
    const uint32_t ones[2] = {ONES2, ONES2};
    const int S = SEQ >> 6;
    for (int s = 0; s < S; s++) {
        if (s + 1 < S) { cp_slab((s + 1) & 1, (s + 1) << 6); CP_COMMIT(); }
        uint32_t db = sbase + PBUF0 + (s & 1) * PBUFSZ;

        float cs[2][4][4] = {};
#pragma unroll
        for (int kq4 = 0; kq4 < 4; kq4++) {
            uint32_t b2[2][4];
#pragma unroll
            for (int np = 0; np < 2; np++)
                ldsm_x4(b2[np], db + soff(wn + (np << 4) + bnq, (kq4 << 4) + bk8) * 2);
#pragma unroll
            for (int mf = 0; mf < 2; mf++)
#pragma unroll
                for (int nf = 0; nf < 4; nf++)
                    mma_f16(cs[mf][nf], qf[kq4][mf], &b2[nf >> 1][(nf & 1) << 1]);
        }
#pragma unroll
        for (int mf = 0; mf < 2; mf++)
#pragma unroll
            for (int half = 0; half < 2; half++) {
                const int row = wm + (mf << 4) + (half << 3) + r4;
                const float inv = s_inv[row];
#pragma unroll
                for (int nf = 0; nf < 4; nf++) {
                    float ex = __expf(cs[mf][nf][half * 2 + 0] * inv);
                    float ey = __expf(cs[mf][nf][half * 2 + 1] * inv);
                    *(__half2*)(sm + PG_OFF + soff(row, wn + (nf << 3) + c2) * 2)
                        = __floats2half2_rn(ex, ey);
                }
            }
        __syncthreads();
#pragma unroll
        for (int kq4 = 0; kq4 < 4; kq4++) {
            uint32_t a[2][4], bh2[2][4];
#pragma unroll
            for (int mf = 0; mf < 2; mf++)
                ldsm_x4(a[mf], sbase + PG_OFF + soff(wm + (mf << 4) + lrow, (kq4 << 4) + (lhalf << 3)) * 2);
#pragma unroll
            for (int np = 0; np < 2; np++)
                ldsm_x4(bh2[np], db + PVH_OFF + soff(wn + (np << 4) + bnq, (kq4 << 4) + bk8) * 2);
#pragma unroll
            for (int mf = 0; mf < 2; mf++) {
#pragma unroll
                for (int nf = 0; nf < 4; nf++)
                    mma_f16(c_pv[mf][nf], a[mf], &bh2[nf >> 1][(nf & 1) << 1]);
                mma_f16(c_se[mf], a[mf], ones);   // row-sum of P -> sumexp
            }
        }
        if (s + 1 < S) CP_WAIT0();
        __syncthreads();
    }

    // ---- epilogue: sumexp already in c_se (cols identical; pick c[half*2]) ----
#pragma unroll
    for (int mf = 0; mf < 2; mf++)
#pragma unroll
        for (int half = 0; half < 2; half++) {
            const int rl = wm + (mf << 4) + (half << 3) + r4;
            const float rse = 1.0f / c_se[mf][half * 2];
            const size_t gr = (size_t)(b * SEQ + m0 + rl) * DMODEL;
#pragma unroll
            for (int nf = 0; nf < 4; nf++) {
                const int gc = h * HDIM + wn + (nf << 3) + c2;
                float ox = c_pv[mf][nf][half * 2 + 0] * rse;
                float oy = c_pv[mf][nf][half * 2 + 1] * rse;
                __nv_bfloat162 hh = __floats2bfloat162_rn(ox, oy);
                __nv_bfloat162 ll = __floats2bfloat162_rn(ox - __low2float(hh),
                                                          oy - __high2float(hh));
                *(uint32_t*)&g_ah[gr + gc] = *(uint32_t*)&hh;
                *(uint32_t*)&g_al[gr + gc] = *(uint32_t*)&ll;
            }
        }
}

// ============================================================================
// Final projection: attn (split bf16) @ proj_w^T (split bf16) + bias -> fp32.
// ============================================================================
__global__ __launch_bounds__(256, 2) void proj_tc(float* __restrict__ out,
                                                  const float* __restrict__ bias)
{
    extern __shared__ char sm[];
    const int t = threadIdx.x, lane = t & 31, wid = t >> 5;
    const int m0 = blockIdx.y * 128, n0 = blockIdx.x * 64;
    const uint32_t sbase = smem_u32(sm);

    auto cp_slab = [&](int bs, int k0) {
        uint32_t db = sbase + bs * BUF3;
#pragma unroll
        for (int i = 0; i < 4; i++) {
            int idx = i * 256 + t, row = idx >> 3, q8 = (idx & 7) << 3;
            uint32_t dsw = soff(row, q8) * 2;
            cp16(db + A_HI + dsw, g_ah + (size_t)(m0 + row) * DMODEL + k0 + q8);
            cp16(db + A_LO + dsw, g_al + (size_t)(m0 + row) * DMODEL + k0 + q8);
        }
#pragma unroll
        for (int i = 0; i < 2; i++) {
            int idx = i * 256 + t, row = idx >> 3, q8 = (idx & 7) << 3;
            uint32_t dsw = soff(row, q8) * 2;
            cp16(db + B_HI + dsw, g_pwh + (size_t)(n0 + row) * DMODEL + k0 + q8);
            cp16(db + B_LO + dsw, g_pwl + (size_t)(n0 + row) * DMODEL + k0 + q8);
        }
    };

    float c[2][4][4] = {};
    cp_slab(0, 0); CP_COMMIT();
    const int S = DMODEL >> 6;
    for (int s = 0; s < S; s++) {
        if (s + 1 < S) { cp_slab((s + 1) & 1, (s + 1) << 6); CP_COMMIT(); CP_WAIT1(); }
        else CP_WAIT0();
        __syncthreads();
        mma_slab3(sbase + (s & 1) * BUF3, c, wid, lane);
        __syncthreads();
    }

    const int wm = (wid & 3) << 5, wn = (wid >> 2) << 5;
    const int r4 = lane >> 2, c2 = (lane & 3) << 1;
#pragma unroll
    for (int mf = 0; mf < 2; mf++)
#pragma unroll
        for (int half = 0; half < 2; half++) {
            const int row = m0 + wm + (mf << 4) + (half << 3) + r4;
#pragma unroll
            for (int nf = 0; nf < 4; nf++) {
                const int col = n0 + wn + (nf << 3) + c2;
                float2 o;
                o.x = c[mf][nf][half * 2 + 0] + bias[col];
                o.y = c[mf][nf][half * 2 + 1] + bias[col + 1];
                *(float2*)&out[(size_t)row * DMODEL + col] = o;
            }
        }
}

// ---------------------------------------------------------------------------
extern "C" void kernel_launch(void* const* d_in, const int* in_sizes, int n_in,
                              void* d_out, int out_size)
{
    const float* x      = (const float*)d_in[0];
    const float* qkv_w  = (const float*)d_in[1];
    const float* qkv_b  = (const float*)d_in[2];
    const float* proj_w = (const float*)d_in[3];
    const float* proj_b = (const float*)d_in[4];
    float* out = (float*)d_out;

    cudaFuncSetAttribute(qkv_tc, cudaFuncAttributeMaxDynamicSharedMemorySize, 2 * BUF3);
    cudaFuncSetAttribute(gmat_tc, cudaFuncAttributeMaxDynamicSharedMemorySize, 16384);
    cudaFuncSetAttribute(pv_tc, cudaFuncAttributeMaxDynamicSharedMemorySize, PV_SMEM);
    cudaFuncSetAttribute(proj_tc, cudaFuncAttributeMaxDynamicSharedMemorySize, 2 * BUF3);

    // 0) pre-split fp32 inputs into bf16 hi/lo (single fused launch)
    presplit_all<<<(NX_F4 + NW_F4 + NP_F4) / 256, 256>>>(
        (const float4*)x, (const float4*)qkv_w, (const float4*)proj_w);

    // 1) QKV projection -> fp16 Q / K / K^T, fp16 V^T
    qkv_tc<<<dim3(QKVDIM / 64, (BATCH * SEQ) / 128), 256, 2 * BUF3>>>(qkv_b);

    // 2) Gram matrices G = K^T K
    gmat_tc<<<16, 256, 16384>>>();

    // 3) fused norm+softmax+attention
    pv_tc<<<dim3(1, SEQ / 128, ZTOT), 256, PV_SMEM>>>();

    // 4) final projection
    proj_tc<<<dim3(DMODEL / 64, (BATCH * SEQ) / 128), 256, 2 * BUF3>>>(out, proj_b);
}

// round 16
// speedup vs baseline: 6.4793x; 1.0973x over previous
#include <cuda_runtime.h>
#include <cuda_bf16.h>
#include <cuda_fp16.h>
#include <math.h>
#include <stdint.h>

// Problem constants: B=2, N=2048, D=512, H=8, hd=64
#define BATCH 2
#define SEQ   2048
#define DMODEL 512
#define HEADS 8
#define HDIM  64
#define QKVDIM 1536
#define ZTOT  (BATCH * HEADS)        // 16
#define ZSTRIDE ((size_t)SEQ * HDIM) // 131072

// ---------------- scratch (no cudaMalloc -> __device__ globals) ----------------
__device__ __nv_bfloat16 g_xh[(size_t)BATCH * SEQ * DMODEL], g_xl[(size_t)BATCH * SEQ * DMODEL];
__device__ __nv_bfloat16 g_wh[(size_t)QKVDIM * DMODEL],      g_wl[(size_t)QKVDIM * DMODEL];
__device__ __nv_bfloat16 g_pwh[(size_t)DMODEL * DMODEL],     g_pwl[(size_t)DMODEL * DMODEL];
__device__ __half g_q16[(size_t)ZTOT * SEQ * HDIM];           // Q, pre-scaled x0.125
__device__ __half g_k16[(size_t)ZTOT * SEQ * HDIM];           // K row-major
__device__ __half g_kt16[(size_t)ZTOT * HDIM * SEQ];          // K transposed [z][d][n]
__device__ __half g_vh16[(size_t)ZTOT * HDIM * SEQ];          // V transposed, single fp16
__device__ __half g_Gh[(size_t)ZTOT * HDIM * HDIM], g_Gl[(size_t)ZTOT * HDIM * HDIM];
__device__ __nv_bfloat16 g_ah[(size_t)BATCH * SEQ * DMODEL], g_al[(size_t)BATCH * SEQ * DMODEL];

// ---------------- smem: stride-64 rows, XOR swizzle on 16B units ----------------
__device__ __forceinline__ uint32_t soff(int row, int k) {
    int u = ((k >> 3) ^ row) & 7;
    return (uint32_t)((row << 6) + (u << 3) + (k & 7));
}
__device__ __forceinline__ uint32_t smem_u32(const void* p) {
    uint32_t a;
    asm("{ .reg .u64 t; cvta.to.shared.u64 t, %1; cvt.u32.u64 %0, t; }" : "=r"(a) : "l"(p));
    return a;
}
__device__ __forceinline__ void ldsm_x4(uint32_t* r, uint32_t addr) {
    asm volatile("ldmatrix.sync.aligned.m8n8.x4.shared.b16 {%0,%1,%2,%3}, [%4];"
        : "=r"(r[0]), "=r"(r[1]), "=r"(r[2]), "=r"(r[3]) : "r"(addr));
}
__device__ __forceinline__ void mma_bf16(float* c, const uint32_t* a, const uint32_t* b) {
    asm volatile("mma.sync.aligned.m16n8k16.row.col.f32.bf16.bf16.f32 "
        "{%0,%1,%2,%3}, {%4,%5,%6,%7}, {%8,%9}, {%0,%1,%2,%3};"
        : "+f"(c[0]), "+f"(c[1]), "+f"(c[2]), "+f"(c[3])
        : "r"(a[0]), "r"(a[1]), "r"(a[2]), "r"(a[3]), "r"(b[0]), "r"(b[1]));
}
__device__ __forceinline__ void mma_f16(float* c, const uint32_t* a, const uint32_t* b) {
    asm volatile("mma.sync.aligned.m16n8k16.row.col.f32.f16.f16.f32 "
        "{%0,%1,%2,%3}, {%4,%5,%6,%7}, {%8,%9}, {%0,%1,%2,%3};"
        : "+f"(c[0]), "+f"(c[1]), "+f"(c[2]), "+f"(c[3])
        : "r"(a[0]), "r"(a[1]), "r"(a[2]), "r"(a[3]), "r"(b[0]), "r"(b[1]));
}
__device__ __forceinline__ void cp16(uint32_t dst, const void* src) {
    asm volatile("cp.async.cg.shared.global [%0], [%1], 16;" :: "r"(dst), "l"(src));
}
#define CP_COMMIT() asm volatile("cp.async.commit_group;" ::: "memory")
#define CP_WAIT0()  asm volatile("cp.async.wait_group 0;" ::: "memory")
#define CP_WAIT1()  asm volatile("cp.async.wait_group 1;" ::: "memory")

// bf16 GEMM buffers (qkv, proj)
#define A_HI 0
#define A_LO 16384
#define B_HI 32768
#define B_LO 40960
#define BUF3 49152
// pv layout: Q (16KB) | G hi (8K) | G lo (8K) | 2 slab bufs (K 8K + V 8K each)
#define PQ_OFF 0
#define PG_OFF 16384
#define PG_LO  24576
#define PBUF0  32768
#define PVH_OFF 8192
#define PBUFSZ 16384
#define PV_SMEM (PBUF0 + 2 * PBUFSZ)   // 65536

// ---------------- slab MMA variants (warp grid 4x2, warp tile 32x32) ----------------
__device__ __forceinline__ void mma_slab3(uint32_t sbase, float c[2][4][4], int wid, int lane) {
    const int wm = (wid & 3) << 5, wn = (wid >> 2) << 5;
    const int lrow = lane & 15, lhalf = lane >> 4;
    const int bq = lane >> 3, br = lane & 7;
    const int bnq = ((bq >> 1) << 3) + br, bk8 = (bq & 1) << 3;
#pragma unroll
    for (int kk = 0; kk < 64; kk += 16) {
        uint32_t ah[2][4], al[2][4], bh[2][4], bl[2][4];
#pragma unroll
        for (int mf = 0; mf < 2; mf++) {
            uint32_t o = soff(wm + (mf << 4) + lrow, kk + (lhalf << 3)) * 2;
            ldsm_x4(ah[mf], sbase + A_HI + o);
            ldsm_x4(al[mf], sbase + A_LO + o);
        }
#pragma unroll
        for (int np = 0; np < 2; np++) {
            uint32_t o = soff(wn + (np << 4) + bnq, kk + bk8) * 2;
            ldsm_x4(bh[np], sbase + B_HI + o);
            ldsm_x4(bl[np], sbase + B_LO + o);
        }
#pragma unroll
        for (int mf = 0; mf < 2; mf++)
#pragma unroll
            for (int nf = 0; nf < 4; nf++) {
                const uint32_t* bhp = &bh[nf >> 1][(nf & 1) << 1];
                const uint32_t* blp = &bl[nf >> 1][(nf & 1) << 1];
                mma_bf16(c[mf][nf], ah[mf], bhp);
                mma_bf16(c[mf][nf], ah[mf], blp);
                mma_bf16(c[mf][nf], al[mf], bhp);
            }
    }
}
__device__ __forceinline__ void mma_slab1b(uint32_t sbase, float c[2][4][4], int wid, int lane) {
    const int wm = (wid & 3) << 5, wn = (wid >> 2) << 5;
    const int lrow = lane & 15, lhalf = lane >> 4;
    const int bq = lane >> 3, br = lane & 7;
    const int bnq = ((bq >> 1) << 3) + br, bk8 = (bq & 1) << 3;
#pragma unroll
    for (int kk = 0; kk < 64; kk += 16) {
        uint32_t ah[2][4], bh[2][4];
#pragma unroll
        for (int mf = 0; mf < 2; mf++)
            ldsm_x4(ah[mf], sbase + A_HI + soff(wm + (mf << 4) + lrow, kk + (lhalf << 3)) * 2);
#pragma unroll
        for (int np = 0; np < 2; np++)
            ldsm_x4(bh[np], sbase + B_HI + soff(wn + (np << 4) + bnq, kk + bk8) * 2);
#pragma unroll
        for (int mf = 0; mf < 2; mf++)
#pragma unroll
            for (int nf = 0; nf < 4; nf++)
                mma_bf16(c[mf][nf], ah[mf], &bh[nf >> 1][(nf & 1) << 1]);
    }
}

// ============================================================================
// presplit_all
// ============================================================================
#define NX_F4 ((BATCH * SEQ * DMODEL) / 4)
#define NW_F4 ((QKVDIM * DMODEL) / 4)
#define NP_F4 ((DMODEL * DMODEL) / 4)
__global__ void presplit_all(const float4* __restrict__ x, const float4* __restrict__ w,
                             const float4* __restrict__ pw)
{
    int i = blockIdx.x * 256 + threadIdx.x;
    const float4* src;
    __nv_bfloat16 *hi, *lo;
    int j = i;
    if (i < NX_F4)                  { src = x;  hi = g_xh;  lo = g_xl; }
    else if (i < NX_F4 + NW_F4)     { src = w;  hi = g_wh;  lo = g_wl;  j = i - NX_F4; }
    else                            { src = pw; hi = g_pwh; lo = g_pwl; j = i - NX_F4 - NW_F4; }
    float4 v = src[j];
    __nv_bfloat162 h0 = __floats2bfloat162_rn(v.x, v.y);
    __nv_bfloat162 h1 = __floats2bfloat162_rn(v.z, v.w);
    __nv_bfloat162 l0 = __floats2bfloat162_rn(v.x - __low2float(h0), v.y - __high2float(h0));
    __nv_bfloat162 l1 = __floats2bfloat162_rn(v.z - __low2float(h1), v.w - __high2float(h1));
    uint2 hu, lu;
    hu.x = *(uint32_t*)&h0; hu.y = *(uint32_t*)&h1;
    lu.x = *(uint32_t*)&l0; lu.y = *(uint32_t*)&l1;
    *(uint2*)(hi + 4 * (size_t)j) = hu;
    *(uint2*)(lo + 4 * (size_t)j) = lu;
}

// ============================================================================
// QKV projection. Q/K: 1-chain (hi x hi). V: 3-chain.
// ============================================================================
__global__ __launch_bounds__(256, 2) void qkv_tc(const float* __restrict__ bias)
{
    extern __shared__ char sm[];
    const int t = threadIdx.x, lane = t & 31, wid = t >> 5;
    const int m0 = blockIdx.y * 128, n0 = blockIdx.x * 64;
    const uint32_t sbase = smem_u32(sm);
    const int typ = n0 >> 9;
    const bool isV = (typ == 2);

    auto cp_slab = [&](int bs, int k0) {
        uint32_t db = sbase + bs * BUF3;
#pragma unroll
        for (int i = 0; i < 4; i++) {
            int idx = i * 256 + t, row = idx >> 3, q8 = (idx & 7) << 3;
            uint32_t dsw = soff(row, q8) * 2;
            cp16(db + A_HI + dsw, g_xh + (size_t)(m0 + row) * DMODEL + k0 + q8);
            if (isV)
                cp16(db + A_LO + dsw, g_xl + (size_t)(m0 + row) * DMODEL + k0 + q8);
        }
#pragma unroll
        for (int i = 0; i < 2; i++) {
            int idx = i * 256 + t, row = idx >> 3, q8 = (idx & 7) << 3;
            uint32_t dsw = soff(row, q8) * 2;
            cp16(db + B_HI + dsw, g_wh + (size_t)(n0 + row) * DMODEL + k0 + q8);
            if (isV)
                cp16(db + B_LO + dsw, g_wl + (size_t)(n0 + row) * DMODEL + k0 + q8);
        }
    };

    float c[2][4][4] = {};
    cp_slab(0, 0); CP_COMMIT();
    const int S = DMODEL >> 6;
    for (int s = 0; s < S; s++) {
        if (s + 1 < S) { cp_slab((s + 1) & 1, (s + 1) << 6); CP_COMMIT(); CP_WAIT1(); }
        else CP_WAIT0();
        __syncthreads();
        if (isV) mma_slab3(sbase + (s & 1) * BUF3, c, wid, lane);
        else     mma_slab1b(sbase + (s & 1) * BUF3, c, wid, lane);
        __syncthreads();
    }

    const int wm = (wid & 3) << 5, wn = (wid >> 2) << 5;
    const int r4 = lane >> 2, c2 = (lane & 3) << 1;
    const int h = (n0 >> 6) & 7, b = m0 >> 11;
    const int z = b * HEADS + h;
    const int nloc = m0 & (SEQ - 1);

    if (typ == 0) {
        __half* dst = g_q16 + (size_t)z * ZSTRIDE;
#pragma unroll
        for (int mf = 0; mf < 2; mf++)
#pragma unroll
            for (int half = 0; half < 2; half++) {
                const int row = wm + (mf << 4) + (half << 3) + r4;
#pragma unroll
                for (int nf = 0; nf < 4; nf++) {
                    const int d = wn + (nf << 3) + c2;
                    float ox = (c[mf][nf][half * 2 + 0] + bias[n0 + d]) * 0.125f;
                    float oy = (c[mf][nf][half * 2 + 1] + bias[n0 + d + 1]) * 0.125f;
                    *(__half2*)&dst[(size_t)(nloc + row) * HDIM + d] = __floats2half2_rn(ox, oy);
                }
            }
    } else if (typ == 1) {
        __half* dst = g_k16 + (size_t)z * ZSTRIDE;
        __half* th = (__half*)sm;
#pragma unroll
        for (int mf = 0; mf < 2; mf++)
#pragma unroll
            for (int half = 0; half < 2; half++) {
                const int row = wm + (mf << 4) + (half << 3) + r4;
#pragma unroll
                for (int nf = 0; nf < 4; nf++) {
                    const int d = wn + (nf << 3) + c2;
                    float ox = c[mf][nf][half * 2 + 0] + bias[n0 + d];
                    float oy = c[mf][nf][half * 2 + 1] + bias[n0 + d + 1];
                    __half hx = __float2half_rn(ox), hy = __float2half_rn(oy);
                    *(__half2*)&dst[(size_t)(nloc + row) * HDIM + d] = __halves2half2(hx, hy);
                    th[d * 136 + row]       = hx;
                    th[(d + 1) * 136 + row] = hy;
                }
            }
        __syncthreads();
        __half* kt = g_kt16 + (size_t)z * ZSTRIDE;
#pragma unroll
        for (int i = 0; i < 8; i++) {
            int idx = i * 256 + t, d = idx >> 5, nm = (idx & 31) << 2;
            *(uint2*)&kt[(size_t)d * SEQ + nloc + nm] = *(uint2*)&th[d * 136 + nm];
        }
    } else {
        __half* th = (__half*)sm;
#pragma unroll
        for (int mf = 0; mf < 2; mf++)
#pragma unroll
            for (int half = 0; half < 2; half++) {
                const int row = wm + (mf << 4) + (half << 3) + r4;
#pragma unroll
                for (int nf = 0; nf < 4; nf++) {
                    const int d = wn + (nf << 3) + c2;
                    float ox = c[mf][nf][half * 2 + 0] + bias[n0 + d];
                    float oy = c[mf][nf][half * 2 + 1] + bias[n0 + d + 1];
                    th[d * 136 + row]       = __float2half_rn(ox);
                    th[(d + 1) * 136 + row] = __float2half_rn(oy);
                }
            }
        __syncthreads();
        __half* vh = g_vh16 + (size_t)z * ZSTRIDE;
#pragma unroll
        for (int i = 0; i < 8; i++) {
            int idx = i * 256 + t, d = idx >> 5, nm = (idx & 31) << 2;
            *(uint2*)&vh[(size_t)d * SEQ + nloc + nm] = *(uint2*)&th[d * 136 + nm];
        }
    }
}

// ============================================================================
// gmat: G = K^T K per z, output split fp16.
// ============================================================================
__global__ __launch_bounds__(256) void gmat_tc()
{
    extern __shared__ char sm[];
    const int t = threadIdx.x, lane = t & 31, wid = t >> 5;
    const int z = blockIdx.x;
    const __half* kt = g_kt16 + (size_t)z * ZSTRIDE;
    const uint32_t sbase = smem_u32(sm);

    auto cp_slab = [&](int bs, int k0) {
        uint32_t db = sbase + bs * 8192;
#pragma unroll
        for (int i = 0; i < 2; i++) {
            int idx = i * 256 + t, row = idx >> 3, q8 = (idx & 7) << 3;
            cp16(db + soff(row, q8) * 2, kt + (size_t)row * SEQ + k0 + q8);
        }
    };

    const int wm = (wid & 3) << 4, wn = (wid >> 2) << 5;
    const int lrow = lane & 15, lhalf = lane >> 4;
    const int bq = lane >> 3, br = lane & 7;
    const int bnq = ((bq >> 1) << 3) + br, bk8 = (bq & 1) << 3;

    float c[4][4] = {};
    cp_slab(0, 0); CP_COMMIT();
    const int S = SEQ >> 6;
    for (int s = 0; s < S; s++) {
        if (s + 1 < S) { cp_slab((s + 1) & 1, (s + 1) << 6); CP_COMMIT(); CP_WAIT1(); }
        else CP_WAIT0();
        __syncthreads();
        uint32_t db = sbase + (s & 1) * 8192;
#pragma unroll
        for (int kk = 0; kk < 64; kk += 16) {
            uint32_t a[4], b2[2][4];
            ldsm_x4(a, db + soff(wm + lrow, kk + (lhalf << 3)) * 2);
#pragma unroll
            for (int np = 0; np < 2; np++)
                ldsm_x4(b2[np], db + soff(wn + (np << 4) + bnq, kk + bk8) * 2);
#pragma unroll
            for (int nf = 0; nf < 4; nf++)
                mma_f16(c[nf], a, &b2[nf >> 1][(nf & 1) << 1]);
        }
        __syncthreads();
    }

    const int r4 = lane >> 2, c2 = (lane & 3) << 1;
    __half* Gh = g_Gh + (size_t)z * HDIM * HDIM;
    __half* Gl = g_Gl + (size_t)z * HDIM * HDIM;
#pragma unroll
    for (int half = 0; half < 2; half++) {
        const int row = wm + (half << 3) + r4;
#pragma unroll
        for (int nf = 0; nf < 4; nf++) {
            const int col = wn + (nf << 3) + c2;
            float vx = c[nf][half * 2 + 0], vy = c[nf][half * 2 + 1];
            __half hx = __float2half_rn(vx), hy = __float2half_rn(vy);
            *(__half2*)&Gh[row * HDIM + col] = __halves2half2(hx, hy);
            __half lx = __float2half_rn(vx - __half2float(hx));
            __half ly = __float2half_rn(vy - __half2float(hy));
            *(__half2*)&Gl[row * HDIM + col] = __halves2half2(lx, ly);
        }
    }
}

// ============================================================================
// pv_fused (FA2-style): warp owns 16 rows x 64 cols. P stays in registers:
// S C-fragments repack directly into PV A-fragments. One sync per slab.
// sumexp via P x ones MMA. Epilogue: /sumexp, write split-bf16 attn.
// ============================================================================
__global__ __launch_bounds__(256, 2) void pv_tc()
{
    extern __shared__ char sm[];
    __shared__ float s_inv[128], s_red[128];
    const int t = threadIdx.x, lane = t & 31, wid = t >> 5;
    const int z = blockIdx.z, b = z >> 3, h = z & 7;
    const int m0 = blockIdx.y * 128;
    const __half* q    = g_q16 + (size_t)z * ZSTRIDE;
    const __half* kk16 = g_k16 + (size_t)z * ZSTRIDE;
    const __half* vh   = g_vh16 + (size_t)z * ZSTRIDE;
    const uint32_t sbase = smem_u32(sm);

    const int wr0 = wid << 4;                 // warp's 16-row block
    const int lrow = lane & 15, lhalf = lane >> 4;
    const int bq = lane >> 3, br = lane & 7;
    const int bnq = ((bq >> 1) << 3) + br, bk8 = (bq & 1) << 3;
    const int r4 = lane >> 2, c2 = (lane & 3) << 1;

    auto cp_slab = [&](int bs, int k0) {
        uint32_t db = sbase + PBUF0 + bs * PBUFSZ;
#pragma unroll
        for (int i = 0; i < 2; i++) {
            int idx = i * 256 + t, row = idx >> 3, q8 = (idx & 7) << 3;
            uint32_t dsw = soff(row, q8) * 2;
            cp16(db + dsw,           kk16 + (size_t)(k0 + row) * HDIM + q8);
            cp16(db + PVH_OFF + dsw, vh + (size_t)row * SEQ + k0 + q8);
        }
    };

#pragma unroll
    for (int i = 0; i < 4; i++) {
        int idx = i * 256 + t, row = idx >> 3, q8 = (idx & 7) << 3;
        cp16(sbase + PQ_OFF + soff(row, q8) * 2, q + (size_t)(m0 + row) * HDIM + q8);
    }
#pragma unroll
    for (int i = 0; i < 2; i++) {
        int idx = i * 256 + t, row = idx >> 3, q8 = (idx & 7) << 3;
        uint32_t dsw = soff(row, q8) * 2;
        cp16(sbase + PG_OFF + dsw, g_Gh + (size_t)z * HDIM * HDIM + (size_t)row * HDIM + q8);
        cp16(sbase + PG_LO + dsw,  g_Gl + (size_t)z * HDIM * HDIM + (size_t)row * HDIM + q8);
    }
    cp_slab(0, 0);
    CP_COMMIT(); CP_WAIT0();
    __syncthreads();

    // ---- Q fragments -> registers (persistent) ----
    uint32_t qf[4][4];
#pragma unroll
    for (int kq4 = 0; kq4 < 4; kq4++)
        ldsm_x4(qf[kq4], sbase + PQ_OFF + soff(wr0 + lrow, (kq4 << 4) + (lhalf << 3)) * 2);

    // ---- sumsq: T = Q G (2 chains), then row-dot with q (no atomics) ----
    {
        float ct[8][4] = {};
#pragma unroll
        for (int kq4 = 0; kq4 < 4; kq4++)
#pragma unroll
            for (int np = 0; np < 4; np++) {
                uint32_t gh[4], gl[4];
                uint32_t o = soff((np << 4) + bnq, (kq4 << 4) + bk8) * 2;
                ldsm_x4(gh, sbase + PG_OFF + o);
                ldsm_x4(gl, sbase + PG_LO + o);
                mma_f16(ct[np * 2 + 0], qf[kq4], &gh[0]);
                mma_f16(ct[np * 2 + 1], qf[kq4], &gh[2]);
                mma_f16(ct[np * 2 + 0], qf[kq4], &gl[0]);
                mma_f16(ct[np * 2 + 1], qf[kq4], &gl[2]);
            }
        float s0 = 0.f, s1 = 0.f;
#pragma unroll
        for (int nf = 0; nf < 8; nf++) {
            const int col = (nf << 3) + c2;
            float2 q0 = __half22float2(*(__half2*)(sm + PQ_OFF + soff(wr0 + r4, col) * 2));
            float2 q1 = __half22float2(*(__half2*)(sm + PQ_OFF + soff(wr0 + r4 + 8, col) * 2));
            s0 += ct[nf][0] * q0.x + ct[nf][1] * q0.y;
            s1 += ct[nf][2] * q1.x + ct[nf][3] * q1.y;
        }
        s0 += __shfl_xor_sync(0xffffffffu, s0, 1);
        s0 += __shfl_xor_sync(0xffffffffu, s0, 2);
        s1 += __shfl_xor_sync(0xffffffffu, s1, 1);
        s1 += __shfl_xor_sync(0xffffffffu, s1, 2);
        if ((lane & 3) == 0) {
            s_red[wr0 + r4]     = s0;
            s_red[wr0 + r4 + 8] = s1;
        }
    }
    __syncthreads();
    if (t < 128) s_inv[t] = 1.0f / (sqrtf(s_red[t]) + 1e-6f);
    __syncthreads();
    const float inv0 = s_inv[wr0 + r4];
    const float inv1 = s_inv[wr0 + r4 + 8];

    // ---- main loop: S-MMA -> exp (registers) -> pack to A-frags -> PV-MMA ----
    float c_pv[8][4] = {};
    float c_se[4] = {};
    const uint32_t ONES2 = 0x3C003C00u;       // fp16 (1.0, 1.0)
    const uint32_t ones[2] = {ONES2, ONES2};
    const int S = SEQ >> 6;
    for (int s = 0; s < S; s++) {
        if (s + 1 < S) { cp_slab((s + 1) & 1, (s + 1) << 6); CP_COMMIT(); }
        uint32_t db = sbase + PBUF0 + (s & 1) * PBUFSZ;

        // S = Q x K  (cs[nf] covers cols nf*8..nf*8+7 of the 64-wide slab)
        float cs[8][4] = {};
#pragma unroll
        for (int kq4 = 0; kq4 < 4; kq4++)
#pragma unroll
            for (int np = 0; np < 4; np++) {
                uint32_t bk[4];
                ldsm_x4(bk, db + soff((np << 4) + bnq, (kq4 << 4) + bk8) * 2);
                mma_f16(cs[np * 2 + 0], qf[kq4], &bk[0]);
                mma_f16(cs[np * 2 + 1], qf[kq4], &bk[2]);
            }

        // exp in registers, pack C-frags (m16n8 pairs) into A-frags (m16k16)
        uint32_t pa[4][4];
#pragma unroll
        for (int g = 0; g < 4; g++) {
            float* e0 = cs[g * 2];
            float* e1 = cs[g * 2 + 1];
            __half2 h00 = __floats2half2_rn(__expf(e0[0] * inv0), __expf(e0[1] * inv0));
            __half2 h01 = __floats2half2_rn(__expf(e0[2] * inv1), __expf(e0[3] * inv1));
            __half2 h10 = __floats2half2_rn(__expf(e1[0] * inv0), __expf(e1[1] * inv0));
            __half2 h11 = __floats2half2_rn(__expf(e1[2] * inv1), __expf(e1[3] * inv1));
            pa[g][0] = *(uint32_t*)&h00;
            pa[g][1] = *(uint32_t*)&h01;
            pa[g][2] = *(uint32_t*)&h10;
            pa[g][3] = *(uint32_t*)&h11;
        }

        // PV += P x V ; sumexp += P x ones
#pragma unroll
        for (int g = 0; g < 4; g++) {
            mma_f16(c_se, pa[g], ones);
#pragma unroll
            for (int np = 0; np < 4; np++) {
                uint32_t bv[4];
                ldsm_x4(bv, db + PVH_OFF + soff((np << 4) + bnq, (g << 4) + bk8) * 2);
                mma_f16(c_pv[np * 2 + 0], pa[g], &bv[0]);
                mma_f16(c_pv[np * 2 + 1], pa[g], &bv[2]);
            }
        }
        if (s + 1 < S) CP_WAIT0();
        __syncthreads();
    }

    // ---- epilogue ----
    const float rse0 = 1.0f / c_se[0];
    const float rse1 = 1.0f / c_se[2];
    const size_t gr0 = (size_t)(b * SEQ + m0 + wr0 + r4) * DMODEL;
    const size_t gr1 = (size_t)(b * SEQ + m0 + wr0 + r4 + 8) * DMODEL;
#pragma unroll
    for (int nf = 0; nf < 8; nf++) {
        const int gc = h * HDIM + (nf << 3) + c2;
        {
            float ox = c_pv[nf][0] * rse0, oy = c_pv[nf][1] * rse0;
            __nv_bfloat162 hh = __floats2bfloat162_rn(ox, oy);
            __nv_bfloat162 ll = __floats2bfloat162_rn(ox - __low2float(hh), oy - __high2float(hh));
            *(uint32_t*)&g_ah[gr0 + gc] = *(uint32_t*)&hh;
            *(uint32_t*)&g_al[gr0 + gc] = *(uint32_t*)&ll;
        }
        {
            float ox = c_pv[nf][2] * rse1, oy = c_pv[nf][3] * rse1;
            __nv_bfloat162 hh = __floats2bfloat162_rn(ox, oy);
            __nv_bfloat162 ll = __floats2bfloat162_rn(ox - __low2float(hh), oy - __high2float(hh));
            *(uint32_t*)&g_ah[gr1 + gc] = *(uint32_t*)&hh;
            *(uint32_t*)&g_al[gr1 + gc] = *(uint32_t*)&ll;
        }
    }
}

// ============================================================================
// Final projection: attn (split bf16) @ proj_w^T (split bf16) + bias -> fp32.
// ============================================================================
__global__ __launch_bounds__(256, 2) void proj_tc(float* __restrict__ out,
                                                  const float* __restrict__ bias)
{
    extern __shared__ char sm[];
    const int t = threadIdx.x, lane = t & 31, wid = t >> 5;
    const int m0 = blockIdx.y * 128, n0 = blockIdx.x * 64;
    const uint32_t sbase = smem_u32(sm);

    auto cp_slab = [&](int bs, int k0) {
        uint32_t db = sbase + bs * BUF3;
#pragma unroll
        for (int i = 0; i < 4; i++) {
            int idx = i * 256 + t, row = idx >> 3, q8 = (idx & 7) << 3;
            uint32_t dsw = soff(row, q8) * 2;
            cp16(db + A_HI + dsw, g_ah + (size_t)(m0 + row) * DMODEL + k0 + q8);
            cp16(db + A_LO + dsw, g_al + (size_t)(m0 + row) * DMODEL + k0 + q8);
        }
#pragma unroll
        for (int i = 0; i < 2; i++) {
            int idx = i * 256 + t, row = idx >> 3, q8 = (idx & 7) << 3;
            uint32_t dsw = soff(row, q8) * 2;
            cp16(db + B_HI + dsw, g_pwh + (size_t)(n0 + row) * DMODEL + k0 + q8);
            cp16(db + B_LO + dsw, g_pwl + (size_t)(n0 + row) * DMODEL + k0 + q8);
        }
    };

    float c[2][4][4] = {};
    cp_slab(0, 0); CP_COMMIT();
    const int S = DMODEL >> 6;
    for (int s = 0; s < S; s++) {
        if (s + 1 < S) { cp_slab((s + 1) & 1, (s + 1) << 6); CP_COMMIT(); CP_WAIT1(); }
        else CP_WAIT0();
        __syncthreads();
        mma_slab3(sbase + (s & 1) * BUF3, c, wid, lane);
        __syncthreads();
    }

    const int wm = (wid & 3) << 5, wn = (wid >> 2) << 5;
    const int r4 = lane >> 2, c2 = (lane & 3) << 1;
#pragma unroll
    for (int mf = 0; mf < 2; mf++)
#pragma unroll
        for (int half = 0; half < 2; half++) {
            const int row = m0 + wm + (mf << 4) + (half << 3) + r4;
#pragma unroll
            for (int nf = 0; nf < 4; nf++) {
                const int col = n0 + wn + (nf << 3) + c2;
                float2 o;
                o.x = c[mf][nf][half * 2 + 0] + bias[col];
                o.y = c[mf][nf][half * 2 + 1] + bias[col + 1];
                *(float2*)&out[(size_t)row * DMODEL + col] = o;
            }
        }
}

// ---------------------------------------------------------------------------
extern "C" void kernel_launch(void* const* d_in, const int* in_sizes, int n_in,
                              void* d_out, int out_size)
{
    const float* x      = (const float*)d_in[0];
    const float* qkv_w  = (const float*)d_in[1];
    const float* qkv_b  = (const float*)d_in[2];
    const float* proj_w = (const float*)d_in[3];
    const float* proj_b = (const float*)d_in[4];
    float* out = (float*)d_out;

    cudaFuncSetAttribute(qkv_tc, cudaFuncAttributeMaxDynamicSharedMemorySize, 2 * BUF3);
    cudaFuncSetAttribute(gmat_tc, cudaFuncAttributeMaxDynamicSharedMemorySize, 16384);
    cudaFuncSetAttribute(pv_tc, cudaFuncAttributeMaxDynamicSharedMemorySize, PV_SMEM);
    cudaFuncSetAttribute(proj_tc, cudaFuncAttributeMaxDynamicSharedMemorySize, 2 * BUF3);

    presplit_all<<<(NX_F4 + NW_F4 + NP_F4) / 256, 256>>>(
        (const float4*)x, (const float4*)qkv_w, (const float4*)proj_w);

    qkv_tc<<<dim3(QKVDIM / 64, (BATCH * SEQ) / 128), 256, 2 * BUF3>>>(qkv_b);

    gmat_tc<<<16, 256, 16384>>>();

    pv_tc<<<dim3(1, SEQ / 128, ZTOT), 256, PV_SMEM>>>();

    proj_tc<<<dim3(DMODEL / 64, (BATCH * SEQ) / 128), 256, 2 * BUF3>>>(out, proj_b);
}

// round 17
// speedup vs baseline: 7.0135x; 1.0824x over previous
#include <cuda_runtime.h>
#include <cuda_bf16.h>
#include <cuda_fp16.h>
#include <math.h>
#include <stdint.h>

// Problem constants: B=2, N=2048, D=512, H=8, hd=64
#define BATCH 2
#define SEQ   2048
#define DMODEL 512
#define HEADS 8
#define HDIM  64
#define QKVDIM 1536
#define ZTOT  (BATCH * HEADS)        // 16
#define ZSTRIDE ((size_t)SEQ * HDIM) // 131072

// ---------------- scratch (no cudaMalloc -> __device__ globals) ----------------
__device__ __nv_bfloat16 g_xh[(size_t)BATCH * SEQ * DMODEL], g_xl[(size_t)BATCH * SEQ * DMODEL];
__device__ __nv_bfloat16 g_wh[(size_t)QKVDIM * DMODEL],      g_wl[(size_t)QKVDIM * DMODEL];
__device__ __half g_pw16h[(size_t)DMODEL * DMODEL], g_pw16l[(size_t)DMODEL * DMODEL]; // fp16 split
__device__ __half g_q16[(size_t)ZTOT * SEQ * HDIM];           // Q, pre-scaled x0.125
__device__ __half g_k16[(size_t)ZTOT * SEQ * HDIM];           // K row-major
__device__ __half g_kt16[(size_t)ZTOT * HDIM * SEQ];          // K transposed [z][d][n]
__device__ __half g_vh16[(size_t)ZTOT * HDIM * SEQ];          // V transposed, single fp16
__device__ __half g_Gh[(size_t)ZTOT * HDIM * HDIM], g_Gl[(size_t)ZTOT * HDIM * HDIM];
__device__ __half g_a16[(size_t)BATCH * SEQ * DMODEL];        // attn, single fp16

// ---------------- smem: stride-64 rows, XOR swizzle on 16B units ----------------
__device__ __forceinline__ uint32_t soff(int row, int k) {
    int u = ((k >> 3) ^ row) & 7;
    return (uint32_t)((row << 6) + (u << 3) + (k & 7));
}
__device__ __forceinline__ uint32_t smem_u32(const void* p) {
    uint32_t a;
    asm("{ .reg .u64 t; cvta.to.shared.u64 t, %1; cvt.u32.u64 %0, t; }" : "=r"(a) : "l"(p));
    return a;
}
__device__ __forceinline__ void ldsm_x4(uint32_t* r, uint32_t addr) {
    asm volatile("ldmatrix.sync.aligned.m8n8.x4.shared.b16 {%0,%1,%2,%3}, [%4];"
        : "=r"(r[0]), "=r"(r[1]), "=r"(r[2]), "=r"(r[3]) : "r"(addr));
}
__device__ __forceinline__ void mma_bf16(float* c, const uint32_t* a, const uint32_t* b) {
    asm volatile("mma.sync.aligned.m16n8k16.row.col.f32.bf16.bf16.f32 "
        "{%0,%1,%2,%3}, {%4,%5,%6,%7}, {%8,%9}, {%0,%1,%2,%3};"
        : "+f"(c[0]), "+f"(c[1]), "+f"(c[2]), "+f"(c[3])
        : "r"(a[0]), "r"(a[1]), "r"(a[2]), "r"(a[3]), "r"(b[0]), "r"(b[1]));
}
__device__ __forceinline__ void mma_f16(float* c, const uint32_t* a, const uint32_t* b) {
    asm volatile("mma.sync.aligned.m16n8k16.row.col.f32.f16.f16.f32 "
        "{%0,%1,%2,%3}, {%4,%5,%6,%7}, {%8,%9}, {%0,%1,%2,%3};"
        : "+f"(c[0]), "+f"(c[1]), "+f"(c[2]), "+f"(c[3])
        : "r"(a[0]), "r"(a[1]), "r"(a[2]), "r"(a[3]), "r"(b[0]), "r"(b[1]));
}
__device__ __forceinline__ uint32_t h2exp2_u(uint32_t x) {
    uint32_t r;
    asm("ex2.approx.f16x2 %0, %1;" : "=r"(r) : "r"(x));
    return r;
}
__device__ __forceinline__ void cp16(uint32_t dst, const void* src) {
    asm volatile("cp.async.cg.shared.global [%0], [%1], 16;" :: "r"(dst), "l"(src));
}
#define CP_COMMIT() asm volatile("cp.async.commit_group;" ::: "memory")
#define CP_WAIT0()  asm volatile("cp.async.wait_group 0;" ::: "memory")
#define CP_WAIT1()  asm volatile("cp.async.wait_group 1;" ::: "memory")

// GEMM buffers (qkv, proj)
#define A_HI 0
#define A_LO 16384
#define B_HI 32768
#define B_LO 40960
#define BUF3 49152
// pv layout: Q (16KB) | G hi (8K) | G lo (8K) | 2 slab bufs (K 8K + V 8K each)
#define PQ_OFF 0
#define PG_OFF 16384
#define PG_LO  24576
#define PBUF0  32768
#define PVH_OFF 8192
#define PBUFSZ 16384
#define PV_SMEM (PBUF0 + 2 * PBUFSZ)   // 65536

// ---------------- slab MMA variants (warp grid 4x2, warp tile 32x32) ----------------
__device__ __forceinline__ void mma_slab3(uint32_t sbase, float c[2][4][4], int wid, int lane) {
    const int wm = (wid & 3) << 5, wn = (wid >> 2) << 5;
    const int lrow = lane & 15, lhalf = lane >> 4;
    const int bq = lane >> 3, br = lane & 7;
    const int bnq = ((bq >> 1) << 3) + br, bk8 = (bq & 1) << 3;
#pragma unroll
    for (int kk = 0; kk < 64; kk += 16) {
        uint32_t ah[2][4], al[2][4], bh[2][4], bl[2][4];
#pragma unroll
        for (int mf = 0; mf < 2; mf++) {
            uint32_t o = soff(wm + (mf << 4) + lrow, kk + (lhalf << 3)) * 2;
            ldsm_x4(ah[mf], sbase + A_HI + o);
            ldsm_x4(al[mf], sbase + A_LO + o);
        }
#pragma unroll
        for (int np = 0; np < 2; np++) {
            uint32_t o = soff(wn + (np << 4) + bnq, kk + bk8) * 2;
            ldsm_x4(bh[np], sbase + B_HI + o);
            ldsm_x4(bl[np], sbase + B_LO + o);
        }
#pragma unroll
        for (int mf = 0; mf < 2; mf++)
#pragma unroll
            for (int nf = 0; nf < 4; nf++) {
                const uint32_t* bhp = &bh[nf >> 1][(nf & 1) << 1];
                const uint32_t* blp = &bl[nf >> 1][(nf & 1) << 1];
                mma_bf16(c[mf][nf], ah[mf], bhp);
                mma_bf16(c[mf][nf], ah[mf], blp);
                mma_bf16(c[mf][nf], al[mf], bhp);
            }
    }
}
__device__ __forceinline__ void mma_slab1b(uint32_t sbase, float c[2][4][4], int wid, int lane) {
    const int wm = (wid & 3) << 5, wn = (wid >> 2) << 5;
    const int lrow = lane & 15, lhalf = lane >> 4;
    const int bq = lane >> 3, br = lane & 7;
    const int bnq = ((bq >> 1) << 3) + br, bk8 = (bq & 1) << 3;
#pragma unroll
    for (int kk = 0; kk < 64; kk += 16) {
        uint32_t ah[2][4], bh[2][4];
#pragma unroll
        for (int mf = 0; mf < 2; mf++)
            ldsm_x4(ah[mf], sbase + A_HI + soff(wm + (mf << 4) + lrow, kk + (lhalf << 3)) * 2);
#pragma unroll
        for (int np = 0; np < 2; np++)
            ldsm_x4(bh[np], sbase + B_HI + soff(wn + (np << 4) + bnq, kk + bk8) * 2);
#pragma unroll
        for (int mf = 0; mf < 2; mf++)
#pragma unroll
            for (int nf = 0; nf < 4; nf++)
                mma_bf16(c[mf][nf], ah[mf], &bh[nf >> 1][(nf & 1) << 1]);
    }
}
// proj: A single fp16 x B fp16 hi/lo (2 chains)
__device__ __forceinline__ void mma_slab2h(uint32_t sbase, float c[2][4][4], int wid, int lane) {
    const int wm = (wid & 3) << 5, wn = (wid >> 2) << 5;
    const int lrow = lane & 15, lhalf = lane >> 4;
    const int bq = lane >> 3, br = lane & 7;
    const int bnq = ((bq >> 1) << 3) + br, bk8 = (bq & 1) << 3;
#pragma unroll
    for (int kk = 0; kk < 64; kk += 16) {
        uint32_t ah[2][4], bh[2][4], bl[2][4];
#pragma unroll
        for (int mf = 0; mf < 2; mf++)
            ldsm_x4(ah[mf], sbase + A_HI + soff(wm + (mf << 4) + lrow, kk + (lhalf << 3)) * 2);
#pragma unroll
        for (int np = 0; np < 2; np++) {
            uint32_t o = soff(wn + (np << 4) + bnq, kk + bk8) * 2;
            ldsm_x4(bh[np], sbase + B_HI + o);
            ldsm_x4(bl[np], sbase + B_LO + o);
        }
#pragma unroll
        for (int mf = 0; mf < 2; mf++)
#pragma unroll
            for (int nf = 0; nf < 4; nf++) {
                mma_f16(c[mf][nf], ah[mf], &bh[nf >> 1][(nf & 1) << 1]);
                mma_f16(c[mf][nf], ah[mf], &bl[nf >> 1][(nf & 1) << 1]);
            }
    }
}

// ============================================================================
// presplit_all: x, qkv_w -> bf16 hi/lo; proj_w -> fp16 hi/lo.
// ============================================================================
#define NX_F4 ((BATCH * SEQ * DMODEL) / 4)
#define NW_F4 ((QKVDIM * DMODEL) / 4)
#define NP_F4 ((DMODEL * DMODEL) / 4)
__global__ void presplit_all(const float4* __restrict__ x, const float4* __restrict__ w,
                             const float4* __restrict__ pw)
{
    int i = blockIdx.x * 256 + threadIdx.x;
    if (i < NX_F4 + NW_F4) {
        const float4* src;
        __nv_bfloat16 *hi, *lo;
        int j = i;
        if (i < NX_F4) { src = x; hi = g_xh; lo = g_xl; }
        else           { src = w; hi = g_wh; lo = g_wl; j = i - NX_F4; }
        float4 v = src[j];
        __nv_bfloat162 h0 = __floats2bfloat162_rn(v.x, v.y);
        __nv_bfloat162 h1 = __floats2bfloat162_rn(v.z, v.w);
        __nv_bfloat162 l0 = __floats2bfloat162_rn(v.x - __low2float(h0), v.y - __high2float(h0));
        __nv_bfloat162 l1 = __floats2bfloat162_rn(v.z - __low2float(h1), v.w - __high2float(h1));
        uint2 hu, lu;
        hu.x = *(uint32_t*)&h0; hu.y = *(uint32_t*)&h1;
        lu.x = *(uint32_t*)&l0; lu.y = *(uint32_t*)&l1;
        *(uint2*)(hi + 4 * (size_t)j) = hu;
        *(uint2*)(lo + 4 * (size_t)j) = lu;
    } else {
        int j = i - NX_F4 - NW_F4;
        float4 v = pw[j];
        __half2 h0 = __floats2half2_rn(v.x, v.y);
        __half2 h1 = __floats2half2_rn(v.z, v.w);
        __half2 l0 = __floats2half2_rn(v.x - __low2float(h0), v.y - __high2float(h0));
        __half2 l1 = __floats2half2_rn(v.z - __low2float(h1), v.w - __high2float(h1));
        uint2 hu, lu;
        hu.x = *(uint32_t*)&h0; hu.y = *(uint32_t*)&h1;
        lu.x = *(uint32_t*)&l0; lu.y = *(uint32_t*)&l1;
        *(uint2*)(g_pw16h + 4 * (size_t)j) = hu;
        *(uint2*)(g_pw16l + 4 * (size_t)j) = lu;
    }
}

// ============================================================================
// QKV projection. Q/K: 1-chain (hi x hi). V: 3-chain.
// ============================================================================
__global__ __launch_bounds__(256, 2) void qkv_tc(const float* __restrict__ bias)
{
    extern __shared__ char sm[];
    const int t = threadIdx.x, lane = t & 31, wid = t >> 5;
    const int m0 = blockIdx.y * 128, n0 = blockIdx.x * 64;
    const uint32_t sbase = smem_u32(sm);
    const int typ = n0 >> 9;
    const bool isV = (typ == 2);

    auto cp_slab = [&](int bs, int k0) {
        uint32_t db = sbase + bs * BUF3;
#pragma unroll
        for (int i = 0; i < 4; i++) {
            int idx = i * 256 + t, row = idx >> 3, q8 = (idx & 7) << 3;
            uint32_t dsw = soff(row, q8) * 2;
            cp16(db + A_HI + dsw, g_xh + (size_t)(m0 + row) * DMODEL + k0 + q8);
            if (isV)
                cp16(db + A_LO + dsw, g_xl + (size_t)(m0 + row) * DMODEL + k0 + q8);
        }
#pragma unroll
        for (int i = 0; i < 2; i++) {
            int idx = i * 256 + t, row = idx >> 3, q8 = (idx & 7) << 3;
            uint32_t dsw = soff(row, q8) * 2;
            cp16(db + B_HI + dsw, g_wh + (size_t)(n0 + row) * DMODEL + k0 + q8);
            if (isV)
                cp16(db + B_LO + dsw, g_wl + (size_t)(n0 + row) * DMODEL + k0 + q8);
        }
    };

    float c[2][4][4] = {};
    cp_slab(0, 0); CP_COMMIT();
    const int S = DMODEL >> 6;
    for (int s = 0; s < S; s++) {
        if (s + 1 < S) { cp_slab((s + 1) & 1, (s + 1) << 6); CP_COMMIT(); CP_WAIT1(); }
        else CP_WAIT0();
        __syncthreads();
        if (isV) mma_slab3(sbase + (s & 1) * BUF3, c, wid, lane);
        else     mma_slab1b(sbase + (s & 1) * BUF3, c, wid, lane);
        __syncthreads();
    }

    const int wm = (wid & 3) << 5, wn = (wid >> 2) << 5;
    const int r4 = lane >> 2, c2 = (lane & 3) << 1;
    const int h = (n0 >> 6) & 7, b = m0 >> 11;
    const int z = b * HEADS + h;
    const int nloc = m0 & (SEQ - 1);

    if (typ == 0) {
        __half* dst = g_q16 + (size_t)z * ZSTRIDE;
#pragma unroll
        for (int mf = 0; mf < 2; mf++)
#pragma unroll
            for (int half = 0; half < 2; half++) {
                const int row = wm + (mf << 4) + (half << 3) + r4;
#pragma unroll
                for (int nf = 0; nf < 4; nf++) {
                    const int d = wn + (nf << 3) + c2;
                    float ox = (c[mf][nf][half * 2 + 0] + bias[n0 + d]) * 0.125f;
                    float oy = (c[mf][nf][half * 2 + 1] + bias[n0 + d + 1]) * 0.125f;
                    *(__half2*)&dst[(size_t)(nloc + row) * HDIM + d] = __floats2half2_rn(ox, oy);
                }
            }
    } else if (typ == 1) {
        __half* dst = g_k16 + (size_t)z * ZSTRIDE;
        __half* th = (__half*)sm;
#pragma unroll
        for (int mf = 0; mf < 2; mf++)
#pragma unroll
            for (int half = 0; half < 2; half++) {
                const int row = wm + (mf << 4) + (half << 3) + r4;
#pragma unroll
                for (int nf = 0; nf < 4; nf++) {
                    const int d = wn + (nf << 3) + c2;
                    float ox = c[mf][nf][half * 2 + 0] + bias[n0 + d];
                    float oy = c[mf][nf][half * 2 + 1] + bias[n0 + d + 1];
                    __half hx = __float2half_rn(ox), hy = __float2half_rn(oy);
                    *(__half2*)&dst[(size_t)(nloc + row) * HDIM + d] = __halves2half2(hx, hy);
                    th[d * 136 + row]       = hx;
                    th[(d + 1) * 136 + row] = hy;
                }
            }
        __syncthreads();
        __half* kt = g_kt16 + (size_t)z * ZSTRIDE;
#pragma unroll
        for (int i = 0; i < 8; i++) {
            int idx = i * 256 + t, d = idx >> 5, nm = (idx & 31) << 2;
            *(uint2*)&kt[(size_t)d * SEQ + nloc + nm] = *(uint2*)&th[d * 136 + nm];
        }
    } else {
        __half* th = (__half*)sm;
#pragma unroll
        for (int mf = 0; mf < 2; mf++)
#pragma unroll
            for (int half = 0; half < 2; half++) {
                const int row = wm + (mf << 4) + (half << 3) + r4;
#pragma unroll
                for (int nf = 0; nf < 4; nf++) {
                    const int d = wn + (nf << 3) + c2;
                    float ox = c[mf][nf][half * 2 + 0] + bias[n0 + d];
                    float oy = c[mf][nf][half * 2 + 1] + bias[n0 + d + 1];
                    th[d * 136 + row]       = __float2half_rn(ox);
                    th[(d + 1) * 136 + row] = __float2half_rn(oy);
                }
            }
        __syncthreads();
        __half* vh = g_vh16 + (size_t)z * ZSTRIDE;
#pragma unroll
        for (int i = 0; i < 8; i++) {
            int idx = i * 256 + t, d = idx >> 5, nm = (idx & 31) << 2;
            *(uint2*)&vh[(size_t)d * SEQ + nloc + nm] = *(uint2*)&th[d * 136 + nm];
        }
    }
}

// ============================================================================
// gmat: G = K^T K per z, output split fp16.
// ============================================================================
__global__ __launch_bounds__(256) void gmat_tc()
{
    extern __shared__ char sm[];
    const int t = threadIdx.x, lane = t & 31, wid = t >> 5;
    const int z = blockIdx.x;
    const __half* kt = g_kt16 + (size_t)z * ZSTRIDE;
    const uint32_t sbase = smem_u32(sm);

    auto cp_slab = [&](int bs, int k0) {
        uint32_t db = sbase + bs * 8192;
#pragma unroll
        for (int i = 0; i < 2; i++) {
            int idx = i * 256 + t, row = idx >> 3, q8 = (idx & 7) << 3;
            cp16(db + soff(row, q8) * 2, kt + (size_t)row * SEQ + k0 + q8);
        }
    };

    const int wm = (wid & 3) << 4, wn = (wid >> 2) << 5;
    const int lrow = lane & 15, lhalf = lane >> 4;
    const int bq = lane >> 3, br = lane & 7;
    const int bnq = ((bq >> 1) << 3) + br, bk8 = (bq & 1) << 3;

    float c[4][4] = {};
    cp_slab(0, 0); CP_COMMIT();
    const int S = SEQ >> 6;
    for (int s = 0; s < S; s++) {
        if (s + 1 < S) { cp_slab((s + 1) & 1, (s + 1) << 6); CP_COMMIT(); CP_WAIT1(); }
        else CP_WAIT0();
        __syncthreads();
        uint32_t db = sbase + (s & 1) * 8192;
#pragma unroll
        for (int kk = 0; kk < 64; kk += 16) {
            uint32_t a[4], b2[2][4];
            ldsm_x4(a, db + soff(wm + lrow, kk + (lhalf << 3)) * 2);
#pragma unroll
            for (int np = 0; np < 2; np++)
                ldsm_x4(b2[np], db + soff(wn + (np << 4) + bnq, kk + bk8) * 2);
#pragma unroll
            for (int nf = 0; nf < 4; nf++)
                mma_f16(c[nf], a, &b2[nf >> 1][(nf & 1) << 1]);
        }
        __syncthreads();
    }

    const int r4 = lane >> 2, c2 = (lane & 3) << 1;
    __half* Gh = g_Gh + (size_t)z * HDIM * HDIM;
    __half* Gl = g_Gl + (size_t)z * HDIM * HDIM;
#pragma unroll
    for (int half = 0; half < 2; half++) {
        const int row = wm + (half << 3) + r4;
#pragma unroll
        for (int nf = 0; nf < 4; nf++) {
            const int col = wn + (nf << 3) + c2;
            float vx = c[nf][half * 2 + 0], vy = c[nf][half * 2 + 1];
            __half hx = __float2half_rn(vx), hy = __float2half_rn(vy);
            *(__half2*)&Gh[row * HDIM + col] = __halves2half2(hx, hy);
            __half lx = __float2half_rn(vx - __half2float(hx));
            __half ly = __float2half_rn(vy - __half2float(hy));
            *(__half2*)&Gl[row * HDIM + col] = __halves2half2(lx, ly);
        }
    }
}

// ============================================================================
// pv_fused (FA2-style): warp owns 16 rows x 64 cols; P in registers.
// exp via ex2.approx.f16x2 (inv pre-multiplied by log2 e, applied in fp16).
// sumexp via P x ones MMA. Epilogue: /sumexp, write single-fp16 attn.
// ============================================================================
__global__ __launch_bounds__(256, 2) void pv_tc()
{
    extern __shared__ char sm[];
    __shared__ float s_inv[128], s_red[128];
    const int t = threadIdx.x, lane = t & 31, wid = t >> 5;
    const int z = blockIdx.z, b = z >> 3, h = z & 7;
    const int m0 = blockIdx.y * 128;
    const __half* q    = g_q16 + (size_t)z * ZSTRIDE;
    const __half* kk16 = g_k16 + (size_t)z * ZSTRIDE;
    const __half* vh   = g_vh16 + (size_t)z * ZSTRIDE;
    const uint32_t sbase = smem_u32(sm);

    const int wr0 = wid << 4;
    const int lrow = lane & 15, lhalf = lane >> 4;
    const int bq = lane >> 3, br = lane & 7;
    const int bnq = ((bq >> 1) << 3) + br, bk8 = (bq & 1) << 3;
    const int r4 = lane >> 2, c2 = (lane & 3) << 1;

    auto cp_slab = [&](int bs, int k0) {
        uint32_t db = sbase + PBUF0 + bs * PBUFSZ;
#pragma unroll
        for (int i = 0; i < 2; i++) {
            int idx = i * 256 + t, row = idx >> 3, q8 = (idx & 7) << 3;
            uint32_t dsw = soff(row, q8) * 2;
            cp16(db + dsw,           kk16 + (size_t)(k0 + row) * HDIM + q8);
            cp16(db + PVH_OFF + dsw, vh + (size_t)row * SEQ + k0 + q8);
        }
    };

#pragma unroll
    for (int i = 0; i < 4; i++) {
        int idx = i * 256 + t, row = idx >> 3, q8 = (idx & 7) << 3;
        cp16(sbase + PQ_OFF + soff(row, q8) * 2, q + (size_t)(m0 + row) * HDIM + q8);
    }
#pragma unroll
    for (int i = 0; i < 2; i++) {
        int idx = i * 256 + t, row = idx >> 3, q8 = (idx & 7) << 3;
        uint32_t dsw = soff(row, q8) * 2;
        cp16(sbase + PG_OFF + dsw, g_Gh + (size_t)z * HDIM * HDIM + (size_t)row * HDIM + q8);
        cp16(sbase + PG_LO + dsw,  g_Gl + (size_t)z * HDIM * HDIM + (size_t)row * HDIM + q8);
    }
    cp_slab(0, 0);
    CP_COMMIT(); CP_WAIT0();
    __syncthreads();

    // ---- Q fragments -> registers (persistent) ----
    uint32_t qf[4][4];
#pragma unroll
    for (int kq4 = 0; kq4 < 4; kq4++)
        ldsm_x4(qf[kq4], sbase + PQ_OFF + soff(wr0 + lrow, (kq4 << 4) + (lhalf << 3)) * 2);

    // ---- sumsq: T = Q G (2 chains), then row-dot with q ----
    {
        float ct[8][4] = {};
#pragma unroll
        for (int kq4 = 0; kq4 < 4; kq4++)
#pragma unroll
            for (int np = 0; np < 4; np++) {
                uint32_t gh[4], gl[4];
                uint32_t o = soff((np << 4) + bnq, (kq4 << 4) + bk8) * 2;
                ldsm_x4(gh, sbase + PG_OFF + o);
                ldsm_x4(gl, sbase + PG_LO + o);
                mma_f16(ct[np * 2 + 0], qf[kq4], &gh[0]);
                mma_f16(ct[np * 2 + 1], qf[kq4], &gh[2]);
                mma_f16(ct[np * 2 + 0], qf[kq4], &gl[0]);
                mma_f16(ct[np * 2 + 1], qf[kq4], &gl[2]);
            }
        float s0 = 0.f, s1 = 0.f;
#pragma unroll
        for (int nf = 0; nf < 8; nf++) {
            const int col = (nf << 3) + c2;
            float2 q0 = __half22float2(*(__half2*)(sm + PQ_OFF + soff(wr0 + r4, col) * 2));
            float2 q1 = __half22float2(*(__half2*)(sm + PQ_OFF + soff(wr0 + r4 + 8, col) * 2));
            s0 += ct[nf][0] * q0.x + ct[nf][1] * q0.y;
            s1 += ct[nf][2] * q1.x + ct[nf][3] * q1.y;
        }
        s0 += __shfl_xor_sync(0xffffffffu, s0, 1);
        s0 += __shfl_xor_sync(0xffffffffu, s0, 2);
        s1 += __shfl_xor_sync(0xffffffffu, s1, 1);
        s1 += __shfl_xor_sync(0xffffffffu, s1, 2);
        if ((lane & 3) == 0) {
            s_red[wr0 + r4]     = s0;
            s_red[wr0 + r4 + 8] = s1;
        }
    }
    __syncthreads();
    if (t < 128) s_inv[t] = 1.44269504f / (sqrtf(s_red[t]) + 1e-6f);  // x log2(e)
    __syncthreads();
    const float inv0 = s_inv[wr0 + r4];
    const float inv1 = s_inv[wr0 + r4 + 8];
    const __half2 inv0h = __float2half2_rn(inv0);
    const __half2 inv1h = __float2half2_rn(inv1);

    // ---- main loop: S-MMA -> ex2.f16x2 (registers) -> PV-MMA ----
    float c_pv[8][4] = {};
    float c_se[4] = {};
    const uint32_t ONES2 = 0x3C003C00u;
    const uint32_t ones[2] = {ONES2, ONES2};
    const int S = SEQ >> 6;
    for (int s = 0; s < S; s++) {
        if (s + 1 < S) { cp_slab((s + 1) & 1, (s + 1) << 6); CP_COMMIT(); }
        uint32_t db = sbase + PBUF0 + (s & 1) * PBUFSZ;

        float cs[8][4] = {};
#pragma unroll
        for (int kq4 = 0; kq4 < 4; kq4++)
#pragma unroll
            for (int np = 0; np < 4; np++) {
                uint32_t bk[4];
                ldsm_x4(bk, db + soff((np << 4) + bnq, (kq4 << 4) + bk8) * 2);
                mma_f16(cs[np * 2 + 0], qf[kq4], &bk[0]);
                mma_f16(cs[np * 2 + 1], qf[kq4], &bk[2]);
            }

        // P = 2^(s * inv*log2e), computed in fp16x2, lands pre-packed as A-frags
        uint32_t pa[4][4];
#pragma unroll
        for (int g = 0; g < 4; g++) {
            float* e0 = cs[g * 2];
            float* e1 = cs[g * 2 + 1];
            __half2 a00 = __hmul2(__floats2half2_rn(e0[0], e0[1]), inv0h);
            __half2 a01 = __hmul2(__floats2half2_rn(e0[2], e0[3]), inv1h);
            __half2 a10 = __hmul2(__floats2half2_rn(e1[0], e1[1]), inv0h);
            __half2 a11 = __hmul2(__floats2half2_rn(e1[2], e1[3]), inv1h);
            pa[g][0] = h2exp2_u(*(uint32_t*)&a00);
            pa[g][1] = h2exp2_u(*(uint32_t*)&a01);
            pa[g][2] = h2exp2_u(*(uint32_t*)&a10);
            pa[g][3] = h2exp2_u(*(uint32_t*)&a11);
        }

#pragma unroll
        for (int g = 0; g < 4; g++) {
            mma_f16(c_se, pa[g], ones);
#pragma unroll
            for (int np = 0; np < 4; np++) {
                uint32_t bv[4];
                ldsm_x4(bv, db + PVH_OFF + soff((np << 4) + bnq, (g << 4) + bk8) * 2);
                mma_f16(c_pv[np * 2 + 0], pa[g], &bv[0]);
                mma_f16(c_pv[np * 2 + 1], pa[g], &bv[2]);
            }
        }
        if (s + 1 < S) CP_WAIT0();
        __syncthreads();
    }

    // ---- epilogue: single fp16 attn ----
    const float rse0 = 1.0f / c_se[0];
    const float rse1 = 1.0f / c_se[2];
    __half* a0 = g_a16 + (size_t)(b * SEQ + m0 + wr0 + r4) * DMODEL + h * HDIM;
    __half* a1 = g_a16 + (size_t)(b * SEQ + m0 + wr0 + r4 + 8) * DMODEL + h * HDIM;
#pragma unroll
    for (int nf = 0; nf < 8; nf++) {
        const int gc = (nf << 3) + c2;
        *(__half2*)&a0[gc] = __floats2half2_rn(c_pv[nf][0] * rse0, c_pv[nf][1] * rse0);
        *(__half2*)&a1[gc] = __floats2half2_rn(c_pv[nf][2] * rse1, c_pv[nf][3] * rse1);
    }
}

// ============================================================================
// Final projection: attn (fp16) @ proj_w^T (fp16 hi/lo) + bias -> fp32. 2 chains.
// ============================================================================
__global__ __launch_bounds__(256, 2) void proj_tc(float* __restrict__ out,
                                                  const float* __restrict__ bias)
{
    extern __shared__ char sm[];
    const int t = threadIdx.x, lane = t & 31, wid = t >> 5;
    const int m0 = blockIdx.y * 128, n0 = blockIdx.x * 64;
    const uint32_t sbase = smem_u32(sm);

    auto cp_slab = [&](int bs, int k0) {
        uint32_t db = sbase + bs * BUF3;
#pragma unroll
        for (int i = 0; i < 4; i++) {
            int idx = i * 256 + t, row = idx >> 3, q8 = (idx & 7) << 3;
            cp16(db + A_HI + soff(row, q8) * 2, g_a16 + (size_t)(m0 + row) * DMODEL + k0 + q8);
        }
#pragma unroll
        for (int i = 0; i < 2; i++) {
            int idx = i * 256 + t, row = idx >> 3, q8 = (idx & 7) << 3;
            uint32_t dsw = soff(row, q8) * 2;
            cp16(db + B_HI + dsw, g_pw16h + (size_t)(n0 + row) * DMODEL + k0 + q8);
            cp16(db + B_LO + dsw, g_pw16l + (size_t)(n0 + row) * DMODEL + k0 + q8);
        }
    };

    float c[2][4][4] = {};
    cp_slab(0, 0); CP_COMMIT();
    const int S = DMODEL >> 6;
    for (int s = 0; s < S; s++) {
        if (s + 1 < S) { cp_slab((s + 1) & 1, (s + 1) << 6); CP_COMMIT(); CP_WAIT1(); }
        else CP_WAIT0();
        __syncthreads();
        mma_slab2h(sbase + (s & 1) * BUF3, c, wid, lane);
        __syncthreads();
    }

    const int wm = (wid & 3) << 5, wn = (wid >> 2) << 5;
    const int r4 = lane >> 2, c2 = (lane & 3) << 1;
#pragma unroll
    for (int mf = 0; mf < 2; mf++)
#pragma unroll
        for (int half = 0; half < 2; half++) {
            const int row = m0 + wm + (mf << 4) + (half << 3) + r4;
#pragma unroll
            for (int nf = 0; nf < 4; nf++) {
                const int col = n0 + wn + (nf << 3) + c2;
                float2 o;
                o.x = c[mf][nf][half * 2 + 0] + bias[col];
                o.y = c[mf][nf][half * 2 + 1] + bias[col + 1];
                *(float2*)&out[(size_t)row * DMODEL + col] = o;
            }
        }
}

// ---------------------------------------------------------------------------
extern "C" void kernel_launch(void* const* d_in, const int* in_sizes, int n_in,
                              void* d_out, int out_size)
{
    const float* x      = (const float*)d_in[0];
    const float* qkv_w  = (const float*)d_in[1];
    const float* qkv_b  = (const float*)d_in[2];
    const float* proj_w = (const float*)d_in[3];
    const float* proj_b = (const float*)d_in[4];
    float* out = (float*)d_out;

    cudaFuncSetAttribute(qkv_tc, cudaFuncAttributeMaxDynamicSharedMemorySize, 2 * BUF3);
    cudaFuncSetAttribute(gmat_tc, cudaFuncAttributeMaxDynamicSharedMemorySize, 16384);
    cudaFuncSetAttribute(pv_tc, cudaFuncAttributeMaxDynamicSharedMemorySize, PV_SMEM);
    cudaFuncSetAttribute(proj_tc, cudaFuncAttributeMaxDynamicSharedMemorySize, 2 * BUF3);

    presplit_all<<<(NX_F4 + NW_F4 + NP_F4) / 256, 256>>>(
        (const float4*)x, (const float4*)qkv_w, (const float4*)proj_w);

    qkv_tc<<<dim3(QKVDIM / 64, (BATCH * SEQ) / 128), 256, 2 * BUF3>>>(qkv_b);

    gmat_tc<<<16, 256, 16384>>>();

    pv_tc<<<dim3(1, SEQ / 128, ZTOT), 256, PV_SMEM>>>();

    proj_tc<<<dim3(DMODEL / 64, (BATCH * SEQ) / 128), 256, 2 * BUF3>>>(out, proj_b);
}